// round 1
// baseline (speedup 1.0000x reference)
#include <cuda_runtime.h>
#include <math.h>
#include <stdint.h>

#define BATCH 16
#define NB    1024
#define NS    4096
#define CDIM  768
#define HEADS 12
#define DH    64
#define TOPK  128
#define C4    3072

// ---------------- device scratch (no allocation allowed) ----------------
__device__ float g_q  [BATCH * (size_t)NB * CDIM];   // Q proj, later reused for O-proj out / MLP2 out? (see pipeline)
__device__ float g_k  [BATCH * (size_t)TOPK * CDIM];
__device__ float g_v  [BATCH * (size_t)TOPK * CDIM];
__device__ float g_ctx[BATCH * (size_t)NB * CDIM];   // attention context, reused for MLP2 out
__device__ float g_x1 [BATCH * (size_t)NB * CDIM];   // LN1 output
__device__ float g_h  [BATCH * (size_t)NB * C4];     // MLP hidden (201 MB)
__device__ float g_sel[BATCH * (size_t)TOPK * CDIM];
__device__ int   g_topk[BATCH * TOPK];

// ---------------- 1) saliency GEMM + row-max ----------------
// scores[b][i] = max_j dot(sampled[b][i], base[b][j]) / sqrt(C)
// grid (NS/64, B), 256 threads, 64x64 tile, k-chunk 32, fp32.
__global__ __launch_bounds__(256)
void saliency_kernel(const float* __restrict__ sampled,
                     const float* __restrict__ base,
                     float* __restrict__ scores)
{
    __shared__ float As[32][64];
    __shared__ float Bs[32][64];
    __shared__ float red[64][17];

    int b  = blockIdx.y;
    int r0 = blockIdx.x * 64;
    const float* A  = sampled + (size_t)b * NS * CDIM;
    const float* Bm = base    + (size_t)b * NB * CDIM;

    int tid = threadIdx.x;
    int tx = tid & 15, ty = tid >> 4;

    float rmax[4];
#pragma unroll
    for (int i = 0; i < 4; i++) rmax[i] = -3.4e38f;

    for (int jc = 0; jc < NB; jc += 64) {
        float acc[4][4] = {};
        for (int k0 = 0; k0 < CDIM; k0 += 32) {
#pragma unroll
            for (int i = 0; i < 2; i++) {
                int id  = tid + i * 256;
                int row = id >> 3;
                int kq  = (id & 7) * 4;
                float4 va = *(const float4*)(A  + (size_t)(r0 + row) * CDIM + k0 + kq);
                As[kq][row] = va.x; As[kq+1][row] = va.y; As[kq+2][row] = va.z; As[kq+3][row] = va.w;
                float4 vb = *(const float4*)(Bm + (size_t)(jc + row) * CDIM + k0 + kq);
                Bs[kq][row] = vb.x; Bs[kq+1][row] = vb.y; Bs[kq+2][row] = vb.z; Bs[kq+3][row] = vb.w;
            }
            __syncthreads();
#pragma unroll
            for (int kk = 0; kk < 32; kk++) {
                float4 a  = *(float4*)&As[kk][ty * 4];
                float4 bb = *(float4*)&Bs[kk][tx * 4];
                acc[0][0] += a.x * bb.x; acc[0][1] += a.x * bb.y; acc[0][2] += a.x * bb.z; acc[0][3] += a.x * bb.w;
                acc[1][0] += a.y * bb.x; acc[1][1] += a.y * bb.y; acc[1][2] += a.y * bb.z; acc[1][3] += a.y * bb.w;
                acc[2][0] += a.z * bb.x; acc[2][1] += a.z * bb.y; acc[2][2] += a.z * bb.z; acc[2][3] += a.z * bb.w;
                acc[3][0] += a.w * bb.x; acc[3][1] += a.w * bb.y; acc[3][2] += a.w * bb.z; acc[3][3] += a.w * bb.w;
            }
            __syncthreads();
        }
#pragma unroll
        for (int i = 0; i < 4; i++) {
            float m = fmaxf(fmaxf(acc[i][0], acc[i][1]), fmaxf(acc[i][2], acc[i][3]));
            rmax[i] = fmaxf(rmax[i], m);
        }
    }
#pragma unroll
    for (int i = 0; i < 4; i++) red[ty * 4 + i][tx] = rmax[i];
    __syncthreads();
    if (tid < 64) {
        float m = red[tid][0];
#pragma unroll
        for (int j = 1; j < 16; j++) m = fmaxf(m, red[tid][j]);
        scores[(size_t)b * NS + r0 + tid] = m * 0.03608439182435161f; // 1/sqrt(768)
    }
}

// ---------------- 2) exact top-k via bitonic sort ----------------
// key = (~ordered(score) << 32) | index; ascending sort => score desc, index asc (matches lax.top_k ties)
__global__ __launch_bounds__(1024)
void topk_kernel(const float* __restrict__ scores, float* __restrict__ topk_out)
{
    __shared__ unsigned long long keys[NS];
    int b = blockIdx.x, tid = threadIdx.x;
    for (int t = tid; t < NS; t += 1024) {
        unsigned int x = __float_as_uint(scores[(size_t)b * NS + t]);
        unsigned int u = (x & 0x80000000u) ? ~x : (x | 0x80000000u);
        keys[t] = (((unsigned long long)(~u)) << 32) | (unsigned int)t;
    }
    __syncthreads();
    for (int k = 2; k <= NS; k <<= 1) {
        for (int j = k >> 1; j > 0; j >>= 1) {
            for (int t = tid; t < NS; t += 1024) {
                int ixj = t ^ j;
                if (ixj > t) {
                    bool up = ((t & k) == 0);
                    unsigned long long a = keys[t], c = keys[ixj];
                    if ((a > c) == up) { keys[t] = c; keys[ixj] = a; }
                }
            }
            __syncthreads();
        }
    }
    if (tid < TOPK) {
        int idx = (int)(unsigned int)(keys[tid] & 0xFFFFFFFFull);
        g_topk[b * TOPK + tid] = idx;
        topk_out[b * TOPK + tid] = (float)idx;
    }
}

// ---------------- 3) gather selected tokens ----------------
__global__ __launch_bounds__(192)
void gather_kernel(const float* __restrict__ sampled, float* __restrict__ sel_out)
{
    int b = blockIdx.y, kk = blockIdx.x;
    int idx = g_topk[b * TOPK + kk];
    const float4* src = (const float4*)(sampled + ((size_t)b * NS + idx) * CDIM);
    float4 v = src[threadIdx.x];
    ((float4*)(g_sel   + ((size_t)b * TOPK + kk) * CDIM))[threadIdx.x] = v;
    ((float4*)(sel_out + ((size_t)b * TOPK + kk) * CDIM))[threadIdx.x] = v;
}

// ---------------- 4) generic SGEMM  C = A[MxK] @ W[KxN] + bias (opt. exact GELU) ----------------
template <int ACT>
__global__ __launch_bounds__(256)
void sgemm_kernel(const float* __restrict__ A, const float* __restrict__ W,
                  const float* __restrict__ bias, float* __restrict__ C,
                  int M, int N, int K)
{
    __shared__ float As[32][64];
    __shared__ float Bs[32][64];
    int n0 = blockIdx.x * 64, m0 = blockIdx.y * 64;
    int tid = threadIdx.x, tx = tid & 15, ty = tid >> 4;
    float acc[4][4] = {};
    for (int k0 = 0; k0 < K; k0 += 32) {
#pragma unroll
        for (int i = 0; i < 2; i++) {
            int id = tid + i * 256;
            int row = id >> 3, kq = (id & 7) * 4;
            float4 a = *(const float4*)(A + (size_t)(m0 + row) * K + k0 + kq);
            As[kq][row] = a.x; As[kq+1][row] = a.y; As[kq+2][row] = a.z; As[kq+3][row] = a.w;
            int wr = id >> 4, wc = (id & 15) * 4;
            *(float4*)&Bs[wr][wc] = *(const float4*)(W + (size_t)(k0 + wr) * N + n0 + wc);
        }
        __syncthreads();
#pragma unroll
        for (int kk = 0; kk < 32; kk++) {
            float4 a = *(float4*)&As[kk][ty * 4];
            float4 b = *(float4*)&Bs[kk][tx * 4];
            acc[0][0] += a.x * b.x; acc[0][1] += a.x * b.y; acc[0][2] += a.x * b.z; acc[0][3] += a.x * b.w;
            acc[1][0] += a.y * b.x; acc[1][1] += a.y * b.y; acc[1][2] += a.y * b.z; acc[1][3] += a.y * b.w;
            acc[2][0] += a.z * b.x; acc[2][1] += a.z * b.y; acc[2][2] += a.z * b.z; acc[2][3] += a.z * b.w;
            acc[3][0] += a.w * b.x; acc[3][1] += a.w * b.y; acc[3][2] += a.w * b.z; acc[3][3] += a.w * b.w;
        }
        __syncthreads();
    }
    float4 bv = *(const float4*)(bias + n0 + tx * 4);
    float bb[4] = { bv.x, bv.y, bv.z, bv.w };
#pragma unroll
    for (int i = 0; i < 4; i++) {
        float4 o;
        float* po = &o.x;
#pragma unroll
        for (int j = 0; j < 4; j++) {
            float c = acc[i][j] + bb[j];
            if (ACT == 1) c = 0.5f * c * (1.0f + erff(c * 0.70710678118654752f));
            po[j] = c;
        }
        *(float4*)(C + (size_t)(m0 + ty * 4 + i) * N + n0 + tx * 4) = o;
    }
}

// ---------------- 5) cross-attention (per b,h, 32 q-rows) ----------------
__global__ __launch_bounds__(256)
void attn_kernel(float* __restrict__ attn_out)
{
    int qt = blockIdx.x, h = blockIdx.y, b = blockIdx.z;
    int tid = threadIdx.x;
    __shared__ float Qts[64][36];   // Q^T (d-major), padded
    __shared__ float KV[64][68];    // K^T chunk / V chunk, padded (68%4==0 keeps float4 alignment)
    __shared__ float Ls[32][128];   // logits -> probs
    int qr0 = qt * 32;

    // load Q tile transposed
#pragma unroll
    for (int i = 0; i < 2; i++) {
        int id = tid + i * 256;
        int row = id >> 4, c4 = (id & 15) * 4;
        float4 v = *(const float4*)(g_q + ((size_t)(b * NB + qr0 + row)) * CDIM + h * DH + c4);
        Qts[c4][row] = v.x; Qts[c4+1][row] = v.y; Qts[c4+2][row] = v.z; Qts[c4+3][row] = v.w;
    }
    int ty = tid >> 4, tx = tid & 15;

    // ---- logits ----
#pragma unroll
    for (int ch = 0; ch < 2; ch++) {
        __syncthreads();
#pragma unroll
        for (int i = 0; i < 4; i++) {
            int id = tid + i * 256;
            int row = id >> 4, c4 = (id & 15) * 4;
            float4 v = *(const float4*)(g_k + ((size_t)(b * TOPK + ch * 64 + row)) * CDIM + h * DH + c4);
            KV[c4][row] = v.x; KV[c4+1][row] = v.y; KV[c4+2][row] = v.z; KV[c4+3][row] = v.w;
        }
        __syncthreads();
        int r = ty * 2, c = tx * 4;
        float acc[2][4] = {};
#pragma unroll
        for (int d = 0; d < 64; d++) {
            float a0 = Qts[d][r], a1 = Qts[d][r + 1];
            float4 kb = *(float4*)&KV[d][c];
            acc[0][0] += a0 * kb.x; acc[0][1] += a0 * kb.y; acc[0][2] += a0 * kb.z; acc[0][3] += a0 * kb.w;
            acc[1][0] += a1 * kb.x; acc[1][1] += a1 * kb.y; acc[1][2] += a1 * kb.z; acc[1][3] += a1 * kb.w;
        }
#pragma unroll
        for (int ii = 0; ii < 2; ii++)
#pragma unroll
            for (int jj = 0; jj < 4; jj++)
                Ls[r + ii][ch * 64 + c + jj] = acc[ii][jj] * 0.125f;  // 1/sqrt(64)
    }
    __syncthreads();

    // ---- softmax + write attn ----
    int warp = tid >> 5, lane = tid & 31;
    for (int r = warp; r < 32; r += 8) {
        float v0 = Ls[r][lane], v1 = Ls[r][lane + 32], v2 = Ls[r][lane + 64], v3 = Ls[r][lane + 96];
        float m = fmaxf(fmaxf(v0, v1), fmaxf(v2, v3));
#pragma unroll
        for (int o = 16; o; o >>= 1) m = fmaxf(m, __shfl_xor_sync(0xffffffffu, m, o));
        float e0 = expf(v0 - m), e1 = expf(v1 - m), e2 = expf(v2 - m), e3 = expf(v3 - m);
        float s = e0 + e1 + e2 + e3;
#pragma unroll
        for (int o = 16; o; o >>= 1) s += __shfl_xor_sync(0xffffffffu, s, o);
        float inv = 1.0f / s;
        e0 *= inv; e1 *= inv; e2 *= inv; e3 *= inv;
        Ls[r][lane] = e0; Ls[r][lane + 32] = e1; Ls[r][lane + 64] = e2; Ls[r][lane + 96] = e3;
        size_t o = (((size_t)(b * HEADS + h)) * NB + qr0 + r) * TOPK;
        attn_out[o + lane] = e0; attn_out[o + lane + 32] = e1;
        attn_out[o + lane + 64] = e2; attn_out[o + lane + 96] = e3;
    }

    // ---- ctx = P @ V ----
    int r = ty * 2, dc = tx * 4;
    float acc2[2][4] = {};
#pragma unroll
    for (int ch = 0; ch < 2; ch++) {
        __syncthreads();
#pragma unroll
        for (int i = 0; i < 4; i++) {
            int id = tid + i * 256;
            int row = id >> 4, c4 = (id & 15) * 4;
            *(float4*)&KV[row][c4] =
                *(const float4*)(g_v + ((size_t)(b * TOPK + ch * 64 + row)) * CDIM + h * DH + c4);
        }
        __syncthreads();
#pragma unroll
        for (int kv = 0; kv < 64; kv++) {
            float p0 = Ls[r][ch * 64 + kv], p1 = Ls[r + 1][ch * 64 + kv];
            float4 vv = *(float4*)&KV[kv][dc];
            acc2[0][0] += p0 * vv.x; acc2[0][1] += p0 * vv.y; acc2[0][2] += p0 * vv.z; acc2[0][3] += p0 * vv.w;
            acc2[1][0] += p1 * vv.x; acc2[1][1] += p1 * vv.y; acc2[1][2] += p1 * vv.z; acc2[1][3] += p1 * vv.w;
        }
    }
#pragma unroll
    for (int ii = 0; ii < 2; ii++) {
        float4 o = make_float4(acc2[ii][0], acc2[ii][1], acc2[ii][2], acc2[ii][3]);
        *(float4*)(g_ctx + ((size_t)(b * NB + qr0 + r + ii)) * CDIM + h * DH + dc) = o;
    }
}

// ---------------- 6) layernorm of (Xa + Xb) ----------------
__global__ __launch_bounds__(256)
void ln_kernel(const float* __restrict__ Xa, const float* __restrict__ Xb,
               const float* __restrict__ gam, const float* __restrict__ bet,
               float* __restrict__ outp)
{
    int row = blockIdx.x, tid = threadIdx.x;
    __shared__ float xb[CDIM];
    __shared__ float rs[16], rs2[16], stats[2];
    float s = 0.f, ss = 0.f;
    for (int c = tid; c < CDIM; c += 256) {
        float x = Xa[(size_t)row * CDIM + c] + Xb[(size_t)row * CDIM + c];
        xb[c] = x; s += x; ss += x * x;
    }
#pragma unroll
    for (int o = 16; o; o >>= 1) {
        s  += __shfl_xor_sync(0xffffffffu, s,  o);
        ss += __shfl_xor_sync(0xffffffffu, ss, o);
    }
    if ((tid & 31) == 0) { rs[tid >> 5] = s; rs2[tid >> 5] = ss; }
    __syncthreads();
    if (tid == 0) {
        float S = 0.f, SS = 0.f;
        for (int i = 0; i < 8; i++) { S += rs[i]; SS += rs2[i]; }
        float mu = S / CDIM;
        float var = SS / CDIM - mu * mu;
        stats[0] = mu; stats[1] = rsqrtf(var + 1e-5f);
    }
    __syncthreads();
    float mu = stats[0], rstd = stats[1];
    for (int c = tid; c < CDIM; c += 256)
        outp[(size_t)row * CDIM + c] = (xb[c] - mu) * rstd * gam[c] + bet[c];
}

// ---------------- launch ----------------
extern "C" void kernel_launch(void* const* d_in, const int* in_sizes, int n_in,
                              void* d_out, int out_size)
{
    const float* base    = (const float*)d_in[0];
    const float* sampled = (const float*)d_in[1];
    const float* Wq = (const float*)d_in[2];  const float* bq = (const float*)d_in[3];
    const float* Wk = (const float*)d_in[4];  const float* bk = (const float*)d_in[5];
    const float* Wv = (const float*)d_in[6];  const float* bv = (const float*)d_in[7];
    const float* Wo = (const float*)d_in[8];  const float* bo = (const float*)d_in[9];
    const float* g1 = (const float*)d_in[10]; const float* b1 = (const float*)d_in[11];
    const float* g2 = (const float*)d_in[12]; const float* b2 = (const float*)d_in[13];
    const float* Wm1 = (const float*)d_in[14]; const float* bm1 = (const float*)d_in[15];
    const float* Wm2 = (const float*)d_in[16]; const float* bm2 = (const float*)d_in[17];

    float* out = (float*)d_out;
    float* out_x      = out;
    float* out_scores = out + (size_t)BATCH * NB * CDIM;                 // 12582912
    float* out_attn   = out_scores + (size_t)BATCH * NS;                 // +65536
    float* out_topk   = out_attn + (size_t)BATCH * HEADS * NB * TOPK;    // +25165824
    float* out_sel    = out_topk + (size_t)BATCH * TOPK;                 // +2048

    float *p_q, *p_k, *p_v, *p_ctx, *p_x1, *p_h, *p_sel;
    cudaGetSymbolAddress((void**)&p_q,   g_q);
    cudaGetSymbolAddress((void**)&p_k,   g_k);
    cudaGetSymbolAddress((void**)&p_v,   g_v);
    cudaGetSymbolAddress((void**)&p_ctx, g_ctx);
    cudaGetSymbolAddress((void**)&p_x1,  g_x1);
    cudaGetSymbolAddress((void**)&p_h,   g_h);
    cudaGetSymbolAddress((void**)&p_sel, g_sel);

    const int M = BATCH * NB;   // 16384
    const int Ms = BATCH * TOPK; // 2048

    // 1) saliency + max
    saliency_kernel<<<dim3(NS / 64, BATCH), 256>>>(sampled, base, out_scores);
    // 2) top-k
    topk_kernel<<<BATCH, 1024>>>(out_scores, out_topk);
    // 3) gather
    gather_kernel<<<dim3(TOPK, BATCH), 192>>>(sampled, out_sel);
    // 4) projections
    sgemm_kernel<0><<<dim3(CDIM / 64, M / 64), 256>>>(base,  Wq, bq, p_q, M,  CDIM, CDIM);
    sgemm_kernel<0><<<dim3(CDIM / 64, Ms / 64), 256>>>(p_sel, Wk, bk, p_k, Ms, CDIM, CDIM);
    sgemm_kernel<0><<<dim3(CDIM / 64, Ms / 64), 256>>>(p_sel, Wv, bv, p_v, Ms, CDIM, CDIM);
    // 5) attention (writes attn probs to out, ctx to g_ctx)
    attn_kernel<<<dim3(NB / 32, HEADS, BATCH), 256>>>(out_attn);
    // 6) O-projection: g_ctx @ Wo + bo -> g_q (reuse)
    sgemm_kernel<0><<<dim3(CDIM / 64, M / 64), 256>>>(p_ctx, Wo, bo, p_q, M, CDIM, CDIM);
    // 7) LN1: LN(base + attended) -> g_x1
    ln_kernel<<<M, 256>>>(base, p_q, g1, b1, p_x1);
    // 8) MLP1 + exact GELU -> g_h
    sgemm_kernel<1><<<dim3(C4 / 64, M / 64), 256>>>(p_x1, Wm1, bm1, p_h, M, C4, CDIM);
    // 9) MLP2 -> g_ctx (reuse)
    sgemm_kernel<0><<<dim3(CDIM / 64, M / 64), 256>>>(p_h, Wm2, bm2, p_ctx, M, CDIM, C4);
    // 10) LN2: LN(x1 + h) -> out_x
    ln_kernel<<<M, 256>>>(p_x1, p_ctx, g2, b2, out_x);
}

// round 6
// speedup vs baseline: 1.3064x; 1.3064x over previous
#include <cuda_runtime.h>
#include <cuda_fp16.h>
#include <math.h>
#include <stdint.h>

#define BATCH 16
#define NB    1024
#define NS    4096
#define CDIM  768
#define HEADS 12
#define DH    64
#define TOPK  128
#define C4    3072

// ---------------- device scratch ----------------
__device__ float g_q  [BATCH * (size_t)NB * CDIM];
__device__ float g_k  [BATCH * (size_t)TOPK * CDIM];
__device__ float g_v  [BATCH * (size_t)TOPK * CDIM];
__device__ float g_ctx[BATCH * (size_t)NB * CDIM];
__device__ float g_x1 [BATCH * (size_t)NB * CDIM];
__device__ float g_sel[BATCH * (size_t)TOPK * CDIM];
__device__ int   g_topk[BATCH * TOPK];
// fp16 scratch
__device__ __half g_act_h [BATCH * (size_t)NB * CDIM];
__device__ __half g_sel_h [BATCH * (size_t)TOPK * CDIM];
__device__ __half g_h_h   [BATCH * (size_t)NB * C4];
__device__ __half g_WqT[CDIM * CDIM];
__device__ __half g_WkT[CDIM * CDIM];
__device__ __half g_WvT[CDIM * CDIM];
__device__ __half g_WoT[CDIM * CDIM];
__device__ __half g_Wm1T[(size_t)C4 * CDIM];   // [3072,768]
__device__ __half g_Wm2T[(size_t)CDIM * C4];   // [768,3072]

// ================= mma.sync fp16 GEMM =================
// C[M,N] = A[M,K](f16,row) @ Bt[N,K](f16,row == B col-major) + bias
// CTA tile 128x128, 256 thr (8 warps, 4m x 2n), warp tile 32x64, K chunk 32.
#define KCH   32
#define APAD  40   // row stride in halves (80 bytes; conflict-free ldmatrix)

__device__ __forceinline__ uint32_t smem_u32(const void* p) {
    uint32_t a;
    asm("{ .reg .u64 t; cvta.to.shared.u64 t, %1; cvt.u32.u64 %0, t; }" : "=r"(a) : "l"(p));
    return a;
}

template <int ACT, int OUTH>
__global__ __launch_bounds__(256)
void gemm_mma(const __half* __restrict__ A, const __half* __restrict__ Bt,
              const float* __restrict__ bias, float* __restrict__ Cf,
              __half* __restrict__ Ch, int M, int N, int K)
{
    __shared__ __half sA[2][128][APAD];
    __shared__ __half sB[2][128][APAD];

    int tid = threadIdx.x, warp = tid >> 5, lane = tid & 31;
    int m0 = blockIdx.y * 128, n0 = blockIdx.x * 128;
    int wm = (warp >> 1) * 32;
    int wn = (warp & 1) * 64;

    const __half* Ab = A  + (size_t)m0 * K;
    const __half* Bb = Bt + (size_t)n0 * K;

    int r0 = tid >> 2,         q0 = (tid & 3) * 8;
    int r1 = (tid + 256) >> 2, q1 = ((tid + 256) & 3) * 8;

    uint4 ra0, ra1, rb0, rb1;
    ra0 = *(const uint4*)(Ab + (size_t)r0 * K + q0);
    ra1 = *(const uint4*)(Ab + (size_t)r1 * K + q1);
    rb0 = *(const uint4*)(Bb + (size_t)r0 * K + q0);
    rb1 = *(const uint4*)(Bb + (size_t)r1 * K + q1);
    *(uint4*)&sA[0][r0][q0] = ra0;  *(uint4*)&sA[0][r1][q1] = ra1;
    *(uint4*)&sB[0][r0][q0] = rb0;  *(uint4*)&sB[0][r1][q1] = rb1;
    __syncthreads();

    float acc[2][8][4];
#pragma unroll
    for (int i = 0; i < 2; i++)
#pragma unroll
        for (int j = 0; j < 8; j++)
#pragma unroll
            for (int t = 0; t < 4; t++) acc[i][j][t] = 0.f;

    int nch = K / KCH;
    int a_row = lane & 15, a_kh = (lane >> 4) * 8;
    int b_row = lane & 7,  b_kh = ((lane >> 3) & 1) * 8;

    for (int c = 0; c < nch; c++) {
        int cur = c & 1;
        if (c + 1 < nch) {
            const __half* An = Ab + (size_t)(c + 1) * KCH;
            const __half* Bn = Bb + (size_t)(c + 1) * KCH;
            ra0 = *(const uint4*)(An + (size_t)r0 * K + q0);
            ra1 = *(const uint4*)(An + (size_t)r1 * K + q1);
            rb0 = *(const uint4*)(Bn + (size_t)r0 * K + q0);
            rb1 = *(const uint4*)(Bn + (size_t)r1 * K + q1);
        }
#pragma unroll
        for (int ks = 0; ks < 2; ks++) {
            int kk = ks * 16;
            uint32_t afr[2][4];
#pragma unroll
            for (int mt = 0; mt < 2; mt++) {
                uint32_t addr = smem_u32(&sA[cur][wm + mt * 16 + a_row][kk + a_kh]);
                asm volatile("ldmatrix.sync.aligned.m8n8.x4.shared.b16 {%0,%1,%2,%3}, [%4];"
                    : "=r"(afr[mt][0]), "=r"(afr[mt][1]), "=r"(afr[mt][2]), "=r"(afr[mt][3])
                    : "r"(addr));
            }
#pragma unroll
            for (int nt = 0; nt < 8; nt++) {
                uint32_t bfr[2];
                uint32_t addr = smem_u32(&sB[cur][wn + nt * 8 + b_row][kk + b_kh]);
                asm volatile("ldmatrix.sync.aligned.m8n8.x2.shared.b16 {%0,%1}, [%2];"
                    : "=r"(bfr[0]), "=r"(bfr[1]) : "r"(addr));
#pragma unroll
                for (int mt = 0; mt < 2; mt++) {
                    asm volatile(
                        "mma.sync.aligned.m16n8k16.row.col.f32.f16.f16.f32 "
                        "{%0,%1,%2,%3}, {%4,%5,%6,%7}, {%8,%9}, {%0,%1,%2,%3};"
                        : "+f"(acc[mt][nt][0]), "+f"(acc[mt][nt][1]),
                          "+f"(acc[mt][nt][2]), "+f"(acc[mt][nt][3])
                        : "r"(afr[mt][0]), "r"(afr[mt][1]), "r"(afr[mt][2]), "r"(afr[mt][3]),
                          "r"(bfr[0]), "r"(bfr[1]));
                }
            }
        }
        if (c + 1 < nch) {
            int nxt = cur ^ 1;
            *(uint4*)&sA[nxt][r0][q0] = ra0;  *(uint4*)&sA[nxt][r1][q1] = ra1;
            *(uint4*)&sB[nxt][r0][q0] = rb0;  *(uint4*)&sB[nxt][r1][q1] = rb1;
        }
        __syncthreads();
    }

    int g = lane >> 2, t4 = (lane & 3) * 2;
#pragma unroll
    for (int mt = 0; mt < 2; mt++) {
#pragma unroll
        for (int nt = 0; nt < 8; nt++) {
            int col = n0 + wn + nt * 8 + t4;
            float b0 = bias[col], b1 = bias[col + 1];
#pragma unroll
            for (int half_i = 0; half_i < 2; half_i++) {
                int row = m0 + wm + mt * 16 + g + half_i * 8;
                float x0 = acc[mt][nt][half_i * 2 + 0] + b0;
                float x1 = acc[mt][nt][half_i * 2 + 1] + b1;
                if (ACT == 1) {
                    x0 = 0.5f * x0 * (1.0f + erff(x0 * 0.70710678118654752f));
                    x1 = 0.5f * x1 * (1.0f + erff(x1 * 0.70710678118654752f));
                }
                if (OUTH) {
                    *(__half2*)(Ch + (size_t)row * N + col) = __floats2half2_rn(x0, x1);
                } else {
                    *(float2*)(Cf + (size_t)row * N + col) = make_float2(x0, x1);
                }
            }
        }
    }
}

// ================= converts / transposes =================
__global__ __launch_bounds__(256)
void cvt_h_kernel(const float* __restrict__ in, __half* __restrict__ out, int n4)
{
    int i = blockIdx.x * 256 + threadIdx.x;
    if (i < n4) {
        float4 v = ((const float4*)in)[i];
        ((__half2*)out)[2 * i]     = __floats2half2_rn(v.x, v.y);
        ((__half2*)out)[2 * i + 1] = __floats2half2_rn(v.z, v.w);
    }
}

// W [K,N] fp32 -> WT [N,K] fp16
__global__ __launch_bounds__(256)
void transpose_h_kernel(const float* __restrict__ in, __half* __restrict__ out, int K, int N)
{
    __shared__ float t[32][33];
    int k0 = blockIdx.y * 32, n0 = blockIdx.x * 32;
    int tx = threadIdx.x & 31, ty = threadIdx.x >> 5;
#pragma unroll
    for (int i = 0; i < 4; i++)
        t[ty + i * 8][tx] = in[(size_t)(k0 + ty + i * 8) * N + n0 + tx];
    __syncthreads();
#pragma unroll
    for (int i = 0; i < 4; i++)
        out[(size_t)(n0 + ty + i * 8) * K + k0 + tx] = __float2half(t[tx][ty + i * 8]);
}

// ================= saliency (fp32, exact) =================
__global__ __launch_bounds__(256)
void saliency_kernel(const float* __restrict__ sampled,
                     const float* __restrict__ base,
                     float* __restrict__ scores)
{
    __shared__ float As[32][64];
    __shared__ float Bs[32][64];
    __shared__ float red[64][17];
    int b = blockIdx.y;
    int r0 = blockIdx.x * 64;
    const float* A = sampled + (size_t)b * NS * CDIM;
    const float* Bm = base + (size_t)b * NB * CDIM;
    int tid = threadIdx.x, tx = tid & 15, ty = tid >> 4;
    float rmax[4];
#pragma unroll
    for (int i = 0; i < 4; i++) rmax[i] = -3.4e38f;
    for (int jc = 0; jc < NB; jc += 64) {
        float acc[4][4] = {};
        for (int k0 = 0; k0 < CDIM; k0 += 32) {
#pragma unroll
            for (int i = 0; i < 2; i++) {
                int id = tid + i * 256;
                int row = id >> 3, kq = (id & 7) * 4;
                float4 va = *(const float4*)(A + (size_t)(r0 + row) * CDIM + k0 + kq);
                As[kq][row] = va.x; As[kq+1][row] = va.y; As[kq+2][row] = va.z; As[kq+3][row] = va.w;
                float4 vb = *(const float4*)(Bm + (size_t)(jc + row) * CDIM + k0 + kq);
                Bs[kq][row] = vb.x; Bs[kq+1][row] = vb.y; Bs[kq+2][row] = vb.z; Bs[kq+3][row] = vb.w;
            }
            __syncthreads();
#pragma unroll
            for (int kk = 0; kk < 32; kk++) {
                float4 a = *(float4*)&As[kk][ty * 4];
                float4 bb = *(float4*)&Bs[kk][tx * 4];
                acc[0][0] += a.x*bb.x; acc[0][1] += a.x*bb.y; acc[0][2] += a.x*bb.z; acc[0][3] += a.x*bb.w;
                acc[1][0] += a.y*bb.x; acc[1][1] += a.y*bb.y; acc[1][2] += a.y*bb.z; acc[1][3] += a.y*bb.w;
                acc[2][0] += a.z*bb.x; acc[2][1] += a.z*bb.y; acc[2][2] += a.z*bb.z; acc[2][3] += a.z*bb.w;
                acc[3][0] += a.w*bb.x; acc[3][1] += a.w*bb.y; acc[3][2] += a.w*bb.z; acc[3][3] += a.w*bb.w;
            }
            __syncthreads();
        }
#pragma unroll
        for (int i = 0; i < 4; i++) {
            float m = fmaxf(fmaxf(acc[i][0], acc[i][1]), fmaxf(acc[i][2], acc[i][3]));
            rmax[i] = fmaxf(rmax[i], m);
        }
    }
#pragma unroll
    for (int i = 0; i < 4; i++) red[ty * 4 + i][tx] = rmax[i];
    __syncthreads();
    if (tid < 64) {
        float m = red[tid][0];
#pragma unroll
        for (int j = 1; j < 16; j++) m = fmaxf(m, red[tid][j]);
        scores[(size_t)b * NS + r0 + tid] = m * 0.03608439182435161f;
    }
}

// ================= top-k =================
__global__ __launch_bounds__(1024)
void topk_kernel(const float* __restrict__ scores, float* __restrict__ topk_out)
{
    __shared__ unsigned long long keys[NS];
    int b = blockIdx.x, tid = threadIdx.x;
    for (int t = tid; t < NS; t += 1024) {
        unsigned int x = __float_as_uint(scores[(size_t)b * NS + t]);
        unsigned int u = (x & 0x80000000u) ? ~x : (x | 0x80000000u);
        keys[t] = (((unsigned long long)(~u)) << 32) | (unsigned int)t;
    }
    __syncthreads();
    for (int k = 2; k <= NS; k <<= 1) {
        for (int j = k >> 1; j > 0; j >>= 1) {
            for (int t = tid; t < NS; t += 1024) {
                int ixj = t ^ j;
                if (ixj > t) {
                    bool up = ((t & k) == 0);
                    unsigned long long a = keys[t], c = keys[ixj];
                    if ((a > c) == up) { keys[t] = c; keys[ixj] = a; }
                }
            }
            __syncthreads();
        }
    }
    if (tid < TOPK) {
        int idx = (int)(unsigned int)(keys[tid] & 0xFFFFFFFFull);
        g_topk[b * TOPK + tid] = idx;
        topk_out[b * TOPK + tid] = (float)idx;
    }
}

// ================= gather =================
__global__ __launch_bounds__(192)
void gather_kernel(const float* __restrict__ sampled, float* __restrict__ sel_out)
{
    int b = blockIdx.y, kk = blockIdx.x;
    int idx = g_topk[b * TOPK + kk];
    const float4* src = (const float4*)(sampled + ((size_t)b * NS + idx) * CDIM);
    float4 v = src[threadIdx.x];
    ((float4*)(g_sel   + ((size_t)b * TOPK + kk) * CDIM))[threadIdx.x] = v;
    ((float4*)(sel_out + ((size_t)b * TOPK + kk) * CDIM))[threadIdx.x] = v;
}

// ================= attention =================
__global__ __launch_bounds__(256)
void attn_kernel(float* __restrict__ attn_out)
{
    int qt = blockIdx.x, h = blockIdx.y, b = blockIdx.z;
    int tid = threadIdx.x;
    __shared__ float Qts[64][36];
    __shared__ float KV[64][68];
    __shared__ float Ls[32][128];
    int qr0 = qt * 32;
#pragma unroll
    for (int i = 0; i < 2; i++) {
        int id = tid + i * 256;
        int row = id >> 4, c4 = (id & 15) * 4;
        float4 v = *(const float4*)(g_q + ((size_t)(b * NB + qr0 + row)) * CDIM + h * DH + c4);
        Qts[c4][row] = v.x; Qts[c4+1][row] = v.y; Qts[c4+2][row] = v.z; Qts[c4+3][row] = v.w;
    }
    int ty = tid >> 4, tx = tid & 15;
#pragma unroll
    for (int ch = 0; ch < 2; ch++) {
        __syncthreads();
#pragma unroll
        for (int i = 0; i < 4; i++) {
            int id = tid + i * 256;
            int row = id >> 4, c4 = (id & 15) * 4;
            float4 v = *(const float4*)(g_k + ((size_t)(b * TOPK + ch * 64 + row)) * CDIM + h * DH + c4);
            KV[c4][row] = v.x; KV[c4+1][row] = v.y; KV[c4+2][row] = v.z; KV[c4+3][row] = v.w;
        }
        __syncthreads();
        int r = ty * 2, c = tx * 4;
        float acc[2][4] = {};
#pragma unroll
        for (int d = 0; d < 64; d++) {
            float a0 = Qts[d][r], a1 = Qts[d][r + 1];
            float4 kb = *(float4*)&KV[d][c];
            acc[0][0] += a0*kb.x; acc[0][1] += a0*kb.y; acc[0][2] += a0*kb.z; acc[0][3] += a0*kb.w;
            acc[1][0] += a1*kb.x; acc[1][1] += a1*kb.y; acc[1][2] += a1*kb.z; acc[1][3] += a1*kb.w;
        }
#pragma unroll
        for (int ii = 0; ii < 2; ii++)
#pragma unroll
            for (int jj = 0; jj < 4; jj++)
                Ls[r + ii][ch * 64 + c + jj] = acc[ii][jj] * 0.125f;
    }
    __syncthreads();
    int warp = tid >> 5, lane = tid & 31;
    for (int r = warp; r < 32; r += 8) {
        float v0 = Ls[r][lane], v1 = Ls[r][lane + 32], v2 = Ls[r][lane + 64], v3 = Ls[r][lane + 96];
        float m = fmaxf(fmaxf(v0, v1), fmaxf(v2, v3));
#pragma unroll
        for (int o = 16; o; o >>= 1) m = fmaxf(m, __shfl_xor_sync(0xffffffffu, m, o));
        float e0 = expf(v0 - m), e1 = expf(v1 - m), e2 = expf(v2 - m), e3 = expf(v3 - m);
        float s = e0 + e1 + e2 + e3;
#pragma unroll
        for (int o = 16; o; o >>= 1) s += __shfl_xor_sync(0xffffffffu, s, o);
        float inv = 1.0f / s;
        e0 *= inv; e1 *= inv; e2 *= inv; e3 *= inv;
        Ls[r][lane] = e0; Ls[r][lane + 32] = e1; Ls[r][lane + 64] = e2; Ls[r][lane + 96] = e3;
        size_t o = (((size_t)(b * HEADS + h)) * NB + qr0 + r) * TOPK;
        attn_out[o + lane] = e0; attn_out[o + lane + 32] = e1;
        attn_out[o + lane + 64] = e2; attn_out[o + lane + 96] = e3;
    }
    int r = ty * 2, dc = tx * 4;
    float acc2[2][4] = {};
#pragma unroll
    for (int ch = 0; ch < 2; ch++) {
        __syncthreads();
#pragma unroll
        for (int i = 0; i < 4; i++) {
            int id = tid + i * 256;
            int row = id >> 4, c4 = (id & 15) * 4;
            *(float4*)&KV[row][c4] =
                *(const float4*)(g_v + ((size_t)(b * TOPK + ch * 64 + row)) * CDIM + h * DH + c4);
        }
        __syncthreads();
#pragma unroll
        for (int kv = 0; kv < 64; kv++) {
            float p0 = Ls[r][ch * 64 + kv], p1 = Ls[r + 1][ch * 64 + kv];
            float4 vv = *(float4*)&KV[kv][dc];
            acc2[0][0] += p0*vv.x; acc2[0][1] += p0*vv.y; acc2[0][2] += p0*vv.z; acc2[0][3] += p0*vv.w;
            acc2[1][0] += p1*vv.x; acc2[1][1] += p1*vv.y; acc2[1][2] += p1*vv.z; acc2[1][3] += p1*vv.w;
        }
    }
#pragma unroll
    for (int ii = 0; ii < 2; ii++) {
        float4 o = make_float4(acc2[ii][0], acc2[ii][1], acc2[ii][2], acc2[ii][3]);
        *(float4*)(g_ctx + ((size_t)(b * NB + qr0 + r + ii)) * CDIM + h * DH + dc) = o;
    }
}

// ================= layernorm =================
__global__ __launch_bounds__(256)
void ln_kernel(const float* __restrict__ Xa, const float* __restrict__ Xb,
               const float* __restrict__ gam, const float* __restrict__ bet,
               float* __restrict__ outp)
{
    int row = blockIdx.x, tid = threadIdx.x;
    __shared__ float xb[CDIM];
    __shared__ float rs[16], rs2[16], stats[2];
    float s = 0.f, ss = 0.f;
    for (int c = tid; c < CDIM; c += 256) {
        float x = Xa[(size_t)row * CDIM + c] + Xb[(size_t)row * CDIM + c];
        xb[c] = x; s += x; ss += x * x;
    }
#pragma unroll
    for (int o = 16; o; o >>= 1) {
        s  += __shfl_xor_sync(0xffffffffu, s,  o);
        ss += __shfl_xor_sync(0xffffffffu, ss, o);
    }
    if ((tid & 31) == 0) { rs[tid >> 5] = s; rs2[tid >> 5] = ss; }
    __syncthreads();
    if (tid == 0) {
        float S = 0.f, SS = 0.f;
        for (int i = 0; i < 8; i++) { S += rs[i]; SS += rs2[i]; }
        float mu = S / CDIM;
        float var = SS / CDIM - mu * mu;
        stats[0] = mu; stats[1] = rsqrtf(var + 1e-5f);
    }
    __syncthreads();
    float mu = stats[0], rstd = stats[1];
    for (int c = tid; c < CDIM; c += 256)
        outp[(size_t)row * CDIM + c] = (xb[c] - mu) * rstd * gam[c] + bet[c];
}

// ================= launch =================
extern "C" void kernel_launch(void* const* d_in, const int* in_sizes, int n_in,
                              void* d_out, int out_size)
{
    const float* base    = (const float*)d_in[0];
    const float* sampled = (const float*)d_in[1];
    const float* Wq = (const float*)d_in[2];  const float* bq = (const float*)d_in[3];
    const float* Wk = (const float*)d_in[4];  const float* bk = (const float*)d_in[5];
    const float* Wv = (const float*)d_in[6];  const float* bv = (const float*)d_in[7];
    const float* Wo = (const float*)d_in[8];  const float* bo = (const float*)d_in[9];
    const float* g1 = (const float*)d_in[10]; const float* b1 = (const float*)d_in[11];
    const float* g2 = (const float*)d_in[12]; const float* b2 = (const float*)d_in[13];
    const float* Wm1 = (const float*)d_in[14]; const float* bm1 = (const float*)d_in[15];
    const float* Wm2 = (const float*)d_in[16]; const float* bm2 = (const float*)d_in[17];

    float* out = (float*)d_out;
    float* out_x      = out;
    float* out_scores = out + (size_t)BATCH * NB * CDIM;
    float* out_attn   = out_scores + (size_t)BATCH * NS;
    float* out_topk   = out_attn + (size_t)BATCH * HEADS * NB * TOPK;
    float* out_sel    = out_topk + (size_t)BATCH * TOPK;

    float *p_q, *p_k, *p_v, *p_ctx, *p_x1, *p_sel;
    __half *p_act, *p_selh, *p_h, *p_WqT, *p_WkT, *p_WvT, *p_WoT, *p_Wm1T, *p_Wm2T;
    cudaGetSymbolAddress((void**)&p_q,    g_q);
    cudaGetSymbolAddress((void**)&p_k,    g_k);
    cudaGetSymbolAddress((void**)&p_v,    g_v);
    cudaGetSymbolAddress((void**)&p_ctx,  g_ctx);
    cudaGetSymbolAddress((void**)&p_x1,   g_x1);
    cudaGetSymbolAddress((void**)&p_sel,  g_sel);
    cudaGetSymbolAddress((void**)&p_act,  g_act_h);
    cudaGetSymbolAddress((void**)&p_selh, g_sel_h);
    cudaGetSymbolAddress((void**)&p_h,    g_h_h);
    cudaGetSymbolAddress((void**)&p_WqT,  g_WqT);
    cudaGetSymbolAddress((void**)&p_WkT,  g_WkT);
    cudaGetSymbolAddress((void**)&p_WvT,  g_WvT);
    cudaGetSymbolAddress((void**)&p_WoT,  g_WoT);
    cudaGetSymbolAddress((void**)&p_Wm1T, g_Wm1T);
    cudaGetSymbolAddress((void**)&p_Wm2T, g_Wm2T);

    const int M  = BATCH * NB;    // 16384
    const int Ms = BATCH * TOPK;  // 2048

    // weight transposes (fp16, [N,K])
    transpose_h_kernel<<<dim3(CDIM/32, CDIM/32), 256>>>(Wq,  p_WqT,  CDIM, CDIM);
    transpose_h_kernel<<<dim3(CDIM/32, CDIM/32), 256>>>(Wk,  p_WkT,  CDIM, CDIM);
    transpose_h_kernel<<<dim3(CDIM/32, CDIM/32), 256>>>(Wv,  p_WvT,  CDIM, CDIM);
    transpose_h_kernel<<<dim3(CDIM/32, CDIM/32), 256>>>(Wo,  p_WoT,  CDIM, CDIM);
    transpose_h_kernel<<<dim3(C4/32,   CDIM/32), 256>>>(Wm1, p_Wm1T, CDIM, C4);
    transpose_h_kernel<<<dim3(CDIM/32, C4/32),   256>>>(Wm2, p_Wm2T, C4, CDIM);

    // 1) saliency (fp32, exact) + top-k + gather
    saliency_kernel<<<dim3(NS / 64, BATCH), 256>>>(sampled, base, out_scores);
    topk_kernel<<<BATCH, 1024>>>(out_scores, out_topk);
    gather_kernel<<<dim3(TOPK, BATCH), 192>>>(sampled, out_sel);

    // 2) converts
    cvt_h_kernel<<<(M * CDIM / 4 + 255) / 256, 256>>>(base, p_act, M * CDIM / 4);
    cvt_h_kernel<<<(Ms * CDIM / 4 + 255) / 256, 256>>>(p_sel, p_selh, Ms * CDIM / 4);

    // 3) Q/K/V projections (tensor cores via mma.sync fp16)
    gemm_mma<0,0><<<dim3(CDIM/128, M/128),  256>>>(p_act,  p_WqT, bq, p_q, nullptr, M,  CDIM, CDIM);
    gemm_mma<0,0><<<dim3(CDIM/128, Ms/128), 256>>>(p_selh, p_WkT, bk, p_k, nullptr, Ms, CDIM, CDIM);
    gemm_mma<0,0><<<dim3(CDIM/128, Ms/128), 256>>>(p_selh, p_WvT, bv, p_v, nullptr, Ms, CDIM, CDIM);

    // 4) attention
    attn_kernel<<<dim3(NB / 32, HEADS, BATCH), 256>>>(out_attn);

    // 5) O-projection
    cvt_h_kernel<<<(M * CDIM / 4 + 255) / 256, 256>>>(p_ctx, p_act, M * CDIM / 4);
    gemm_mma<0,0><<<dim3(CDIM/128, M/128), 256>>>(p_act, p_WoT, bo, p_q, nullptr, M, CDIM, CDIM);

    // 6) LN1 + MLP + LN2
    ln_kernel<<<M, 256>>>(base, p_q, g1, b1, p_x1);
    cvt_h_kernel<<<(M * CDIM / 4 + 255) / 256, 256>>>(p_x1, p_act, M * CDIM / 4);
    gemm_mma<1,1><<<dim3(C4/128, M/128), 256>>>(p_act, p_Wm1T, bm1, nullptr, p_h, M, C4, CDIM);
    gemm_mma<0,0><<<dim3(CDIM/128, M/128), 256>>>(p_h, p_Wm2T, bm2, p_ctx, nullptr, M, CDIM, C4);
    ln_kernel<<<M, 256>>>(p_x1, p_ctx, g2, b2, out_x);
}

// round 8
// speedup vs baseline: 4.1942x; 3.2106x over previous
#include <cuda_runtime.h>
#include <cuda_fp16.h>
#include <math.h>
#include <stdint.h>

#define BATCH 16
#define NB    1024
#define NS    4096
#define CDIM  768
#define HEADS 12
#define DH    64
#define TOPK  128
#define C4    3072

// ---------------- device scratch ----------------
__device__ float g_q  [BATCH * (size_t)NB * CDIM];
__device__ float g_k  [BATCH * (size_t)TOPK * CDIM];
__device__ float g_v  [BATCH * (size_t)TOPK * CDIM];
__device__ float g_ctx[BATCH * (size_t)NB * CDIM];
__device__ float g_x1 [BATCH * (size_t)NB * CDIM];
__device__ float g_sel[BATCH * (size_t)TOPK * CDIM];
__device__ int   g_topk[BATCH * TOPK];
// fp16 scratch
__device__ __half g_act_h [BATCH * (size_t)NB * CDIM];
__device__ __half g_sel_h [BATCH * (size_t)TOPK * CDIM];
__device__ __half g_h_h   [BATCH * (size_t)NB * C4];
__device__ __half g_WqT[CDIM * CDIM];
__device__ __half g_WkT[CDIM * CDIM];
__device__ __half g_WvT[CDIM * CDIM];
__device__ __half g_WoT[CDIM * CDIM];
__device__ __half g_Wm1T[(size_t)C4 * CDIM];
__device__ __half g_Wm2T[(size_t)CDIM * C4];
// split-fp16 saliency operands
__device__ __half g_s_hi[BATCH * (size_t)NS * CDIM];
__device__ __half g_s_lo[BATCH * (size_t)NS * CDIM];
__device__ __half g_b_hi[BATCH * (size_t)NB * CDIM];
__device__ __half g_b_lo[BATCH * (size_t)NB * CDIM];

// ================= helpers =================
__device__ __forceinline__ uint32_t smem_u32(const void* p) {
    uint32_t a;
    asm("{ .reg .u64 t; cvta.to.shared.u64 t, %1; cvt.u32.u64 %0, t; }" : "=r"(a) : "l"(p));
    return a;
}
__device__ __forceinline__ void cp16(uint32_t dst, const void* src) {
    asm volatile("cp.async.cg.shared.global [%0], [%1], 16;" :: "r"(dst), "l"(src));
}
#define CP_COMMIT() asm volatile("cp.async.commit_group;" ::: "memory")
#define CP_WAIT(n)  asm volatile("cp.async.wait_group %0;" :: "n"(n) : "memory")

#define KCH 32
// row stride 80B (40 halves): conflict-free ldmatrix
#define ROWB 80

__device__ __forceinline__ void ldmA(uint32_t addr, uint32_t* f) {
    asm volatile("ldmatrix.sync.aligned.m8n8.x4.shared.b16 {%0,%1,%2,%3}, [%4];"
        : "=r"(f[0]), "=r"(f[1]), "=r"(f[2]), "=r"(f[3]) : "r"(addr));
}
__device__ __forceinline__ void ldmB(uint32_t addr, uint32_t* f) {
    asm volatile("ldmatrix.sync.aligned.m8n8.x2.shared.b16 {%0,%1}, [%2];"
        : "=r"(f[0]), "=r"(f[1]) : "r"(addr));
}
__device__ __forceinline__ void hmma(float* d, const uint32_t* a, const uint32_t* b) {
    asm volatile(
        "mma.sync.aligned.m16n8k16.row.col.f32.f16.f16.f32 "
        "{%0,%1,%2,%3}, {%4,%5,%6,%7}, {%8,%9}, {%0,%1,%2,%3};"
        : "+f"(d[0]), "+f"(d[1]), "+f"(d[2]), "+f"(d[3])
        : "r"(a[0]), "r"(a[1]), "r"(a[2]), "r"(a[3]), "r"(b[0]), "r"(b[1]));
}

// ================= projection/MLP GEMM: cp.async 3-stage =================
// C[M,N] = A[M,K] @ Bt[N,K]^T + bias. CTA 128x128, 8 warps (4m x 2n), warp 32x64.
#define G_ST_B  20480        // stage bytes: A 10240 + B 10240
#define G_SMEM  (3 * G_ST_B) // 61440

template <int ACT, int OUTH>
__global__ __launch_bounds__(256)
void gemm_mma(const __half* __restrict__ A, const __half* __restrict__ Bt,
              const float* __restrict__ bias, float* __restrict__ Cf,
              __half* __restrict__ Ch, int M, int N, int K)
{
    extern __shared__ char dsm[];
    uint32_t su = smem_u32(dsm);
    int tid = threadIdx.x, warp = tid >> 5, lane = tid & 31;
    int m0 = blockIdx.y * 128, n0 = blockIdx.x * 128;
    int wm = (warp >> 1) * 32, wn = (warp & 1) * 64;

    const __half* Ab = A  + (size_t)m0 * K;
    const __half* Bb = Bt + (size_t)n0 * K;

    int row0 = tid >> 2, seg0 = (tid & 3);
    int row1 = (tid + 256) >> 2, seg1 = ((tid + 256) & 3);

    int nch = K / KCH;
    // prefetch stages 0,1
#pragma unroll
    for (int s = 0; s < 2; s++) {
        uint32_t sb = su + s * G_ST_B;
        const __half* As = Ab + (size_t)s * KCH;
        const __half* Bs = Bb + (size_t)s * KCH;
        cp16(sb + row0 * ROWB + seg0 * 16, As + (size_t)row0 * K + seg0 * 8);
        cp16(sb + row1 * ROWB + seg1 * 16, As + (size_t)row1 * K + seg1 * 8);
        cp16(sb + 10240 + row0 * ROWB + seg0 * 16, Bs + (size_t)row0 * K + seg0 * 8);
        cp16(sb + 10240 + row1 * ROWB + seg1 * 16, Bs + (size_t)row1 * K + seg1 * 8);
        CP_COMMIT();
    }

    float acc[2][8][4];
#pragma unroll
    for (int i = 0; i < 2; i++)
#pragma unroll
        for (int j = 0; j < 8; j++)
#pragma unroll
            for (int t = 0; t < 4; t++) acc[i][j][t] = 0.f;

    int a_row = lane & 15, a_kh = (lane >> 4) * 8;
    int b_row = lane & 7,  b_kh = ((lane >> 3) & 1) * 8;

    for (int c = 0; c < nch; c++) {
        CP_WAIT(1);
        __syncthreads();
        if (c + 2 < nch) {
            int st = (c + 2) % 3;
            uint32_t sb = su + st * G_ST_B;
            const __half* As = Ab + (size_t)(c + 2) * KCH;
            const __half* Bs = Bb + (size_t)(c + 2) * KCH;
            cp16(sb + row0 * ROWB + seg0 * 16, As + (size_t)row0 * K + seg0 * 8);
            cp16(sb + row1 * ROWB + seg1 * 16, As + (size_t)row1 * K + seg1 * 8);
            cp16(sb + 10240 + row0 * ROWB + seg0 * 16, Bs + (size_t)row0 * K + seg0 * 8);
            cp16(sb + 10240 + row1 * ROWB + seg1 * 16, Bs + (size_t)row1 * K + seg1 * 8);
            CP_COMMIT();
        } else {
            CP_COMMIT(); // keep group count in sync for CP_WAIT(1)
        }
        uint32_t sb = su + (c % 3) * G_ST_B;
#pragma unroll
        for (int ks = 0; ks < 2; ks++) {
            int kk = ks * 16;
            uint32_t afr[2][4];
#pragma unroll
            for (int mt = 0; mt < 2; mt++)
                ldmA(sb + (wm + mt * 16 + a_row) * ROWB + (kk + a_kh) * 2, afr[mt]);
#pragma unroll
            for (int nt = 0; nt < 8; nt++) {
                uint32_t bfr[2];
                ldmB(sb + 10240 + (wn + nt * 8 + b_row) * ROWB + (kk + b_kh) * 2, bfr);
                hmma(acc[0][nt], afr[0], bfr);
                hmma(acc[1][nt], afr[1], bfr);
            }
        }
    }

    int g = lane >> 2, t4 = (lane & 3) * 2;
#pragma unroll
    for (int mt = 0; mt < 2; mt++) {
#pragma unroll
        for (int nt = 0; nt < 8; nt++) {
            int col = n0 + wn + nt * 8 + t4;
            float b0 = bias[col], b1 = bias[col + 1];
#pragma unroll
            for (int hf = 0; hf < 2; hf++) {
                int row = m0 + wm + mt * 16 + g + hf * 8;
                float x0 = acc[mt][nt][hf * 2 + 0] + b0;
                float x1 = acc[mt][nt][hf * 2 + 1] + b1;
                if (ACT == 1) {
                    x0 = 0.5f * x0 * (1.0f + erff(x0 * 0.70710678118654752f));
                    x1 = 0.5f * x1 * (1.0f + erff(x1 * 0.70710678118654752f));
                }
                if (OUTH) {
                    *(__half2*)(Ch + (size_t)row * N + col) = __floats2half2_rn(x0, x1);
                } else {
                    *(float2*)(Cf + (size_t)row * N + col) = make_float2(x0, x1);
                }
            }
        }
    }
}

// ================= split-fp16 saliency: tensor cores + fused rowmax =================
// scores[b][i] = max_j (s[i]·base[j]) / sqrt(C), s,b split hi+lo fp16.
// CTA: 128 sampled rows x full K; loop jc over 8 base chunks of 128.
// 2-stage pipeline; stage: Ahi,Alo,Bhi,Blo (10240B each).
#define S_ST_B  40960
#define S_SMEM  (2 * S_ST_B)  // 81920

__global__ __launch_bounds__(256)
void saliency_mma(const __half* __restrict__ shi, const __half* __restrict__ slo,
                  const __half* __restrict__ bhi, const __half* __restrict__ blo,
                  float* __restrict__ scores)
{
    extern __shared__ char dsm[];
    uint32_t su = smem_u32(dsm);
    int tid = threadIdx.x, warp = tid >> 5, lane = tid & 31;
    int b = blockIdx.y;
    int r0 = blockIdx.x * 128;
    int wm = (warp >> 1) * 32, wn = (warp & 1) * 64;

    const __half* Ahi = shi + ((size_t)b * NS + r0) * CDIM;
    const __half* Alo = slo + ((size_t)b * NS + r0) * CDIM;
    const __half* Bhi0 = bhi + (size_t)b * NB * CDIM;
    const __half* Blo0 = blo + (size_t)b * NB * CDIM;

    int row0 = tid >> 2, seg0 = (tid & 3);
    int row1 = (tid + 256) >> 2, seg1 = ((tid + 256) & 3);

    int a_row = lane & 15, a_kh = (lane >> 4) * 8;
    int b_row = lane & 7,  b_kh = ((lane >> 3) & 1) * 8;

    float rm[2][2];
    rm[0][0] = rm[0][1] = rm[1][0] = rm[1][1] = -3.4e38f;

    const int nch = CDIM / KCH; // 24

    for (int jc = 0; jc < 8; jc++) {
        const __half* Bh = Bhi0 + (size_t)jc * 128 * CDIM;
        const __half* Bl = Blo0 + (size_t)jc * 128 * CDIM;

        // prefetch chunk 0 into stage 0
        {
            uint32_t sb = su;
            cp16(sb + row0 * ROWB + seg0 * 16, Ahi + (size_t)row0 * CDIM + seg0 * 8);
            cp16(sb + row1 * ROWB + seg1 * 16, Ahi + (size_t)row1 * CDIM + seg1 * 8);
            cp16(sb + 10240 + row0 * ROWB + seg0 * 16, Alo + (size_t)row0 * CDIM + seg0 * 8);
            cp16(sb + 10240 + row1 * ROWB + seg1 * 16, Alo + (size_t)row1 * CDIM + seg1 * 8);
            cp16(sb + 20480 + row0 * ROWB + seg0 * 16, Bh + (size_t)row0 * CDIM + seg0 * 8);
            cp16(sb + 20480 + row1 * ROWB + seg1 * 16, Bh + (size_t)row1 * CDIM + seg1 * 8);
            cp16(sb + 30720 + row0 * ROWB + seg0 * 16, Bl + (size_t)row0 * CDIM + seg0 * 8);
            cp16(sb + 30720 + row1 * ROWB + seg1 * 16, Bl + (size_t)row1 * CDIM + seg1 * 8);
            CP_COMMIT();
        }

        float acc[2][8][4];
#pragma unroll
        for (int i = 0; i < 2; i++)
#pragma unroll
            for (int j = 0; j < 8; j++)
#pragma unroll
                for (int t = 0; t < 4; t++) acc[i][j][t] = 0.f;

        for (int c = 0; c < nch; c++) {
            CP_WAIT(0);
            __syncthreads();
            if (c + 1 < nch) {
                uint32_t sb = su + ((c + 1) & 1) * S_ST_B;
                int ko = (c + 1) * KCH;
                cp16(sb + row0 * ROWB + seg0 * 16, Ahi + (size_t)row0 * CDIM + ko + seg0 * 8);
                cp16(sb + row1 * ROWB + seg1 * 16, Ahi + (size_t)row1 * CDIM + ko + seg1 * 8);
                cp16(sb + 10240 + row0 * ROWB + seg0 * 16, Alo + (size_t)row0 * CDIM + ko + seg0 * 8);
                cp16(sb + 10240 + row1 * ROWB + seg1 * 16, Alo + (size_t)row1 * CDIM + ko + seg1 * 8);
                cp16(sb + 20480 + row0 * ROWB + seg0 * 16, Bh + (size_t)row0 * CDIM + ko + seg0 * 8);
                cp16(sb + 20480 + row1 * ROWB + seg1 * 16, Bh + (size_t)row1 * CDIM + ko + seg1 * 8);
                cp16(sb + 30720 + row0 * ROWB + seg0 * 16, Bl + (size_t)row0 * CDIM + ko + seg0 * 8);
                cp16(sb + 30720 + row1 * ROWB + seg1 * 16, Bl + (size_t)row1 * CDIM + ko + seg1 * 8);
            }
            CP_COMMIT();
            uint32_t sb = su + (c & 1) * S_ST_B;
#pragma unroll
            for (int ks = 0; ks < 2; ks++) {
                int kk = ks * 16;
                uint32_t ah[2][4], al[2][4];
#pragma unroll
                for (int mt = 0; mt < 2; mt++) {
                    ldmA(sb + (wm + mt * 16 + a_row) * ROWB + (kk + a_kh) * 2, ah[mt]);
                    ldmA(sb + 10240 + (wm + mt * 16 + a_row) * ROWB + (kk + a_kh) * 2, al[mt]);
                }
#pragma unroll
                for (int nt = 0; nt < 8; nt++) {
                    uint32_t bh2[2], bl2[2];
                    ldmB(sb + 20480 + (wn + nt * 8 + b_row) * ROWB + (kk + b_kh) * 2, bh2);
                    ldmB(sb + 30720 + (wn + nt * 8 + b_row) * ROWB + (kk + b_kh) * 2, bl2);
#pragma unroll
                    for (int mt = 0; mt < 2; mt++) {
                        hmma(acc[mt][nt], ah[mt], bh2);
                        hmma(acc[mt][nt], ah[mt], bl2);
                        hmma(acc[mt][nt], al[mt], bh2);
                    }
                }
            }
        }
        // fold this base chunk into running rowmax
#pragma unroll
        for (int mt = 0; mt < 2; mt++)
#pragma unroll
            for (int hf = 0; hf < 2; hf++) {
                float m = rm[mt][hf];
#pragma unroll
                for (int nt = 0; nt < 8; nt++)
                    m = fmaxf(m, fmaxf(acc[mt][nt][hf * 2], acc[mt][nt][hf * 2 + 1]));
                rm[mt][hf] = m;
            }
        __syncthreads(); // all reads of stage smem done before next jc prefetch
    }

    // reduce: quad lanes share a row
    float* red = (float*)dsm;  // [128][2]
    int g = lane >> 2;
#pragma unroll
    for (int mt = 0; mt < 2; mt++)
#pragma unroll
        for (int hf = 0; hf < 2; hf++) {
            float m = rm[mt][hf];
            m = fmaxf(m, __shfl_xor_sync(0xffffffffu, m, 1));
            m = fmaxf(m, __shfl_xor_sync(0xffffffffu, m, 2));
            if ((lane & 3) == 0) {
                int row = wm + mt * 16 + g + hf * 8;
                red[row * 2 + (warp & 1)] = m;
            }
        }
    __syncthreads();
    if (tid < 128)
        scores[(size_t)b * NS + r0 + tid] =
            fmaxf(red[tid * 2], red[tid * 2 + 1]) * 0.03608439182435161f;
}

// ================= converts / transposes =================
__global__ __launch_bounds__(256)
void cvt_h_kernel(const float* __restrict__ in, __half* __restrict__ out, int n4)
{
    int i = blockIdx.x * 256 + threadIdx.x;
    if (i < n4) {
        float4 v = ((const float4*)in)[i];
        ((__half2*)out)[2 * i]     = __floats2half2_rn(v.x, v.y);
        ((__half2*)out)[2 * i + 1] = __floats2half2_rn(v.z, v.w);
    }
}

__global__ __launch_bounds__(256)
void cvt_split_kernel(const float* __restrict__ in, __half* __restrict__ hi,
                      __half* __restrict__ lo, int n4)
{
    int i = blockIdx.x * 256 + threadIdx.x;
    if (i < n4) {
        float4 v = ((const float4*)in)[i];
        float h0 = __half2float(__float2half_rn(v.x));
        float h1 = __half2float(__float2half_rn(v.y));
        float h2 = __half2float(__float2half_rn(v.z));
        float h3 = __half2float(__float2half_rn(v.w));
        ((__half2*)hi)[2 * i]     = __floats2half2_rn(v.x, v.y);
        ((__half2*)hi)[2 * i + 1] = __floats2half2_rn(v.z, v.w);
        ((__half2*)lo)[2 * i]     = __floats2half2_rn(v.x - h0, v.y - h1);
        ((__half2*)lo)[2 * i + 1] = __floats2half2_rn(v.z - h2, v.w - h3);
    }
}

// W [K,N] fp32 -> WT [N,K] fp16
__global__ __launch_bounds__(256)
void transpose_h_kernel(const float* __restrict__ in, __half* __restrict__ out, int K, int N)
{
    __shared__ float t[32][33];
    int k0 = blockIdx.y * 32, n0 = blockIdx.x * 32;
    int tx = threadIdx.x & 31, ty = threadIdx.x >> 5;
#pragma unroll
    for (int i = 0; i < 4; i++)
        t[ty + i * 8][tx] = in[(size_t)(k0 + ty + i * 8) * N + n0 + tx];
    __syncthreads();
#pragma unroll
    for (int i = 0; i < 4; i++)
        out[(size_t)(n0 + ty + i * 8) * K + k0 + tx] = __float2half(t[tx][ty + i * 8]);
}

// ================= top-k =================
__global__ __launch_bounds__(1024)
void topk_kernel(const float* __restrict__ scores, float* __restrict__ topk_out)
{
    __shared__ unsigned long long keys[NS];
    int b = blockIdx.x, tid = threadIdx.x;
    for (int t = tid; t < NS; t += 1024) {
        unsigned int x = __float_as_uint(scores[(size_t)b * NS + t]);
        unsigned int u = (x & 0x80000000u) ? ~x : (x | 0x80000000u);
        keys[t] = (((unsigned long long)(~u)) << 32) | (unsigned int)t;
    }
    __syncthreads();
    for (int k = 2; k <= NS; k <<= 1) {
        for (int j = k >> 1; j > 0; j >>= 1) {
            for (int t = tid; t < NS; t += 1024) {
                int ixj = t ^ j;
                if (ixj > t) {
                    bool up = ((t & k) == 0);
                    unsigned long long a = keys[t], c = keys[ixj];
                    if ((a > c) == up) { keys[t] = c; keys[ixj] = a; }
                }
            }
            __syncthreads();
        }
    }
    if (tid < TOPK) {
        int idx = (int)(unsigned int)(keys[tid] & 0xFFFFFFFFull);
        g_topk[b * TOPK + tid] = idx;
        topk_out[b * TOPK + tid] = (float)idx;
    }
}

// ================= gather =================
__global__ __launch_bounds__(192)
void gather_kernel(const float* __restrict__ sampled, float* __restrict__ sel_out)
{
    int b = blockIdx.y, kk = blockIdx.x;
    int idx = g_topk[b * TOPK + kk];
    const float4* src = (const float4*)(sampled + ((size_t)b * NS + idx) * CDIM);
    float4 v = src[threadIdx.x];
    ((float4*)(g_sel   + ((size_t)b * TOPK + kk) * CDIM))[threadIdx.x] = v;
    ((float4*)(sel_out + ((size_t)b * TOPK + kk) * CDIM))[threadIdx.x] = v;
}

// ================= attention =================
__global__ __launch_bounds__(256)
void attn_kernel(float* __restrict__ attn_out)
{
    int qt = blockIdx.x, h = blockIdx.y, b = blockIdx.z;
    int tid = threadIdx.x;
    __shared__ float Qts[64][36];
    __shared__ float KV[64][68];
    __shared__ float Ls[32][128];
    int qr0 = qt * 32;
#pragma unroll
    for (int i = 0; i < 2; i++) {
        int id = tid + i * 256;
        int row = id >> 4, c4 = (id & 15) * 4;
        float4 v = *(const float4*)(g_q + ((size_t)(b * NB + qr0 + row)) * CDIM + h * DH + c4);
        Qts[c4][row] = v.x; Qts[c4+1][row] = v.y; Qts[c4+2][row] = v.z; Qts[c4+3][row] = v.w;
    }
    int ty = tid >> 4, tx = tid & 15;
#pragma unroll
    for (int ch = 0; ch < 2; ch++) {
        __syncthreads();
#pragma unroll
        for (int i = 0; i < 4; i++) {
            int id = tid + i * 256;
            int row = id >> 4, c4 = (id & 15) * 4;
            float4 v = *(const float4*)(g_k + ((size_t)(b * TOPK + ch * 64 + row)) * CDIM + h * DH + c4);
            KV[c4][row] = v.x; KV[c4+1][row] = v.y; KV[c4+2][row] = v.z; KV[c4+3][row] = v.w;
        }
        __syncthreads();
        int r = ty * 2, c = tx * 4;
        float acc[2][4] = {};
#pragma unroll
        for (int d = 0; d < 64; d++) {
            float a0 = Qts[d][r], a1 = Qts[d][r + 1];
            float4 kb = *(float4*)&KV[d][c];
            acc[0][0] += a0*kb.x; acc[0][1] += a0*kb.y; acc[0][2] += a0*kb.z; acc[0][3] += a0*kb.w;
            acc[1][0] += a1*kb.x; acc[1][1] += a1*kb.y; acc[1][2] += a1*kb.z; acc[1][3] += a1*kb.w;
        }
#pragma unroll
        for (int ii = 0; ii < 2; ii++)
#pragma unroll
            for (int jj = 0; jj < 4; jj++)
                Ls[r + ii][ch * 64 + c + jj] = acc[ii][jj] * 0.125f;
    }
    __syncthreads();
    int warp = tid >> 5, lane = tid & 31;
    for (int r = warp; r < 32; r += 8) {
        float v0 = Ls[r][lane], v1 = Ls[r][lane + 32], v2 = Ls[r][lane + 64], v3 = Ls[r][lane + 96];
        float m = fmaxf(fmaxf(v0, v1), fmaxf(v2, v3));
#pragma unroll
        for (int o = 16; o; o >>= 1) m = fmaxf(m, __shfl_xor_sync(0xffffffffu, m, o));
        float e0 = expf(v0 - m), e1 = expf(v1 - m), e2 = expf(v2 - m), e3 = expf(v3 - m);
        float s = e0 + e1 + e2 + e3;
#pragma unroll
        for (int o = 16; o; o >>= 1) s += __shfl_xor_sync(0xffffffffu, s, o);
        float inv = 1.0f / s;
        e0 *= inv; e1 *= inv; e2 *= inv; e3 *= inv;
        Ls[r][lane] = e0; Ls[r][lane + 32] = e1; Ls[r][lane + 64] = e2; Ls[r][lane + 96] = e3;
        size_t o = (((size_t)(b * HEADS + h)) * NB + qr0 + r) * TOPK;
        attn_out[o + lane] = e0; attn_out[o + lane + 32] = e1;
        attn_out[o + lane + 64] = e2; attn_out[o + lane + 96] = e3;
    }
    int r = ty * 2, dc = tx * 4;
    float acc2[2][4] = {};
#pragma unroll
    for (int ch = 0; ch < 2; ch++) {
        __syncthreads();
#pragma unroll
        for (int i = 0; i < 4; i++) {
            int id = tid + i * 256;
            int row = id >> 4, c4 = (id & 15) * 4;
            *(float4*)&KV[row][c4] =
                *(const float4*)(g_v + ((size_t)(b * TOPK + ch * 64 + row)) * CDIM + h * DH + c4);
        }
        __syncthreads();
#pragma unroll
        for (int kv = 0; kv < 64; kv++) {
            float p0 = Ls[r][ch * 64 + kv], p1 = Ls[r + 1][ch * 64 + kv];
            float4 vv = *(float4*)&KV[kv][dc];
            acc2[0][0] += p0*vv.x; acc2[0][1] += p0*vv.y; acc2[0][2] += p0*vv.z; acc2[0][3] += p0*vv.w;
            acc2[1][0] += p1*vv.x; acc2[1][1] += p1*vv.y; acc2[1][2] += p1*vv.z; acc2[1][3] += p1*vv.w;
        }
    }
#pragma unroll
    for (int ii = 0; ii < 2; ii++) {
        float4 o = make_float4(acc2[ii][0], acc2[ii][1], acc2[ii][2], acc2[ii][3]);
        *(float4*)(g_ctx + ((size_t)(b * NB + qr0 + r + ii)) * CDIM + h * DH + dc) = o;
    }
}

// ================= layernorm =================
__global__ __launch_bounds__(256)
void ln_kernel(const float* __restrict__ Xa, const float* __restrict__ Xb,
               const float* __restrict__ gam, const float* __restrict__ bet,
               float* __restrict__ outp)
{
    int row = blockIdx.x, tid = threadIdx.x;
    __shared__ float xb[CDIM];
    __shared__ float rs[16], rs2[16], stats[2];
    float s = 0.f, ss = 0.f;
    for (int c = tid; c < CDIM; c += 256) {
        float x = Xa[(size_t)row * CDIM + c] + Xb[(size_t)row * CDIM + c];
        xb[c] = x; s += x; ss += x * x;
    }
#pragma unroll
    for (int o = 16; o; o >>= 1) {
        s  += __shfl_xor_sync(0xffffffffu, s,  o);
        ss += __shfl_xor_sync(0xffffffffu, ss, o);
    }
    if ((tid & 31) == 0) { rs[tid >> 5] = s; rs2[tid >> 5] = ss; }
    __syncthreads();
    if (tid == 0) {
        float S = 0.f, SS = 0.f;
        for (int i = 0; i < 8; i++) { S += rs[i]; SS += rs2[i]; }
        float mu = S / CDIM;
        float var = SS / CDIM - mu * mu;
        stats[0] = mu; stats[1] = rsqrtf(var + 1e-5f);
    }
    __syncthreads();
    float mu = stats[0], rstd = stats[1];
    for (int c = tid; c < CDIM; c += 256)
        outp[(size_t)row * CDIM + c] = (xb[c] - mu) * rstd * gam[c] + bet[c];
}

// ================= launch =================
extern "C" void kernel_launch(void* const* d_in, const int* in_sizes, int n_in,
                              void* d_out, int out_size)
{
    const float* base    = (const float*)d_in[0];
    const float* sampled = (const float*)d_in[1];
    const float* Wq = (const float*)d_in[2];  const float* bq = (const float*)d_in[3];
    const float* Wk = (const float*)d_in[4];  const float* bk = (const float*)d_in[5];
    const float* Wv = (const float*)d_in[6];  const float* bv = (const float*)d_in[7];
    const float* Wo = (const float*)d_in[8];  const float* bo = (const float*)d_in[9];
    const float* g1 = (const float*)d_in[10]; const float* b1 = (const float*)d_in[11];
    const float* g2 = (const float*)d_in[12]; const float* b2 = (const float*)d_in[13];
    const float* Wm1 = (const float*)d_in[14]; const float* bm1 = (const float*)d_in[15];
    const float* Wm2 = (const float*)d_in[16]; const float* bm2 = (const float*)d_in[17];

    float* out = (float*)d_out;
    float* out_x      = out;
    float* out_scores = out + (size_t)BATCH * NB * CDIM;
    float* out_attn   = out_scores + (size_t)BATCH * NS;
    float* out_topk   = out_attn + (size_t)BATCH * HEADS * NB * TOPK;
    float* out_sel    = out_topk + (size_t)BATCH * TOPK;

    float *p_q, *p_k, *p_v, *p_ctx, *p_x1, *p_sel;
    __half *p_act, *p_selh, *p_h, *p_WqT, *p_WkT, *p_WvT, *p_WoT, *p_Wm1T, *p_Wm2T;
    __half *p_shi, *p_slo, *p_bhi, *p_blo;
    cudaGetSymbolAddress((void**)&p_q,    g_q);
    cudaGetSymbolAddress((void**)&p_k,    g_k);
    cudaGetSymbolAddress((void**)&p_v,    g_v);
    cudaGetSymbolAddress((void**)&p_ctx,  g_ctx);
    cudaGetSymbolAddress((void**)&p_x1,   g_x1);
    cudaGetSymbolAddress((void**)&p_sel,  g_sel);
    cudaGetSymbolAddress((void**)&p_act,  g_act_h);
    cudaGetSymbolAddress((void**)&p_selh, g_sel_h);
    cudaGetSymbolAddress((void**)&p_h,    g_h_h);
    cudaGetSymbolAddress((void**)&p_WqT,  g_WqT);
    cudaGetSymbolAddress((void**)&p_WkT,  g_WkT);
    cudaGetSymbolAddress((void**)&p_WvT,  g_WvT);
    cudaGetSymbolAddress((void**)&p_WoT,  g_WoT);
    cudaGetSymbolAddress((void**)&p_Wm1T, g_Wm1T);
    cudaGetSymbolAddress((void**)&p_Wm2T, g_Wm2T);
    cudaGetSymbolAddress((void**)&p_shi,  g_s_hi);
    cudaGetSymbolAddress((void**)&p_slo,  g_s_lo);
    cudaGetSymbolAddress((void**)&p_bhi,  g_b_hi);
    cudaGetSymbolAddress((void**)&p_blo,  g_b_lo);

    // opt-in dynamic smem (host-side attribute; idempotent)
    cudaFuncSetAttribute(gemm_mma<0,0>, cudaFuncAttributeMaxDynamicSharedMemorySize, G_SMEM);
    cudaFuncSetAttribute(gemm_mma<1,1>, cudaFuncAttributeMaxDynamicSharedMemorySize, G_SMEM);
    cudaFuncSetAttribute(saliency_mma,  cudaFuncAttributeMaxDynamicSharedMemorySize, S_SMEM);

    const int M  = BATCH * NB;    // 16384
    const int Ms = BATCH * TOPK;  // 2048

    // weight transposes (fp16, [N,K])
    transpose_h_kernel<<<dim3(CDIM/32, CDIM/32), 256>>>(Wq,  p_WqT,  CDIM, CDIM);
    transpose_h_kernel<<<dim3(CDIM/32, CDIM/32), 256>>>(Wk,  p_WkT,  CDIM, CDIM);
    transpose_h_kernel<<<dim3(CDIM/32, CDIM/32), 256>>>(Wv,  p_WvT,  CDIM, CDIM);
    transpose_h_kernel<<<dim3(CDIM/32, CDIM/32), 256>>>(Wo,  p_WoT,  CDIM, CDIM);
    transpose_h_kernel<<<dim3(C4/32,   CDIM/32), 256>>>(Wm1, p_Wm1T, CDIM, C4);
    transpose_h_kernel<<<dim3(CDIM/32, C4/32),   256>>>(Wm2, p_Wm2T, C4, CDIM);

    // 1) split converts + saliency (tensor cores, fp32-accurate) + top-k + gather
    cvt_split_kernel<<<(BATCH * NS * CDIM / 4 + 255) / 256, 256>>>(sampled, p_shi, p_slo, BATCH * NS * CDIM / 4);
    cvt_split_kernel<<<(BATCH * NB * CDIM / 4 + 255) / 256, 256>>>(base, p_bhi, p_blo, BATCH * NB * CDIM / 4);
    saliency_mma<<<dim3(NS/128, BATCH), 256, S_SMEM>>>(p_shi, p_slo, p_bhi, p_blo, out_scores);
    topk_kernel<<<BATCH, 1024>>>(out_scores, out_topk);
    gather_kernel<<<dim3(TOPK, BATCH), 192>>>(sampled, out_sel);

    // 2) converts
    cvt_h_kernel<<<(M * CDIM / 4 + 255) / 256, 256>>>(base, p_act, M * CDIM / 4);
    cvt_h_kernel<<<(Ms * CDIM / 4 + 255) / 256, 256>>>(p_sel, p_selh, Ms * CDIM / 4);

    // 3) Q/K/V projections
    gemm_mma<0,0><<<dim3(CDIM/128, M/128),  256, G_SMEM>>>(p_act,  p_WqT, bq, p_q, nullptr, M,  CDIM, CDIM);
    gemm_mma<0,0><<<dim3(CDIM/128, Ms/128), 256, G_SMEM>>>(p_selh, p_WkT, bk, p_k, nullptr, Ms, CDIM, CDIM);
    gemm_mma<0,0><<<dim3(CDIM/128, Ms/128), 256, G_SMEM>>>(p_selh, p_WvT, bv, p_v, nullptr, Ms, CDIM, CDIM);

    // 4) attention
    attn_kernel<<<dim3(NB / 32, HEADS, BATCH), 256>>>(out_attn);

    // 5) O-projection
    cvt_h_kernel<<<(M * CDIM / 4 + 255) / 256, 256>>>(p_ctx, p_act, M * CDIM / 4);
    gemm_mma<0,0><<<dim3(CDIM/128, M/128), 256, G_SMEM>>>(p_act, p_WoT, bo, p_q, nullptr, M, CDIM, CDIM);

    // 6) LN1 + MLP + LN2
    ln_kernel<<<M, 256>>>(base, p_q, g1, b1, p_x1);
    cvt_h_kernel<<<(M * CDIM / 4 + 255) / 256, 256>>>(p_x1, p_act, M * CDIM / 4);
    gemm_mma<1,1><<<dim3(C4/128, M/128), 256, G_SMEM>>>(p_act, p_Wm1T, bm1, nullptr, p_h, M, C4, CDIM);
    gemm_mma<0,0><<<dim3(CDIM/128, M/128), 256, G_SMEM>>>(p_h, p_Wm2T, bm2, p_ctx, nullptr, M, CDIM, C4);
    ln_kernel<<<M, 256>>>(p_x1, p_ctx, g2, b2, out_x);
}

// round 9
// speedup vs baseline: 4.3540x; 1.0381x over previous
#include <cuda_runtime.h>
#include <cuda_fp16.h>
#include <math.h>
#include <stdint.h>

#define BATCH 16
#define NB    1024
#define NS    4096
#define CDIM  768
#define HEADS 12
#define DH    64
#define TOPK  128
#define C4    3072

// ---------------- device scratch ----------------
__device__ float g_q  [BATCH * (size_t)NB * CDIM];
__device__ float g_k  [BATCH * (size_t)TOPK * CDIM];
__device__ float g_v  [BATCH * (size_t)TOPK * CDIM];
__device__ float g_ctx[BATCH * (size_t)NB * CDIM];
__device__ float g_x1 [BATCH * (size_t)NB * CDIM];
__device__ float g_sel[BATCH * (size_t)TOPK * CDIM];
__device__ int   g_topk[BATCH * TOPK];
// fp16 scratch
__device__ __half g_act_h [BATCH * (size_t)NB * CDIM];   // attn-ctx / ln1-out (sequential reuse)
__device__ __half g_sel_h [BATCH * (size_t)TOPK * CDIM];
__device__ __half g_h_h   [BATCH * (size_t)NB * C4];
__device__ __half g_WqT[CDIM * CDIM];
__device__ __half g_WkT[CDIM * CDIM];
__device__ __half g_WvT[CDIM * CDIM];
__device__ __half g_WoT[CDIM * CDIM];
__device__ __half g_Wm1T[(size_t)C4 * CDIM];
__device__ __half g_Wm2T[(size_t)CDIM * C4];
// split-fp16 saliency operands (b_hi doubles as fp16(base) for Q-proj)
__device__ __half g_s_hi[BATCH * (size_t)NS * CDIM];
__device__ __half g_s_lo[BATCH * (size_t)NS * CDIM];
__device__ __half g_b_hi[BATCH * (size_t)NB * CDIM];
__device__ __half g_b_lo[BATCH * (size_t)NB * CDIM];

// ================= helpers =================
__device__ __forceinline__ uint32_t smem_u32(const void* p) {
    uint32_t a;
    asm("{ .reg .u64 t; cvta.to.shared.u64 t, %1; cvt.u32.u64 %0, t; }" : "=r"(a) : "l"(p));
    return a;
}
__device__ __forceinline__ void cp16(uint32_t dst, const void* src) {
    asm volatile("cp.async.cg.shared.global [%0], [%1], 16;" :: "r"(dst), "l"(src));
}
#define CP_COMMIT() asm volatile("cp.async.commit_group;" ::: "memory")
#define CP_WAIT(n)  asm volatile("cp.async.wait_group %0;" :: "n"(n) : "memory")

#define KCH 32
#define ROWB 80   // 40-half row stride: conflict-free ldmatrix

__device__ __forceinline__ void ldmA(uint32_t addr, uint32_t* f) {
    asm volatile("ldmatrix.sync.aligned.m8n8.x4.shared.b16 {%0,%1,%2,%3}, [%4];"
        : "=r"(f[0]), "=r"(f[1]), "=r"(f[2]), "=r"(f[3]) : "r"(addr));
}
__device__ __forceinline__ void ldmB4(uint32_t addr, uint32_t* f) {
    asm volatile("ldmatrix.sync.aligned.m8n8.x4.shared.b16 {%0,%1,%2,%3}, [%4];"
        : "=r"(f[0]), "=r"(f[1]), "=r"(f[2]), "=r"(f[3]) : "r"(addr));
}
__device__ __forceinline__ void hmma(float* d, const uint32_t* a, const uint32_t* b) {
    asm volatile(
        "mma.sync.aligned.m16n8k16.row.col.f32.f16.f16.f32 "
        "{%0,%1,%2,%3}, {%4,%5,%6,%7}, {%8,%9}, {%0,%1,%2,%3};"
        : "+f"(d[0]), "+f"(d[1]), "+f"(d[2]), "+f"(d[3])
        : "r"(a[0]), "r"(a[1]), "r"(a[2]), "r"(a[3]), "r"(b[0]), "r"(b[1]));
}

// ================= projection/MLP GEMM: cp.async 4-stage =================
#define G_ST_B  20480
#define G_SMEM  (4 * G_ST_B)  // 81920

template <int ACT, int OUTH>
__global__ __launch_bounds__(256)
void gemm_mma(const __half* __restrict__ A, const __half* __restrict__ Bt,
              const float* __restrict__ bias, float* __restrict__ Cf,
              __half* __restrict__ Ch, int M, int N, int K)
{
    extern __shared__ char dsm[];
    uint32_t su = smem_u32(dsm);
    int tid = threadIdx.x, warp = tid >> 5, lane = tid & 31;
    int m0 = blockIdx.y * 128, n0 = blockIdx.x * 128;
    int wm = (warp >> 1) * 32, wn = (warp & 1) * 64;

    const __half* Ab = A  + (size_t)m0 * K;
    const __half* Bb = Bt + (size_t)n0 * K;

    int row0 = tid >> 2, seg0 = (tid & 3);
    int row1 = (tid + 256) >> 2, seg1 = ((tid + 256) & 3);

    int nch = K / KCH;
#pragma unroll
    for (int s = 0; s < 3; s++) {
        uint32_t sb = su + s * G_ST_B;
        const __half* As = Ab + (size_t)s * KCH;
        const __half* Bs = Bb + (size_t)s * KCH;
        cp16(sb + row0 * ROWB + seg0 * 16, As + (size_t)row0 * K + seg0 * 8);
        cp16(sb + row1 * ROWB + seg1 * 16, As + (size_t)row1 * K + seg1 * 8);
        cp16(sb + 10240 + row0 * ROWB + seg0 * 16, Bs + (size_t)row0 * K + seg0 * 8);
        cp16(sb + 10240 + row1 * ROWB + seg1 * 16, Bs + (size_t)row1 * K + seg1 * 8);
        CP_COMMIT();
    }

    float acc[2][8][4];
#pragma unroll
    for (int i = 0; i < 2; i++)
#pragma unroll
        for (int j = 0; j < 8; j++)
#pragma unroll
            for (int t = 0; t < 4; t++) acc[i][j][t] = 0.f;

    int a_row = lane & 15, a_kh = (lane >> 4) * 8;
    // ldmatrix x4 B-pair addressing: lane groups -> (tile, k-half)
    int bp_row = ((lane >> 4) & 1) * 8 + (lane & 7);
    int bp_kh  = ((lane >> 3) & 1) * 8;

    for (int c = 0; c < nch; c++) {
        CP_WAIT(2);
        __syncthreads();
        if (c + 3 < nch) {
            uint32_t sb = su + ((c + 3) & 3) * G_ST_B;
            const __half* As = Ab + (size_t)(c + 3) * KCH;
            const __half* Bs = Bb + (size_t)(c + 3) * KCH;
            cp16(sb + row0 * ROWB + seg0 * 16, As + (size_t)row0 * K + seg0 * 8);
            cp16(sb + row1 * ROWB + seg1 * 16, As + (size_t)row1 * K + seg1 * 8);
            cp16(sb + 10240 + row0 * ROWB + seg0 * 16, Bs + (size_t)row0 * K + seg0 * 8);
            cp16(sb + 10240 + row1 * ROWB + seg1 * 16, Bs + (size_t)row1 * K + seg1 * 8);
        }
        CP_COMMIT();
        uint32_t sb = su + (c & 3) * G_ST_B;
#pragma unroll
        for (int ks = 0; ks < 2; ks++) {
            int kk = ks * 16;
            uint32_t afr[2][4];
#pragma unroll
            for (int mt = 0; mt < 2; mt++)
                ldmA(sb + (wm + mt * 16 + a_row) * ROWB + (kk + a_kh) * 2, afr[mt]);
#pragma unroll
            for (int p = 0; p < 4; p++) {
                uint32_t bfr[4];
                ldmB4(sb + 10240 + (wn + p * 16 + bp_row) * ROWB + (kk + bp_kh) * 2, bfr);
                hmma(acc[0][2 * p],     afr[0], bfr);
                hmma(acc[1][2 * p],     afr[1], bfr);
                hmma(acc[0][2 * p + 1], afr[0], bfr + 2);
                hmma(acc[1][2 * p + 1], afr[1], bfr + 2);
            }
        }
    }

    int g = lane >> 2, t4 = (lane & 3) * 2;
#pragma unroll
    for (int mt = 0; mt < 2; mt++) {
#pragma unroll
        for (int nt = 0; nt < 8; nt++) {
            int col = n0 + wn + nt * 8 + t4;
            float b0 = bias[col], b1 = bias[col + 1];
#pragma unroll
            for (int hf = 0; hf < 2; hf++) {
                int row = m0 + wm + mt * 16 + g + hf * 8;
                float x0 = acc[mt][nt][hf * 2 + 0] + b0;
                float x1 = acc[mt][nt][hf * 2 + 1] + b1;
                if (ACT == 1) {
                    x0 = 0.5f * x0 * (1.0f + erff(x0 * 0.70710678118654752f));
                    x1 = 0.5f * x1 * (1.0f + erff(x1 * 0.70710678118654752f));
                }
                if (OUTH) {
                    *(__half2*)(Ch + (size_t)row * N + col) = __floats2half2_rn(x0, x1);
                } else {
                    *(float2*)(Cf + (size_t)row * N + col) = make_float2(x0, x1);
                }
            }
        }
    }
}

// ================= split-fp16 saliency: 3-stage, flattened loop =================
#define S_ST_B  40960
#define S_SMEM  (3 * S_ST_B)  // 122880

__global__ __launch_bounds__(256)
void saliency_mma(const __half* __restrict__ shi, const __half* __restrict__ slo,
                  const __half* __restrict__ bhi, const __half* __restrict__ blo,
                  float* __restrict__ scores)
{
    extern __shared__ char dsm[];
    uint32_t su = smem_u32(dsm);
    int tid = threadIdx.x, warp = tid >> 5, lane = tid & 31;
    int b = blockIdx.y;
    int r0 = blockIdx.x * 128;
    int wm = (warp >> 1) * 32, wn = (warp & 1) * 64;

    const __half* Ahi = shi + ((size_t)b * NS + r0) * CDIM;
    const __half* Alo = slo + ((size_t)b * NS + r0) * CDIM;
    const __half* Bhi0 = bhi + (size_t)b * NB * CDIM;
    const __half* Blo0 = blo + (size_t)b * NB * CDIM;

    int row0 = tid >> 2, seg0 = (tid & 3);
    int row1 = (tid + 256) >> 2, seg1 = ((tid + 256) & 3);

    int a_row = lane & 15, a_kh = (lane >> 4) * 8;
    int bp_row = ((lane >> 4) & 1) * 8 + (lane & 7);
    int bp_kh  = ((lane >> 3) & 1) * 8;

    const int NCH = CDIM / KCH;   // 24
    const int NIT = 8 * NCH;      // 192

    // prefetch iteration `it` into stage it%3
#define S_PREF(it) do { \
        int _jc = (it) / NCH, _c = (it) % NCH; \
        uint32_t sb = su + ((it) % 3) * S_ST_B; \
        int ko = _c * KCH; \
        const __half* Bh = Bhi0 + (size_t)_jc * 128 * CDIM; \
        const __half* Bl = Blo0 + (size_t)_jc * 128 * CDIM; \
        cp16(sb + row0 * ROWB + seg0 * 16, Ahi + (size_t)row0 * CDIM + ko + seg0 * 8); \
        cp16(sb + row1 * ROWB + seg1 * 16, Ahi + (size_t)row1 * CDIM + ko + seg1 * 8); \
        cp16(sb + 10240 + row0 * ROWB + seg0 * 16, Alo + (size_t)row0 * CDIM + ko + seg0 * 8); \
        cp16(sb + 10240 + row1 * ROWB + seg1 * 16, Alo + (size_t)row1 * CDIM + ko + seg1 * 8); \
        cp16(sb + 20480 + row0 * ROWB + seg0 * 16, Bh + (size_t)row0 * CDIM + ko + seg0 * 8); \
        cp16(sb + 20480 + row1 * ROWB + seg1 * 16, Bh + (size_t)row1 * CDIM + ko + seg1 * 8); \
        cp16(sb + 30720 + row0 * ROWB + seg0 * 16, Bl + (size_t)row0 * CDIM + ko + seg0 * 8); \
        cp16(sb + 30720 + row1 * ROWB + seg1 * 16, Bl + (size_t)row1 * CDIM + ko + seg1 * 8); \
    } while (0)

    S_PREF(0); CP_COMMIT();
    S_PREF(1); CP_COMMIT();

    float rm[2][2];
    rm[0][0] = rm[0][1] = rm[1][0] = rm[1][1] = -3.4e38f;
    float acc[2][8][4];

    for (int it = 0; it < NIT; it++) {
        int c = it % NCH;
        if (c == 0) {
#pragma unroll
            for (int i = 0; i < 2; i++)
#pragma unroll
                for (int j = 0; j < 8; j++)
#pragma unroll
                    for (int t = 0; t < 4; t++) acc[i][j][t] = 0.f;
        }
        CP_WAIT(1);
        __syncthreads();
        if (it + 2 < NIT) S_PREF(it + 2);
        CP_COMMIT();
        uint32_t sb = su + (it % 3) * S_ST_B;
#pragma unroll
        for (int ks = 0; ks < 2; ks++) {
            int kk = ks * 16;
            uint32_t ah[2][4], al[2][4];
#pragma unroll
            for (int mt = 0; mt < 2; mt++) {
                ldmA(sb + (wm + mt * 16 + a_row) * ROWB + (kk + a_kh) * 2, ah[mt]);
                ldmA(sb + 10240 + (wm + mt * 16 + a_row) * ROWB + (kk + a_kh) * 2, al[mt]);
            }
#pragma unroll
            for (int p = 0; p < 4; p++) {
                uint32_t bh4[4], bl4[4];
                ldmB4(sb + 20480 + (wn + p * 16 + bp_row) * ROWB + (kk + bp_kh) * 2, bh4);
                ldmB4(sb + 30720 + (wn + p * 16 + bp_row) * ROWB + (kk + bp_kh) * 2, bl4);
#pragma unroll
                for (int t = 0; t < 2; t++) {
                    int nt = 2 * p + t;
#pragma unroll
                    for (int mt = 0; mt < 2; mt++) {
                        hmma(acc[mt][nt], ah[mt], bh4 + 2 * t);
                        hmma(acc[mt][nt], ah[mt], bl4 + 2 * t);
                        hmma(acc[mt][nt], al[mt], bh4 + 2 * t);
                    }
                }
            }
        }
        if (c == NCH - 1) {
#pragma unroll
            for (int mt = 0; mt < 2; mt++)
#pragma unroll
                for (int hf = 0; hf < 2; hf++) {
                    float m = rm[mt][hf];
#pragma unroll
                    for (int nt = 0; nt < 8; nt++)
                        m = fmaxf(m, fmaxf(acc[mt][nt][hf * 2], acc[mt][nt][hf * 2 + 1]));
                    rm[mt][hf] = m;
                }
        }
    }
#undef S_PREF

    __syncthreads();
    float* red = (float*)dsm;  // [128][2]
    int g = lane >> 2;
#pragma unroll
    for (int mt = 0; mt < 2; mt++)
#pragma unroll
        for (int hf = 0; hf < 2; hf++) {
            float m = rm[mt][hf];
            m = fmaxf(m, __shfl_xor_sync(0xffffffffu, m, 1));
            m = fmaxf(m, __shfl_xor_sync(0xffffffffu, m, 2));
            if ((lane & 3) == 0) {
                int row = wm + mt * 16 + g + hf * 8;
                red[row * 2 + (warp & 1)] = m;
            }
        }
    __syncthreads();
    if (tid < 128)
        scores[(size_t)b * NS + r0 + tid] =
            fmaxf(red[tid * 2], red[tid * 2 + 1]) * 0.03608439182435161f;
}

// ================= converts / transposes =================
__global__ __launch_bounds__(256)
void cvt_split_kernel(const float* __restrict__ in, __half* __restrict__ hi,
                      __half* __restrict__ lo, int n4)
{
    int i = blockIdx.x * 256 + threadIdx.x;
    if (i < n4) {
        float4 v = ((const float4*)in)[i];
        float h0 = __half2float(__float2half_rn(v.x));
        float h1 = __half2float(__float2half_rn(v.y));
        float h2 = __half2float(__float2half_rn(v.z));
        float h3 = __half2float(__float2half_rn(v.w));
        ((__half2*)hi)[2 * i]     = __floats2half2_rn(v.x, v.y);
        ((__half2*)hi)[2 * i + 1] = __floats2half2_rn(v.z, v.w);
        ((__half2*)lo)[2 * i]     = __floats2half2_rn(v.x - h0, v.y - h1);
        ((__half2*)lo)[2 * i + 1] = __floats2half2_rn(v.z - h2, v.w - h3);
    }
}

__global__ __launch_bounds__(256)
void transpose_h_kernel(const float* __restrict__ in, __half* __restrict__ out, int K, int N)
{
    __shared__ float t[32][33];
    int k0 = blockIdx.y * 32, n0 = blockIdx.x * 32;
    int tx = threadIdx.x & 31, ty = threadIdx.x >> 5;
#pragma unroll
    for (int i = 0; i < 4; i++)
        t[ty + i * 8][tx] = in[(size_t)(k0 + ty + i * 8) * N + n0 + tx];
    __syncthreads();
#pragma unroll
    for (int i = 0; i < 4; i++)
        out[(size_t)(n0 + ty + i * 8) * K + k0 + tx] = __float2half(t[tx][ty + i * 8]);
}

// ================= top-k =================
__global__ __launch_bounds__(1024)
void topk_kernel(const float* __restrict__ scores, float* __restrict__ topk_out)
{
    __shared__ unsigned long long keys[NS];
    int b = blockIdx.x, tid = threadIdx.x;
    for (int t = tid; t < NS; t += 1024) {
        unsigned int x = __float_as_uint(scores[(size_t)b * NS + t]);
        unsigned int u = (x & 0x80000000u) ? ~x : (x | 0x80000000u);
        keys[t] = (((unsigned long long)(~u)) << 32) | (unsigned int)t;
    }
    __syncthreads();
    for (int k = 2; k <= NS; k <<= 1) {
        for (int j = k >> 1; j > 0; j >>= 1) {
            for (int t = tid; t < NS; t += 1024) {
                int ixj = t ^ j;
                if (ixj > t) {
                    bool up = ((t & k) == 0);
                    unsigned long long a = keys[t], c = keys[ixj];
                    if ((a > c) == up) { keys[t] = c; keys[ixj] = a; }
                }
            }
            __syncthreads();
        }
    }
    if (tid < TOPK) {
        int idx = (int)(unsigned int)(keys[tid] & 0xFFFFFFFFull);
        g_topk[b * TOPK + tid] = idx;
        topk_out[b * TOPK + tid] = (float)idx;
    }
}

// ================= gather (fp32 out + fp16 for K/V proj) =================
__global__ __launch_bounds__(192)
void gather_kernel(const float* __restrict__ sampled, float* __restrict__ sel_out,
                   __half* __restrict__ sel_h)
{
    int b = blockIdx.y, kk = blockIdx.x;
    int idx = g_topk[b * TOPK + kk];
    const float4* src = (const float4*)(sampled + ((size_t)b * NS + idx) * CDIM);
    float4 v = src[threadIdx.x];
    size_t rowoff = ((size_t)b * TOPK + kk) * CDIM;
    ((float4*)(g_sel   + rowoff))[threadIdx.x] = v;
    ((float4*)(sel_out + rowoff))[threadIdx.x] = v;
    __half2* dh = (__half2*)(sel_h + rowoff);
    dh[2 * threadIdx.x]     = __floats2half2_rn(v.x, v.y);
    dh[2 * threadIdx.x + 1] = __floats2half2_rn(v.z, v.w);
}

// ================= attention (fp32 compute, fp16 ctx out) =================
__global__ __launch_bounds__(256)
void attn_kernel(float* __restrict__ attn_out, __half* __restrict__ ctx_h)
{
    int qt = blockIdx.x, h = blockIdx.y, b = blockIdx.z;
    int tid = threadIdx.x;
    __shared__ float Qts[64][36];
    __shared__ float KV[64][68];
    __shared__ float Ls[32][128];
    int qr0 = qt * 32;
#pragma unroll
    for (int i = 0; i < 2; i++) {
        int id = tid + i * 256;
        int row = id >> 4, c4 = (id & 15) * 4;
        float4 v = *(const float4*)(g_q + ((size_t)(b * NB + qr0 + row)) * CDIM + h * DH + c4);
        Qts[c4][row] = v.x; Qts[c4+1][row] = v.y; Qts[c4+2][row] = v.z; Qts[c4+3][row] = v.w;
    }
    int ty = tid >> 4, tx = tid & 15;
#pragma unroll
    for (int ch = 0; ch < 2; ch++) {
        __syncthreads();
#pragma unroll
        for (int i = 0; i < 4; i++) {
            int id = tid + i * 256;
            int row = id >> 4, c4 = (id & 15) * 4;
            float4 v = *(const float4*)(g_k + ((size_t)(b * TOPK + ch * 64 + row)) * CDIM + h * DH + c4);
            KV[c4][row] = v.x; KV[c4+1][row] = v.y; KV[c4+2][row] = v.z; KV[c4+3][row] = v.w;
        }
        __syncthreads();
        int r = ty * 2, c = tx * 4;
        float acc[2][4] = {};
#pragma unroll
        for (int d = 0; d < 64; d++) {
            float a0 = Qts[d][r], a1 = Qts[d][r + 1];
            float4 kb = *(float4*)&KV[d][c];
            acc[0][0] += a0*kb.x; acc[0][1] += a0*kb.y; acc[0][2] += a0*kb.z; acc[0][3] += a0*kb.w;
            acc[1][0] += a1*kb.x; acc[1][1] += a1*kb.y; acc[1][2] += a1*kb.z; acc[1][3] += a1*kb.w;
        }
#pragma unroll
        for (int ii = 0; ii < 2; ii++)
#pragma unroll
            for (int jj = 0; jj < 4; jj++)
                Ls[r + ii][ch * 64 + c + jj] = acc[ii][jj] * 0.125f;
    }
    __syncthreads();
    int warp = tid >> 5, lane = tid & 31;
    for (int r = warp; r < 32; r += 8) {
        float v0 = Ls[r][lane], v1 = Ls[r][lane + 32], v2 = Ls[r][lane + 64], v3 = Ls[r][lane + 96];
        float m = fmaxf(fmaxf(v0, v1), fmaxf(v2, v3));
#pragma unroll
        for (int o = 16; o; o >>= 1) m = fmaxf(m, __shfl_xor_sync(0xffffffffu, m, o));
        float e0 = expf(v0 - m), e1 = expf(v1 - m), e2 = expf(v2 - m), e3 = expf(v3 - m);
        float s = e0 + e1 + e2 + e3;
#pragma unroll
        for (int o = 16; o; o >>= 1) s += __shfl_xor_sync(0xffffffffu, s, o);
        float inv = 1.0f / s;
        e0 *= inv; e1 *= inv; e2 *= inv; e3 *= inv;
        Ls[r][lane] = e0; Ls[r][lane + 32] = e1; Ls[r][lane + 64] = e2; Ls[r][lane + 96] = e3;
        size_t o = (((size_t)(b * HEADS + h)) * NB + qr0 + r) * TOPK;
        attn_out[o + lane] = e0; attn_out[o + lane + 32] = e1;
        attn_out[o + lane + 64] = e2; attn_out[o + lane + 96] = e3;
    }
    int r = ty * 2, dc = tx * 4;
    float acc2[2][4] = {};
#pragma unroll
    for (int ch = 0; ch < 2; ch++) {
        __syncthreads();
#pragma unroll
        for (int i = 0; i < 4; i++) {
            int id = tid + i * 256;
            int row = id >> 4, c4 = (id & 15) * 4;
            *(float4*)&KV[row][c4] =
                *(const float4*)(g_v + ((size_t)(b * TOPK + ch * 64 + row)) * CDIM + h * DH + c4);
        }
        __syncthreads();
#pragma unroll
        for (int kv = 0; kv < 64; kv++) {
            float p0 = Ls[r][ch * 64 + kv], p1 = Ls[r + 1][ch * 64 + kv];
            float4 vv = *(float4*)&KV[kv][dc];
            acc2[0][0] += p0*vv.x; acc2[0][1] += p0*vv.y; acc2[0][2] += p0*vv.z; acc2[0][3] += p0*vv.w;
            acc2[1][0] += p1*vv.x; acc2[1][1] += p1*vv.y; acc2[1][2] += p1*vv.z; acc2[1][3] += p1*vv.w;
        }
    }
#pragma unroll
    for (int ii = 0; ii < 2; ii++) {
        __half2* dh = (__half2*)(ctx_h + ((size_t)(b * NB + qr0 + r + ii)) * CDIM + h * DH + dc);
        dh[0] = __floats2half2_rn(acc2[ii][0], acc2[ii][1]);
        dh[1] = __floats2half2_rn(acc2[ii][2], acc2[ii][3]);
    }
}

// ================= layernorm (fp32 out + optional fp16 out) =================
template <int OUTH>
__global__ __launch_bounds__(256)
void ln_kernel(const float* __restrict__ Xa, const float* __restrict__ Xb,
               const float* __restrict__ gam, const float* __restrict__ bet,
               float* __restrict__ outp, __half* __restrict__ outh)
{
    int row = blockIdx.x, tid = threadIdx.x;
    __shared__ float xb[CDIM];
    __shared__ float rs[16], rs2[16], stats[2];
    float s = 0.f, ss = 0.f;
    for (int c = tid; c < CDIM; c += 256) {
        float x = Xa[(size_t)row * CDIM + c] + Xb[(size_t)row * CDIM + c];
        xb[c] = x; s += x; ss += x * x;
    }
#pragma unroll
    for (int o = 16; o; o >>= 1) {
        s  += __shfl_xor_sync(0xffffffffu, s,  o);
        ss += __shfl_xor_sync(0xffffffffu, ss, o);
    }
    if ((tid & 31) == 0) { rs[tid >> 5] = s; rs2[tid >> 5] = ss; }
    __syncthreads();
    if (tid == 0) {
        float S = 0.f, SS = 0.f;
        for (int i = 0; i < 8; i++) { S += rs[i]; SS += rs2[i]; }
        float mu = S / CDIM;
        float var = SS / CDIM - mu * mu;
        stats[0] = mu; stats[1] = rsqrtf(var + 1e-5f);
    }
    __syncthreads();
    float mu = stats[0], rstd = stats[1];
    for (int c = tid; c < CDIM; c += 256) {
        float y = (xb[c] - mu) * rstd * gam[c] + bet[c];
        outp[(size_t)row * CDIM + c] = y;
        if (OUTH) outh[(size_t)row * CDIM + c] = __float2half(y);
    }
}

// ================= launch =================
extern "C" void kernel_launch(void* const* d_in, const int* in_sizes, int n_in,
                              void* d_out, int out_size)
{
    const float* base    = (const float*)d_in[0];
    const float* sampled = (const float*)d_in[1];
    const float* Wq = (const float*)d_in[2];  const float* bq = (const float*)d_in[3];
    const float* Wk = (const float*)d_in[4];  const float* bk = (const float*)d_in[5];
    const float* Wv = (const float*)d_in[6];  const float* bv = (const float*)d_in[7];
    const float* Wo = (const float*)d_in[8];  const float* bo = (const float*)d_in[9];
    const float* g1 = (const float*)d_in[10]; const float* b1 = (const float*)d_in[11];
    const float* g2 = (const float*)d_in[12]; const float* b2 = (const float*)d_in[13];
    const float* Wm1 = (const float*)d_in[14]; const float* bm1 = (const float*)d_in[15];
    const float* Wm2 = (const float*)d_in[16]; const float* bm2 = (const float*)d_in[17];

    float* out = (float*)d_out;
    float* out_x      = out;
    float* out_scores = out + (size_t)BATCH * NB * CDIM;
    float* out_attn   = out_scores + (size_t)BATCH * NS;
    float* out_topk   = out_attn + (size_t)BATCH * HEADS * NB * TOPK;
    float* out_sel    = out_topk + (size_t)BATCH * TOPK;

    float *p_q, *p_k, *p_v, *p_ctx, *p_x1;
    __half *p_act, *p_selh, *p_h, *p_WqT, *p_WkT, *p_WvT, *p_WoT, *p_Wm1T, *p_Wm2T;
    __half *p_shi, *p_slo, *p_bhi, *p_blo;
    cudaGetSymbolAddress((void**)&p_q,    g_q);
    cudaGetSymbolAddress((void**)&p_k,    g_k);
    cudaGetSymbolAddress((void**)&p_v,    g_v);
    cudaGetSymbolAddress((void**)&p_ctx,  g_ctx);
    cudaGetSymbolAddress((void**)&p_x1,   g_x1);
    cudaGetSymbolAddress((void**)&p_act,  g_act_h);
    cudaGetSymbolAddress((void**)&p_selh, g_sel_h);
    cudaGetSymbolAddress((void**)&p_h,    g_h_h);
    cudaGetSymbolAddress((void**)&p_WqT,  g_WqT);
    cudaGetSymbolAddress((void**)&p_WkT,  g_WkT);
    cudaGetSymbolAddress((void**)&p_WvT,  g_WvT);
    cudaGetSymbolAddress((void**)&p_WoT,  g_WoT);
    cudaGetSymbolAddress((void**)&p_Wm1T, g_Wm1T);
    cudaGetSymbolAddress((void**)&p_Wm2T, g_Wm2T);
    cudaGetSymbolAddress((void**)&p_shi,  g_s_hi);
    cudaGetSymbolAddress((void**)&p_slo,  g_s_lo);
    cudaGetSymbolAddress((void**)&p_bhi,  g_b_hi);
    cudaGetSymbolAddress((void**)&p_blo,  g_b_lo);

    cudaFuncSetAttribute(gemm_mma<0,0>, cudaFuncAttributeMaxDynamicSharedMemorySize, G_SMEM);
    cudaFuncSetAttribute(gemm_mma<1,1>, cudaFuncAttributeMaxDynamicSharedMemorySize, G_SMEM);
    cudaFuncSetAttribute(saliency_mma,  cudaFuncAttributeMaxDynamicSharedMemorySize, S_SMEM);

    const int M  = BATCH * NB;    // 16384
    const int Ms = BATCH * TOPK;  // 2048

    // weight transposes (fp16, [N,K])
    transpose_h_kernel<<<dim3(CDIM/32, CDIM/32), 256>>>(Wq,  p_WqT,  CDIM, CDIM);
    transpose_h_kernel<<<dim3(CDIM/32, CDIM/32), 256>>>(Wk,  p_WkT,  CDIM, CDIM);
    transpose_h_kernel<<<dim3(CDIM/32, CDIM/32), 256>>>(Wv,  p_WvT,  CDIM, CDIM);
    transpose_h_kernel<<<dim3(CDIM/32, CDIM/32), 256>>>(Wo,  p_WoT,  CDIM, CDIM);
    transpose_h_kernel<<<dim3(C4/32,   CDIM/32), 256>>>(Wm1, p_Wm1T, CDIM, C4);
    transpose_h_kernel<<<dim3(CDIM/32, C4/32),   256>>>(Wm2, p_Wm2T, C4, CDIM);

    // 1) split converts + saliency + top-k + gather
    cvt_split_kernel<<<(BATCH * NS * CDIM / 4 + 255) / 256, 256>>>(sampled, p_shi, p_slo, BATCH * NS * CDIM / 4);
    cvt_split_kernel<<<(BATCH * NB * CDIM / 4 + 255) / 256, 256>>>(base, p_bhi, p_blo, BATCH * NB * CDIM / 4);
    saliency_mma<<<dim3(NS/128, BATCH), 256, S_SMEM>>>(p_shi, p_slo, p_bhi, p_blo, out_scores);
    topk_kernel<<<BATCH, 1024>>>(out_scores, out_topk);
    gather_kernel<<<dim3(TOPK, BATCH), 192>>>(sampled, out_sel, p_selh);

    // 2) Q/K/V projections (Q input = b_hi == fp16(base))
    gemm_mma<0,0><<<dim3(CDIM/128, M/128),  256, G_SMEM>>>(p_bhi,  p_WqT, bq, p_q, nullptr, M,  CDIM, CDIM);
    gemm_mma<0,0><<<dim3(CDIM/128, Ms/128), 256, G_SMEM>>>(p_selh, p_WkT, bk, p_k, nullptr, Ms, CDIM, CDIM);
    gemm_mma<0,0><<<dim3(CDIM/128, Ms/128), 256, G_SMEM>>>(p_selh, p_WvT, bv, p_v, nullptr, Ms, CDIM, CDIM);

    // 3) attention (ctx written as fp16 directly)
    attn_kernel<<<dim3(NB / 32, HEADS, BATCH), 256>>>(out_attn, p_act);

    // 4) O-projection
    gemm_mma<0,0><<<dim3(CDIM/128, M/128), 256, G_SMEM>>>(p_act, p_WoT, bo, p_q, nullptr, M, CDIM, CDIM);

    // 5) LN1 (dual out) + MLP + LN2
    ln_kernel<1><<<M, 256>>>(base, p_q, g1, b1, p_x1, p_act);
    gemm_mma<1,1><<<dim3(C4/128, M/128), 256, G_SMEM>>>(p_act, p_Wm1T, bm1, nullptr, p_h, M, C4, CDIM);
    gemm_mma<0,0><<<dim3(CDIM/128, M/128), 256, G_SMEM>>>(p_h, p_Wm2T, bm2, p_ctx, nullptr, M, CDIM, C4);
    ln_kernel<0><<<M, 256>>>(p_x1, p_ctx, g2, b2, out_x, nullptr);
}

// round 11
// speedup vs baseline: 4.9386x; 1.1343x over previous
#include <cuda_runtime.h>
#include <cuda_fp16.h>
#include <math.h>
#include <stdint.h>

#define BATCH 16
#define NB    1024
#define NS    4096
#define CDIM  768
#define HEADS 12
#define DH    64
#define TOPK  128
#define C4    3072

// ---------------- device scratch ----------------
__device__ float g_tmp[BATCH * (size_t)NB * CDIM];   // O-proj out (fp32)
__device__ float g_ctx[BATCH * (size_t)NB * CDIM];   // MLP2 out
__device__ float g_x1 [BATCH * (size_t)NB * CDIM];
__device__ int   g_topk[BATCH * TOPK];
// fp16 scratch
__device__ __half g_q_h [BATCH * (size_t)NB * CDIM];
__device__ __half g_k_h [BATCH * (size_t)TOPK * CDIM];
__device__ __half g_v_h [BATCH * (size_t)TOPK * CDIM];
__device__ __half g_act_h [BATCH * (size_t)NB * CDIM];   // attn-ctx / ln1-out
__device__ __half g_sel_h [BATCH * (size_t)TOPK * CDIM];
__device__ __half g_h_h   [BATCH * (size_t)NB * C4];
__device__ __half g_WqT[CDIM * CDIM];
__device__ __half g_WkT[CDIM * CDIM];
__device__ __half g_WvT[CDIM * CDIM];
__device__ __half g_WoT[CDIM * CDIM];
__device__ __half g_Wm1T[(size_t)C4 * CDIM];
__device__ __half g_Wm2T[(size_t)CDIM * C4];
// split-fp16 saliency operands (b_hi doubles as fp16(base) for Q-proj)
__device__ __half g_s_hi[BATCH * (size_t)NS * CDIM];
__device__ __half g_s_lo[BATCH * (size_t)NS * CDIM];
__device__ __half g_b_hi[BATCH * (size_t)NB * CDIM];
__device__ __half g_b_lo[BATCH * (size_t)NB * CDIM];

// ================= helpers =================
__device__ __forceinline__ uint32_t smem_u32(const void* p) {
    uint32_t a;
    asm("{ .reg .u64 t; cvta.to.shared.u64 t, %1; cvt.u32.u64 %0, t; }" : "=r"(a) : "l"(p));
    return a;
}
__device__ __forceinline__ void cp16(uint32_t dst, const void* src) {
    asm volatile("cp.async.cg.shared.global [%0], [%1], 16;" :: "r"(dst), "l"(src));
}
#define CP_COMMIT() asm volatile("cp.async.commit_group;" ::: "memory")
#define CP_WAIT(n)  asm volatile("cp.async.wait_group %0;" :: "n"(n) : "memory")

#define KCH 32
#define ROWB 80   // 40-half row stride: conflict-free ldmatrix

__device__ __forceinline__ void ldmA(uint32_t addr, uint32_t* f) {
    asm volatile("ldmatrix.sync.aligned.m8n8.x4.shared.b16 {%0,%1,%2,%3}, [%4];"
        : "=r"(f[0]), "=r"(f[1]), "=r"(f[2]), "=r"(f[3]) : "r"(addr));
}
__device__ __forceinline__ void ldmB4(uint32_t addr, uint32_t* f) {
    asm volatile("ldmatrix.sync.aligned.m8n8.x4.shared.b16 {%0,%1,%2,%3}, [%4];"
        : "=r"(f[0]), "=r"(f[1]), "=r"(f[2]), "=r"(f[3]) : "r"(addr));
}
__device__ __forceinline__ void ldmB4T(uint32_t addr, uint32_t* f) {
    asm volatile("ldmatrix.sync.aligned.m8n8.x4.trans.shared.b16 {%0,%1,%2,%3}, [%4];"
        : "=r"(f[0]), "=r"(f[1]), "=r"(f[2]), "=r"(f[3]) : "r"(addr));
}
__device__ __forceinline__ void hmma(float* d, const uint32_t* a, const uint32_t* b) {
    asm volatile(
        "mma.sync.aligned.m16n8k16.row.col.f32.f16.f16.f32 "
        "{%0,%1,%2,%3}, {%4,%5,%6,%7}, {%8,%9}, {%0,%1,%2,%3};"
        : "+f"(d[0]), "+f"(d[1]), "+f"(d[2]), "+f"(d[3])
        : "r"(a[0]), "r"(a[1]), "r"(a[2]), "r"(a[3]), "r"(b[0]), "r"(b[1]));
}

// ================= projection/MLP GEMM: cp.async 4-stage =================
#define G_ST_B  20480
#define G_SMEM  (4 * G_ST_B)  // 81920

template <int ACT, int OUTH>
__global__ __launch_bounds__(256)
void gemm_mma(const __half* __restrict__ A, const __half* __restrict__ Bt,
              const float* __restrict__ bias, float* __restrict__ Cf,
              __half* __restrict__ Ch, int M, int N, int K)
{
    extern __shared__ char dsm[];
    uint32_t su = smem_u32(dsm);
    int tid = threadIdx.x, warp = tid >> 5, lane = tid & 31;
    int m0 = blockIdx.y * 128, n0 = blockIdx.x * 128;
    int wm = (warp >> 1) * 32, wn = (warp & 1) * 64;

    const __half* Ab = A  + (size_t)m0 * K;
    const __half* Bb = Bt + (size_t)n0 * K;

    int row0 = tid >> 2, seg0 = (tid & 3);
    int row1 = (tid + 256) >> 2, seg1 = ((tid + 256) & 3);

    int nch = K / KCH;
#pragma unroll
    for (int s = 0; s < 3; s++) {
        uint32_t sb = su + s * G_ST_B;
        const __half* As = Ab + (size_t)s * KCH;
        const __half* Bs = Bb + (size_t)s * KCH;
        cp16(sb + row0 * ROWB + seg0 * 16, As + (size_t)row0 * K + seg0 * 8);
        cp16(sb + row1 * ROWB + seg1 * 16, As + (size_t)row1 * K + seg1 * 8);
        cp16(sb + 10240 + row0 * ROWB + seg0 * 16, Bs + (size_t)row0 * K + seg0 * 8);
        cp16(sb + 10240 + row1 * ROWB + seg1 * 16, Bs + (size_t)row1 * K + seg1 * 8);
        CP_COMMIT();
    }

    float acc[2][8][4];
#pragma unroll
    for (int i = 0; i < 2; i++)
#pragma unroll
        for (int j = 0; j < 8; j++)
#pragma unroll
            for (int t = 0; t < 4; t++) acc[i][j][t] = 0.f;

    int a_row = lane & 15, a_kh = (lane >> 4) * 8;
    int bp_row = ((lane >> 4) & 1) * 8 + (lane & 7);
    int bp_kh  = ((lane >> 3) & 1) * 8;

    for (int c = 0; c < nch; c++) {
        CP_WAIT(2);
        __syncthreads();
        if (c + 3 < nch) {
            uint32_t sb = su + ((c + 3) & 3) * G_ST_B;
            const __half* As = Ab + (size_t)(c + 3) * KCH;
            const __half* Bs = Bb + (size_t)(c + 3) * KCH;
            cp16(sb + row0 * ROWB + seg0 * 16, As + (size_t)row0 * K + seg0 * 8);
            cp16(sb + row1 * ROWB + seg1 * 16, As + (size_t)row1 * K + seg1 * 8);
            cp16(sb + 10240 + row0 * ROWB + seg0 * 16, Bs + (size_t)row0 * K + seg0 * 8);
            cp16(sb + 10240 + row1 * ROWB + seg1 * 16, Bs + (size_t)row1 * K + seg1 * 8);
        }
        CP_COMMIT();
        uint32_t sb = su + (c & 3) * G_ST_B;
#pragma unroll
        for (int ks = 0; ks < 2; ks++) {
            int kk = ks * 16;
            uint32_t afr[2][4];
#pragma unroll
            for (int mt = 0; mt < 2; mt++)
                ldmA(sb + (wm + mt * 16 + a_row) * ROWB + (kk + a_kh) * 2, afr[mt]);
#pragma unroll
            for (int p = 0; p < 4; p++) {
                uint32_t bfr[4];
                ldmB4(sb + 10240 + (wn + p * 16 + bp_row) * ROWB + (kk + bp_kh) * 2, bfr);
                hmma(acc[0][2 * p],     afr[0], bfr);
                hmma(acc[1][2 * p],     afr[1], bfr);
                hmma(acc[0][2 * p + 1], afr[0], bfr + 2);
                hmma(acc[1][2 * p + 1], afr[1], bfr + 2);
            }
        }
    }

    int g = lane >> 2, t4 = (lane & 3) * 2;
#pragma unroll
    for (int mt = 0; mt < 2; mt++) {
#pragma unroll
        for (int nt = 0; nt < 8; nt++) {
            int col = n0 + wn + nt * 8 + t4;
            float b0 = bias[col], b1 = bias[col + 1];
#pragma unroll
            for (int hf = 0; hf < 2; hf++) {
                int row = m0 + wm + mt * 16 + g + hf * 8;
                float x0 = acc[mt][nt][hf * 2 + 0] + b0;
                float x1 = acc[mt][nt][hf * 2 + 1] + b1;
                if (ACT == 1) {
                    x0 = 0.5f * x0 * (1.0f + erff(x0 * 0.70710678118654752f));
                    x1 = 0.5f * x1 * (1.0f + erff(x1 * 0.70710678118654752f));
                }
                if (OUTH) {
                    *(__half2*)(Ch + (size_t)row * N + col) = __floats2half2_rn(x0, x1);
                } else {
                    *(float2*)(Cf + (size_t)row * N + col) = make_float2(x0, x1);
                }
            }
        }
    }
}

// ================= split-fp16 saliency: 3-stage, flattened loop =================
#define S_ST_B  40960
#define S_SMEM  (3 * S_ST_B)  // 122880

__global__ __launch_bounds__(256)
void saliency_mma(const __half* __restrict__ shi, const __half* __restrict__ slo,
                  const __half* __restrict__ bhi, const __half* __restrict__ blo,
                  float* __restrict__ scores)
{
    extern __shared__ char dsm[];
    uint32_t su = smem_u32(dsm);
    int tid = threadIdx.x, warp = tid >> 5, lane = tid & 31;
    int b = blockIdx.y;
    int r0 = blockIdx.x * 128;
    int wm = (warp >> 1) * 32, wn = (warp & 1) * 64;

    const __half* Ahi = shi + ((size_t)b * NS + r0) * CDIM;
    const __half* Alo = slo + ((size_t)b * NS + r0) * CDIM;
    const __half* Bhi0 = bhi + (size_t)b * NB * CDIM;
    const __half* Blo0 = blo + (size_t)b * NB * CDIM;

    int row0 = tid >> 2, seg0 = (tid & 3);
    int row1 = (tid + 256) >> 2, seg1 = ((tid + 256) & 3);

    int a_row = lane & 15, a_kh = (lane >> 4) * 8;
    int bp_row = ((lane >> 4) & 1) * 8 + (lane & 7);
    int bp_kh  = ((lane >> 3) & 1) * 8;

    const int NCH = CDIM / KCH;   // 24
    const int NIT = 8 * NCH;      // 192

#define S_PREF(it) do { \
        int _jc = (it) / NCH, _c = (it) % NCH; \
        uint32_t sb = su + ((it) % 3) * S_ST_B; \
        int ko = _c * KCH; \
        const __half* Bh = Bhi0 + (size_t)_jc * 128 * CDIM; \
        const __half* Bl = Blo0 + (size_t)_jc * 128 * CDIM; \
        cp16(sb + row0 * ROWB + seg0 * 16, Ahi + (size_t)row0 * CDIM + ko + seg0 * 8); \
        cp16(sb + row1 * ROWB + seg1 * 16, Ahi + (size_t)row1 * CDIM + ko + seg1 * 8); \
        cp16(sb + 10240 + row0 * ROWB + seg0 * 16, Alo + (size_t)row0 * CDIM + ko + seg0 * 8); \
        cp16(sb + 10240 + row1 * ROWB + seg1 * 16, Alo + (size_t)row1 * CDIM + ko + seg1 * 8); \
        cp16(sb + 20480 + row0 * ROWB + seg0 * 16, Bh + (size_t)row0 * CDIM + ko + seg0 * 8); \
        cp16(sb + 20480 + row1 * ROWB + seg1 * 16, Bh + (size_t)row1 * CDIM + ko + seg1 * 8); \
        cp16(sb + 30720 + row0 * ROWB + seg0 * 16, Bl + (size_t)row0 * CDIM + ko + seg0 * 8); \
        cp16(sb + 30720 + row1 * ROWB + seg1 * 16, Bl + (size_t)row1 * CDIM + ko + seg1 * 8); \
    } while (0)

    S_PREF(0); CP_COMMIT();
    S_PREF(1); CP_COMMIT();

    float rm[2][2];
    rm[0][0] = rm[0][1] = rm[1][0] = rm[1][1] = -3.4e38f;
    float acc[2][8][4];

    for (int it = 0; it < NIT; it++) {
        int c = it % NCH;
        if (c == 0) {
#pragma unroll
            for (int i = 0; i < 2; i++)
#pragma unroll
                for (int j = 0; j < 8; j++)
#pragma unroll
                    for (int t = 0; t < 4; t++) acc[i][j][t] = 0.f;
        }
        CP_WAIT(1);
        __syncthreads();
        if (it + 2 < NIT) S_PREF(it + 2);
        CP_COMMIT();
        uint32_t sb = su + (it % 3) * S_ST_B;
#pragma unroll
        for (int ks = 0; ks < 2; ks++) {
            int kk = ks * 16;
            uint32_t ah[2][4], al[2][4];
#pragma unroll
            for (int mt = 0; mt < 2; mt++) {
                ldmA(sb + (wm + mt * 16 + a_row) * ROWB + (kk + a_kh) * 2, ah[mt]);
                ldmA(sb + 10240 + (wm + mt * 16 + a_row) * ROWB + (kk + a_kh) * 2, al[mt]);
            }
#pragma unroll
            for (int p = 0; p < 4; p++) {
                uint32_t bh4[4], bl4[4];
                ldmB4(sb + 20480 + (wn + p * 16 + bp_row) * ROWB + (kk + bp_kh) * 2, bh4);
                ldmB4(sb + 30720 + (wn + p * 16 + bp_row) * ROWB + (kk + bp_kh) * 2, bl4);
#pragma unroll
                for (int t = 0; t < 2; t++) {
                    int nt = 2 * p + t;
#pragma unroll
                    for (int mt = 0; mt < 2; mt++) {
                        hmma(acc[mt][nt], ah[mt], bh4 + 2 * t);
                        hmma(acc[mt][nt], ah[mt], bl4 + 2 * t);
                        hmma(acc[mt][nt], al[mt], bh4 + 2 * t);
                    }
                }
            }
        }
        if (c == NCH - 1) {
#pragma unroll
            for (int mt = 0; mt < 2; mt++)
#pragma unroll
                for (int hf = 0; hf < 2; hf++) {
                    float m = rm[mt][hf];
#pragma unroll
                    for (int nt = 0; nt < 8; nt++)
                        m = fmaxf(m, fmaxf(acc[mt][nt][hf * 2], acc[mt][nt][hf * 2 + 1]));
                    rm[mt][hf] = m;
                }
        }
    }
#undef S_PREF

    __syncthreads();
    float* red = (float*)dsm;  // [128][2]
    int g = lane >> 2;
#pragma unroll
    for (int mt = 0; mt < 2; mt++)
#pragma unroll
        for (int hf = 0; hf < 2; hf++) {
            float m = rm[mt][hf];
            m = fmaxf(m, __shfl_xor_sync(0xffffffffu, m, 1));
            m = fmaxf(m, __shfl_xor_sync(0xffffffffu, m, 2));
            if ((lane & 3) == 0) {
                int row = wm + mt * 16 + g + hf * 8;
                red[row * 2 + (warp & 1)] = m;
            }
        }
    __syncthreads();
    if (tid < 128)
        scores[(size_t)b * NS + r0 + tid] =
            fmaxf(red[tid * 2], red[tid * 2 + 1]) * 0.03608439182435161f;
}

// ================= tensor-core attention =================
#define AT_SMEM 73728
#define AT_Q   0
#define AT_KV  18432
#define AT_P   36864
#define AT_ST  71680
#define QROWB  144   // 72-half row (64 data + 8 pad)
#define PROWB  272   // 136-half row (128 data + 8 pad)

__global__ __launch_bounds__(256)
void attn_kernel(const __half* __restrict__ qh, const __half* __restrict__ kh,
                 const __half* __restrict__ vh,
                 float* __restrict__ attn_out, __half* __restrict__ ctx_h)
{
    extern __shared__ char dsm[];
    uint32_t su = smem_u32(dsm);
    int tid = threadIdx.x, warp = tid >> 5, lane = tid & 31;
    int qt = blockIdx.x, h = blockIdx.y, b = blockIdx.z;
    int qr0 = qt * 128;

    const __half* Qg = qh + ((size_t)(b * NB + qr0)) * CDIM + h * DH;
    const __half* Kg = kh + ((size_t)b * TOPK) * CDIM + h * DH;
    const __half* Vg = vh + ((size_t)b * TOPK) * CDIM + h * DH;

#pragma unroll
    for (int i = 0; i < 4; i++) {
        int idx = tid + i * 256;
        int r = idx >> 3, c = idx & 7;
        *(uint4*)(dsm + AT_Q  + r * QROWB + c * 16) = *(const uint4*)(Qg + (size_t)r * CDIM + c * 8);
        *(uint4*)(dsm + AT_KV + r * QROWB + c * 16) = *(const uint4*)(Kg + (size_t)r * CDIM + c * 8);
    }
    __syncthreads();

    int wm = (warp >> 1) * 32, wn = (warp & 1) * 64;
    int a_row = lane & 15, a_kh = (lane >> 4) * 8;
    int bp_row = ((lane >> 4) & 1) * 8 + (lane & 7);
    int bp_kh  = ((lane >> 3) & 1) * 8;

    float acc[2][8][4];
#pragma unroll
    for (int i = 0; i < 2; i++)
#pragma unroll
        for (int j = 0; j < 8; j++)
#pragma unroll
            for (int t = 0; t < 4; t++) acc[i][j][t] = 0.f;

#pragma unroll
    for (int ks = 0; ks < 4; ks++) {
        int kk = ks * 16;
        uint32_t afr[2][4];
#pragma unroll
        for (int mt = 0; mt < 2; mt++)
            ldmA(su + AT_Q + (wm + mt * 16 + a_row) * QROWB + (kk + a_kh) * 2, afr[mt]);
#pragma unroll
        for (int p = 0; p < 4; p++) {
            uint32_t bfr[4];
            ldmB4(su + AT_KV + (wn + p * 16 + bp_row) * QROWB + (kk + bp_kh) * 2, bfr);
            hmma(acc[0][2 * p],     afr[0], bfr);
            hmma(acc[1][2 * p],     afr[1], bfr);
            hmma(acc[0][2 * p + 1], afr[0], bfr + 2);
            hmma(acc[1][2 * p + 1], afr[1], bfr + 2);
        }
    }
    __syncthreads();   // K reads done everywhere

#pragma unroll
    for (int i = 0; i < 4; i++) {
        int idx = tid + i * 256;
        int r = idx >> 3, c = idx & 7;
        *(uint4*)(dsm + AT_KV + r * QROWB + c * 16) = *(const uint4*)(Vg + (size_t)r * CDIM + c * 8);
    }

    float* rstat = (float*)(dsm + AT_ST);  // [128][2]
    int g = lane >> 2, t4 = (lane & 3) * 2;

#pragma unroll
    for (int i = 0; i < 2; i++)
#pragma unroll
        for (int j = 0; j < 8; j++)
#pragma unroll
            for (int t = 0; t < 4; t++) acc[i][j][t] *= 0.125f;

    float gmax[2][2];
#pragma unroll
    for (int mt = 0; mt < 2; mt++)
#pragma unroll
        for (int hf = 0; hf < 2; hf++) {
            float m = -3.4e38f;
#pragma unroll
            for (int nt = 0; nt < 8; nt++)
                m = fmaxf(m, fmaxf(acc[mt][nt][hf * 2], acc[mt][nt][hf * 2 + 1]));
            m = fmaxf(m, __shfl_xor_sync(0xffffffffu, m, 1));
            m = fmaxf(m, __shfl_xor_sync(0xffffffffu, m, 2));
            if ((lane & 3) == 0)
                rstat[(wm + mt * 16 + g + hf * 8) * 2 + (warp & 1)] = m;
        }
    __syncthreads();
#pragma unroll
    for (int mt = 0; mt < 2; mt++)
#pragma unroll
        for (int hf = 0; hf < 2; hf++) {
            int row = wm + mt * 16 + g + hf * 8;
            gmax[mt][hf] = fmaxf(rstat[row * 2], rstat[row * 2 + 1]);
        }
    __syncthreads();

    float gsum[2][2];
#pragma unroll
    for (int mt = 0; mt < 2; mt++)
#pragma unroll
        for (int hf = 0; hf < 2; hf++) {
            float s = 0.f;
#pragma unroll
            for (int nt = 0; nt < 8; nt++) {
                float e0 = expf(acc[mt][nt][hf * 2]     - gmax[mt][hf]);
                float e1 = expf(acc[mt][nt][hf * 2 + 1] - gmax[mt][hf]);
                acc[mt][nt][hf * 2] = e0; acc[mt][nt][hf * 2 + 1] = e1;
                s += e0 + e1;
            }
            s += __shfl_xor_sync(0xffffffffu, s, 1);
            s += __shfl_xor_sync(0xffffffffu, s, 2);
            if ((lane & 3) == 0)
                rstat[(wm + mt * 16 + g + hf * 8) * 2 + (warp & 1)] = s;
        }
    __syncthreads();
#pragma unroll
    for (int mt = 0; mt < 2; mt++)
#pragma unroll
        for (int hf = 0; hf < 2; hf++) {
            int row = wm + mt * 16 + g + hf * 8;
            gsum[mt][hf] = 1.0f / (rstat[row * 2] + rstat[row * 2 + 1]);
        }

#pragma unroll
    for (int mt = 0; mt < 2; mt++)
#pragma unroll
        for (int hf = 0; hf < 2; hf++) {
            int row = wm + mt * 16 + g + hf * 8;
            size_t o = (((size_t)(b * HEADS + h)) * NB + qr0 + row) * TOPK;
            float inv = gsum[mt][hf];
#pragma unroll
            for (int nt = 0; nt < 8; nt++) {
                int col = wn + nt * 8 + t4;
                float p0 = acc[mt][nt][hf * 2]     * inv;
                float p1 = acc[mt][nt][hf * 2 + 1] * inv;
                *(float2*)(attn_out + o + col) = make_float2(p0, p1);
                *(__half2*)(dsm + AT_P + row * PROWB + col * 2) = __floats2half2_rn(p0, p1);
            }
        }
    __syncthreads();   // P + V visible

    int wq = warp * 16;
    float acc2[8][4];
#pragma unroll
    for (int j = 0; j < 8; j++)
#pragma unroll
        for (int t = 0; t < 4; t++) acc2[j][t] = 0.f;

    int vt = lane >> 3, vr = lane & 7;
#pragma unroll
    for (int ks = 0; ks < 8; ks++) {
        int kk = ks * 16;
        uint32_t ap[4];
        ldmA(su + AT_P + (wq + a_row) * PROWB + (kk + a_kh) * 2, ap);
#pragma unroll
        for (int p = 0; p < 4; p++) {
            uint32_t bv[4];
            uint32_t addr = su + AT_KV + (kk + (vt & 1) * 8 + vr) * QROWB + (p * 16 + (vt >> 1) * 8) * 2;
            ldmB4T(addr, bv);
            hmma(acc2[2 * p],     ap, bv);
            hmma(acc2[2 * p + 1], ap, bv + 2);
        }
    }
#pragma unroll
    for (int nt = 0; nt < 8; nt++)
#pragma unroll
        for (int hf = 0; hf < 2; hf++) {
            int row = wq + g + hf * 8;
            int col = nt * 8 + t4;
            *(__half2*)(ctx_h + ((size_t)(b * NB + qr0 + row)) * CDIM + h * DH + col) =
                __floats2half2_rn(acc2[nt][hf * 2], acc2[nt][hf * 2 + 1]);
        }
}

// ================= converts / transposes =================
__global__ __launch_bounds__(256)
void cvt_split_kernel(const float* __restrict__ in, __half* __restrict__ hi,
                      __half* __restrict__ lo, int n4)
{
    int i = blockIdx.x * 256 + threadIdx.x;
    if (i < n4) {
        float4 v = ((const float4*)in)[i];
        float h0 = __half2float(__float2half_rn(v.x));
        float h1 = __half2float(__float2half_rn(v.y));
        float h2 = __half2float(__float2half_rn(v.z));
        float h3 = __half2float(__float2half_rn(v.w));
        ((__half2*)hi)[2 * i]     = __floats2half2_rn(v.x, v.y);
        ((__half2*)hi)[2 * i + 1] = __floats2half2_rn(v.z, v.w);
        ((__half2*)lo)[2 * i]     = __floats2half2_rn(v.x - h0, v.y - h1);
        ((__half2*)lo)[2 * i + 1] = __floats2half2_rn(v.z - h2, v.w - h3);
    }
}

__global__ __launch_bounds__(256)
void transpose_h_kernel(const float* __restrict__ in, __half* __restrict__ out, int K, int N)
{
    __shared__ float t[32][33];
    int k0 = blockIdx.y * 32, n0 = blockIdx.x * 32;
    int tx = threadIdx.x & 31, ty = threadIdx.x >> 5;
#pragma unroll
    for (int i = 0; i < 4; i++)
        t[ty + i * 8][tx] = in[(size_t)(k0 + ty + i * 8) * N + n0 + tx];
    __syncthreads();
#pragma unroll
    for (int i = 0; i < 4; i++)
        out[(size_t)(n0 + ty + i * 8) * K + k0 + tx] = __float2half(t[tx][ty + i * 8]);
}

// ================= top-k =================
__global__ __launch_bounds__(1024)
void topk_kernel(const float* __restrict__ scores, float* __restrict__ topk_out)
{
    __shared__ unsigned long long keys[NS];
    int b = blockIdx.x, tid = threadIdx.x;
    for (int t = tid; t < NS; t += 1024) {
        unsigned int x = __float_as_uint(scores[(size_t)b * NS + t]);
        unsigned int u = (x & 0x80000000u) ? ~x : (x | 0x80000000u);
        keys[t] = (((unsigned long long)(~u)) << 32) | (unsigned int)t;
    }
    __syncthreads();
    for (int k = 2; k <= NS; k <<= 1) {
        for (int j = k >> 1; j > 0; j >>= 1) {
            for (int t = tid; t < NS; t += 1024) {
                int ixj = t ^ j;
                if (ixj > t) {
                    bool up = ((t & k) == 0);
                    unsigned long long a = keys[t], c = keys[ixj];
                    if ((a > c) == up) { keys[t] = c; keys[ixj] = a; }
                }
            }
            __syncthreads();
        }
    }
    if (tid < TOPK) {
        int idx = (int)(unsigned int)(keys[tid] & 0xFFFFFFFFull);
        g_topk[b * TOPK + tid] = idx;
        topk_out[b * TOPK + tid] = (float)idx;
    }
}

// ================= gather =================
__global__ __launch_bounds__(192)
void gather_kernel(const float* __restrict__ sampled, float* __restrict__ sel_out,
                   __half* __restrict__ sel_h)
{
    int b = blockIdx.y, kk = blockIdx.x;
    int idx = g_topk[b * TOPK + kk];
    const float4* src = (const float4*)(sampled + ((size_t)b * NS + idx) * CDIM);
    float4 v = src[threadIdx.x];
    size_t rowoff = ((size_t)b * TOPK + kk) * CDIM;
    ((float4*)(sel_out + rowoff))[threadIdx.x] = v;
    __half2* dh = (__half2*)(sel_h + rowoff);
    dh[2 * threadIdx.x]     = __floats2half2_rn(v.x, v.y);
    dh[2 * threadIdx.x + 1] = __floats2half2_rn(v.z, v.w);
}

// ================= layernorm: warp per row =================
template <int OUTH>
__global__ __launch_bounds__(256)
void ln_kernel(const float* __restrict__ Xa, const float* __restrict__ Xb,
               const float* __restrict__ gam, const float* __restrict__ bet,
               float* __restrict__ outp, __half* __restrict__ outh)
{
    int warp = threadIdx.x >> 5, lane = threadIdx.x & 31;
    int row = blockIdx.x * 8 + warp;
    const float4* xa = (const float4*)(Xa + (size_t)row * CDIM);
    const float4* xb = (const float4*)(Xb + (size_t)row * CDIM);
    float x[24];
    float s = 0.f, ss = 0.f;
#pragma unroll
    for (int i = 0; i < 6; i++) {
        float4 a = xa[lane + i * 32];
        float4 b = xb[lane + i * 32];
        float v0 = a.x + b.x, v1 = a.y + b.y, v2 = a.z + b.z, v3 = a.w + b.w;
        x[i * 4] = v0; x[i * 4 + 1] = v1; x[i * 4 + 2] = v2; x[i * 4 + 3] = v3;
        s += v0 + v1 + v2 + v3;
        ss += v0 * v0 + v1 * v1 + v2 * v2 + v3 * v3;
    }
#pragma unroll
    for (int o = 16; o; o >>= 1) {
        s  += __shfl_xor_sync(0xffffffffu, s,  o);
        ss += __shfl_xor_sync(0xffffffffu, ss, o);
    }
    float mu = s * (1.0f / CDIM);
    float rstd = rsqrtf(ss * (1.0f / CDIM) - mu * mu + 1e-5f);
    const float4* gv = (const float4*)gam;
    const float4* bv = (const float4*)bet;
#pragma unroll
    for (int i = 0; i < 6; i++) {
        float4 gg = gv[lane + i * 32];
        float4 bb = bv[lane + i * 32];
        float y0 = (x[i * 4]     - mu) * rstd * gg.x + bb.x;
        float y1 = (x[i * 4 + 1] - mu) * rstd * gg.y + bb.y;
        float y2 = (x[i * 4 + 2] - mu) * rstd * gg.z + bb.z;
        float y3 = (x[i * 4 + 3] - mu) * rstd * gg.w + bb.w;
        ((float4*)(outp + (size_t)row * CDIM))[lane + i * 32] = make_float4(y0, y1, y2, y3);
        if (OUTH) {
            __half2* oh = (__half2*)(outh + (size_t)row * CDIM) + (lane + i * 32) * 2;
            oh[0] = __floats2half2_rn(y0, y1);
            oh[1] = __floats2half2_rn(y2, y3);
        }
    }
}

// ================= launch =================
extern "C" void kernel_launch(void* const* d_in, const int* in_sizes, int n_in,
                              void* d_out, int out_size)
{
    const float* base    = (const float*)d_in[0];
    const float* sampled = (const float*)d_in[1];
    const float* Wq = (const float*)d_in[2];  const float* bq = (const float*)d_in[3];
    const float* Wk = (const float*)d_in[4];  const float* bk = (const float*)d_in[5];
    const float* Wv = (const float*)d_in[6];  const float* bv = (const float*)d_in[7];
    const float* Wo = (const float*)d_in[8];  const float* bo = (const float*)d_in[9];
    const float* g1 = (const float*)d_in[10]; const float* b1 = (const float*)d_in[11];
    const float* g2 = (const float*)d_in[12]; const float* b2 = (const float*)d_in[13];
    const float* Wm1 = (const float*)d_in[14]; const float* bm1 = (const float*)d_in[15];
    const float* Wm2 = (const float*)d_in[16]; const float* bm2 = (const float*)d_in[17];

    float* out = (float*)d_out;
    float* out_x      = out;
    float* out_scores = out + (size_t)BATCH * NB * CDIM;
    float* out_attn   = out_scores + (size_t)BATCH * NS;
    float* out_topk   = out_attn + (size_t)BATCH * HEADS * NB * TOPK;
    float* out_sel    = out_topk + (size_t)BATCH * TOPK;

    float *p_tmp, *p_ctx, *p_x1;
    __half *p_qh, *p_kh, *p_vh, *p_act, *p_selh, *p_h;
    __half *p_WqT, *p_WkT, *p_WvT, *p_WoT, *p_Wm1T, *p_Wm2T;
    __half *p_shi, *p_slo, *p_bhi, *p_blo;
    cudaGetSymbolAddress((void**)&p_tmp,  g_tmp);
    cudaGetSymbolAddress((void**)&p_ctx,  g_ctx);
    cudaGetSymbolAddress((void**)&p_x1,   g_x1);
    cudaGetSymbolAddress((void**)&p_qh,   g_q_h);
    cudaGetSymbolAddress((void**)&p_kh,   g_k_h);
    cudaGetSymbolAddress((void**)&p_vh,   g_v_h);
    cudaGetSymbolAddress((void**)&p_act,  g_act_h);
    cudaGetSymbolAddress((void**)&p_selh, g_sel_h);
    cudaGetSymbolAddress((void**)&p_h,    g_h_h);
    cudaGetSymbolAddress((void**)&p_WqT,  g_WqT);
    cudaGetSymbolAddress((void**)&p_WkT,  g_WkT);
    cudaGetSymbolAddress((void**)&p_WvT,  g_WvT);
    cudaGetSymbolAddress((void**)&p_WoT,  g_WoT);
    cudaGetSymbolAddress((void**)&p_Wm1T, g_Wm1T);
    cudaGetSymbolAddress((void**)&p_Wm2T, g_Wm2T);
    cudaGetSymbolAddress((void**)&p_shi,  g_s_hi);
    cudaGetSymbolAddress((void**)&p_slo,  g_s_lo);
    cudaGetSymbolAddress((void**)&p_bhi,  g_b_hi);
    cudaGetSymbolAddress((void**)&p_blo,  g_b_lo);

    cudaFuncSetAttribute(gemm_mma<0,0>, cudaFuncAttributeMaxDynamicSharedMemorySize, G_SMEM);
    cudaFuncSetAttribute(gemm_mma<0,1>, cudaFuncAttributeMaxDynamicSharedMemorySize, G_SMEM);
    cudaFuncSetAttribute(gemm_mma<1,1>, cudaFuncAttributeMaxDynamicSharedMemorySize, G_SMEM);
    cudaFuncSetAttribute(saliency_mma,  cudaFuncAttributeMaxDynamicSharedMemorySize, S_SMEM);
    cudaFuncSetAttribute(attn_kernel,   cudaFuncAttributeMaxDynamicSharedMemorySize, AT_SMEM);

    const int M  = BATCH * NB;    // 16384
    const int Ms = BATCH * TOPK;  // 2048

    transpose_h_kernel<<<dim3(CDIM/32, CDIM/32), 256>>>(Wq,  p_WqT,  CDIM, CDIM);
    transpose_h_kernel<<<dim3(CDIM/32, CDIM/32), 256>>>(Wk,  p_WkT,  CDIM, CDIM);
    transpose_h_kernel<<<dim3(CDIM/32, CDIM/32), 256>>>(Wv,  p_WvT,  CDIM, CDIM);
    transpose_h_kernel<<<dim3(CDIM/32, CDIM/32), 256>>>(Wo,  p_WoT,  CDIM, CDIM);
    transpose_h_kernel<<<dim3(C4/32,   CDIM/32), 256>>>(Wm1, p_Wm1T, CDIM, C4);
    transpose_h_kernel<<<dim3(CDIM/32, C4/32),   256>>>(Wm2, p_Wm2T, C4, CDIM);

    cvt_split_kernel<<<(BATCH * NS * CDIM / 4 + 255) / 256, 256>>>(sampled, p_shi, p_slo, BATCH * NS * CDIM / 4);
    cvt_split_kernel<<<(BATCH * NB * CDIM / 4 + 255) / 256, 256>>>(base, p_bhi, p_blo, BATCH * NB * CDIM / 4);
    saliency_mma<<<dim3(NS/128, BATCH), 256, S_SMEM>>>(p_shi, p_slo, p_bhi, p_blo, out_scores);
    topk_kernel<<<BATCH, 1024>>>(out_scores, out_topk);
    gather_kernel<<<dim3(TOPK, BATCH), 192>>>(sampled, out_sel, p_selh);

    gemm_mma<0,1><<<dim3(CDIM/128, M/128),  256, G_SMEM>>>(p_bhi,  p_WqT, bq, nullptr, p_qh, M,  CDIM, CDIM);
    gemm_mma<0,1><<<dim3(CDIM/128, Ms/128), 256, G_SMEM>>>(p_selh, p_WkT, bk, nullptr, p_kh, Ms, CDIM, CDIM);
    gemm_mma<0,1><<<dim3(CDIM/128, Ms/128), 256, G_SMEM>>>(p_selh, p_WvT, bv, nullptr, p_vh, Ms, CDIM, CDIM);

    attn_kernel<<<dim3(NB/128, HEADS, BATCH), 256, AT_SMEM>>>(p_qh, p_kh, p_vh, out_attn, p_act);

    gemm_mma<0,0><<<dim3(CDIM/128, M/128), 256, G_SMEM>>>(p_act, p_WoT, bo, p_tmp, nullptr, M, CDIM, CDIM);

    ln_kernel<1><<<M/8, 256>>>(base, p_tmp, g1, b1, p_x1, p_act);
    gemm_mma<1,1><<<dim3(C4/128, M/128), 256, G_SMEM>>>(p_act, p_Wm1T, bm1, nullptr, p_h, M, C4, CDIM);
    gemm_mma<0,0><<<dim3(CDIM/128, M/128), 256, G_SMEM>>>(p_h, p_Wm2T, bm2, p_ctx, nullptr, M, CDIM, C4);
    ln_kernel<0><<<M/8, 256>>>(p_x1, p_ctx, g2, b2, out_x, nullptr);
}

// round 12
// speedup vs baseline: 5.0745x; 1.0275x over previous
#include <cuda_runtime.h>
#include <cuda_fp16.h>
#include <math.h>
#include <stdint.h>

#define BATCH 16
#define NB    1024
#define NS    4096
#define CDIM  768
#define HEADS 12
#define DH    64
#define TOPK  128
#define C4    3072

// ---------------- device scratch ----------------
__device__ float g_tmp[BATCH * (size_t)NB * CDIM];
__device__ float g_ctx[BATCH * (size_t)NB * CDIM];
__device__ float g_x1 [BATCH * (size_t)NB * CDIM];
__device__ int   g_topk[BATCH * TOPK];
__device__ __half g_q_h [BATCH * (size_t)NB * CDIM];
__device__ __half g_k_h [BATCH * (size_t)TOPK * CDIM];
__device__ __half g_v_h [BATCH * (size_t)TOPK * CDIM];
__device__ __half g_act_h [BATCH * (size_t)NB * CDIM];
__device__ __half g_sel_h [BATCH * (size_t)TOPK * CDIM];
__device__ __half g_h_h   [BATCH * (size_t)NB * C4];
__device__ __half g_WqT[CDIM * CDIM];
__device__ __half g_WkT[CDIM * CDIM];
__device__ __half g_WvT[CDIM * CDIM];
__device__ __half g_WoT[CDIM * CDIM];
__device__ __half g_Wm1T[(size_t)C4 * CDIM];
__device__ __half g_Wm2T[(size_t)CDIM * C4];
__device__ __half g_s_hi[BATCH * (size_t)NS * CDIM];
__device__ __half g_s_lo[BATCH * (size_t)NS * CDIM];
__device__ __half g_b_hi[BATCH * (size_t)NB * CDIM];
__device__ __half g_b_lo[BATCH * (size_t)NB * CDIM];

// ================= helpers =================
__device__ __forceinline__ uint32_t smem_u32(const void* p) {
    uint32_t a;
    asm("{ .reg .u64 t; cvta.to.shared.u64 t, %1; cvt.u32.u64 %0, t; }" : "=r"(a) : "l"(p));
    return a;
}
__device__ __forceinline__ void cp16(uint32_t dst, const void* src) {
    asm volatile("cp.async.cg.shared.global [%0], [%1], 16;" :: "r"(dst), "l"(src));
}
#define CP_COMMIT() asm volatile("cp.async.commit_group;" ::: "memory")
#define CP_WAIT(n)  asm volatile("cp.async.wait_group %0;" :: "n"(n) : "memory")

#define KCH 32
#define ROWB 80

__device__ __forceinline__ void ldmA(uint32_t addr, uint32_t* f) {
    asm volatile("ldmatrix.sync.aligned.m8n8.x4.shared.b16 {%0,%1,%2,%3}, [%4];"
        : "=r"(f[0]), "=r"(f[1]), "=r"(f[2]), "=r"(f[3]) : "r"(addr));
}
__device__ __forceinline__ void ldmB4(uint32_t addr, uint32_t* f) {
    asm volatile("ldmatrix.sync.aligned.m8n8.x4.shared.b16 {%0,%1,%2,%3}, [%4];"
        : "=r"(f[0]), "=r"(f[1]), "=r"(f[2]), "=r"(f[3]) : "r"(addr));
}
__device__ __forceinline__ void ldmB4T(uint32_t addr, uint32_t* f) {
    asm volatile("ldmatrix.sync.aligned.m8n8.x4.trans.shared.b16 {%0,%1,%2,%3}, [%4];"
        : "=r"(f[0]), "=r"(f[1]), "=r"(f[2]), "=r"(f[3]) : "r"(addr));
}
__device__ __forceinline__ void hmma(float* d, const uint32_t* a, const uint32_t* b) {
    asm volatile(
        "mma.sync.aligned.m16n8k16.row.col.f32.f16.f16.f32 "
        "{%0,%1,%2,%3}, {%4,%5,%6,%7}, {%8,%9}, {%0,%1,%2,%3};"
        : "+f"(d[0]), "+f"(d[1]), "+f"(d[2]), "+f"(d[3])
        : "r"(a[0]), "r"(a[1]), "r"(a[2]), "r"(a[3]), "r"(b[0]), "r"(b[1]));
}

// ================= projection/MLP GEMM: cp.async 4-stage, 2 CTA/SM =================
#define G_ST_B  20480
#define G_SMEM  (4 * G_ST_B)  // 81920

template <int ACT, int OUTH>
__global__ __launch_bounds__(256, 2)
void gemm_mma(const __half* __restrict__ A, const __half* __restrict__ Bt,
              const float* __restrict__ bias, float* __restrict__ Cf,
              __half* __restrict__ Ch, int M, int N, int K)
{
    extern __shared__ char dsm[];
    uint32_t su = smem_u32(dsm);
    int tid = threadIdx.x, warp = tid >> 5, lane = tid & 31;
    int m0 = blockIdx.y * 128, n0 = blockIdx.x * 128;
    int wm = (warp >> 1) * 32, wn = (warp & 1) * 64;

    const __half* Ab = A  + (size_t)m0 * K;
    const __half* Bb = Bt + (size_t)n0 * K;

    int row0 = tid >> 2, seg0 = (tid & 3);
    int row1 = (tid + 256) >> 2, seg1 = ((tid + 256) & 3);

    int nch = K / KCH;
#pragma unroll
    for (int s = 0; s < 3; s++) {
        uint32_t sb = su + s * G_ST_B;
        const __half* As = Ab + (size_t)s * KCH;
        const __half* Bs = Bb + (size_t)s * KCH;
        cp16(sb + row0 * ROWB + seg0 * 16, As + (size_t)row0 * K + seg0 * 8);
        cp16(sb + row1 * ROWB + seg1 * 16, As + (size_t)row1 * K + seg1 * 8);
        cp16(sb + 10240 + row0 * ROWB + seg0 * 16, Bs + (size_t)row0 * K + seg0 * 8);
        cp16(sb + 10240 + row1 * ROWB + seg1 * 16, Bs + (size_t)row1 * K + seg1 * 8);
        CP_COMMIT();
    }

    float acc[2][8][4];
#pragma unroll
    for (int i = 0; i < 2; i++)
#pragma unroll
        for (int j = 0; j < 8; j++)
#pragma unroll
            for (int t = 0; t < 4; t++) acc[i][j][t] = 0.f;

    int a_row = lane & 15, a_kh = (lane >> 4) * 8;
    int bp_row = ((lane >> 4) & 1) * 8 + (lane & 7);
    int bp_kh  = ((lane >> 3) & 1) * 8;

    for (int c = 0; c < nch; c++) {
        CP_WAIT(2);
        __syncthreads();
        if (c + 3 < nch) {
            uint32_t sb = su + ((c + 3) & 3) * G_ST_B;
            const __half* As = Ab + (size_t)(c + 3) * KCH;
            const __half* Bs = Bb + (size_t)(c + 3) * KCH;
            cp16(sb + row0 * ROWB + seg0 * 16, As + (size_t)row0 * K + seg0 * 8);
            cp16(sb + row1 * ROWB + seg1 * 16, As + (size_t)row1 * K + seg1 * 8);
            cp16(sb + 10240 + row0 * ROWB + seg0 * 16, Bs + (size_t)row0 * K + seg0 * 8);
            cp16(sb + 10240 + row1 * ROWB + seg1 * 16, Bs + (size_t)row1 * K + seg1 * 8);
        }
        CP_COMMIT();
        uint32_t sb = su + (c & 3) * G_ST_B;
#pragma unroll
        for (int ks = 0; ks < 2; ks++) {
            int kk = ks * 16;
            uint32_t afr[2][4];
#pragma unroll
            for (int mt = 0; mt < 2; mt++)
                ldmA(sb + (wm + mt * 16 + a_row) * ROWB + (kk + a_kh) * 2, afr[mt]);
#pragma unroll
            for (int p = 0; p < 4; p++) {
                uint32_t bfr[4];
                ldmB4(sb + 10240 + (wn + p * 16 + bp_row) * ROWB + (kk + bp_kh) * 2, bfr);
                hmma(acc[0][2 * p],     afr[0], bfr);
                hmma(acc[1][2 * p],     afr[1], bfr);
                hmma(acc[0][2 * p + 1], afr[0], bfr + 2);
                hmma(acc[1][2 * p + 1], afr[1], bfr + 2);
            }
        }
    }

    int g = lane >> 2, t4 = (lane & 3) * 2;
#pragma unroll
    for (int mt = 0; mt < 2; mt++) {
#pragma unroll
        for (int nt = 0; nt < 8; nt++) {
            int col = n0 + wn + nt * 8 + t4;
            float b0 = bias[col], b1 = bias[col + 1];
#pragma unroll
            for (int hf = 0; hf < 2; hf++) {
                int row = m0 + wm + mt * 16 + g + hf * 8;
                float x0 = acc[mt][nt][hf * 2 + 0] + b0;
                float x1 = acc[mt][nt][hf * 2 + 1] + b1;
                if (ACT == 1) {
                    x0 = 0.5f * x0 * (1.0f + erff(x0 * 0.70710678118654752f));
                    x1 = 0.5f * x1 * (1.0f + erff(x1 * 0.70710678118654752f));
                }
                if (OUTH) {
                    *(__half2*)(Ch + (size_t)row * N + col) = __floats2half2_rn(x0, x1);
                } else {
                    *(float2*)(Cf + (size_t)row * N + col) = make_float2(x0, x1);
                }
            }
        }
    }
}

// ================= split-fp16 saliency: 512 threads, 16 warps =================
#define S_ST_B  40960
#define S_SMEM  (3 * S_ST_B)  // 122880

__global__ __launch_bounds__(512)
void saliency_mma(const __half* __restrict__ shi, const __half* __restrict__ slo,
                  const __half* __restrict__ bhi, const __half* __restrict__ blo,
                  float* __restrict__ scores)
{
    extern __shared__ char dsm[];
    uint32_t su = smem_u32(dsm);
    int tid = threadIdx.x, warp = tid >> 5, lane = tid & 31;
    int b = blockIdx.y;
    int r0 = blockIdx.x * 128;
    int wm = (warp >> 1) * 16, wn = (warp & 1) * 64;   // 8 m-groups x 2 n-groups

    const __half* Ahi = shi + ((size_t)b * NS + r0) * CDIM;
    const __half* Alo = slo + ((size_t)b * NS + r0) * CDIM;
    const __half* Bhi0 = bhi + (size_t)b * NB * CDIM;
    const __half* Blo0 = blo + (size_t)b * NB * CDIM;

    int prow = tid >> 2, pseg = tid & 3;   // 512 threads: one seg per sub-tile each

    int a_row = lane & 15, a_kh = (lane >> 4) * 8;
    int bp_row = ((lane >> 4) & 1) * 8 + (lane & 7);
    int bp_kh  = ((lane >> 3) & 1) * 8;

    const int NCH = CDIM / KCH;   // 24
    const int NIT = 8 * NCH;      // 192

#define S_PREF(it) do { \
        int _jc = (it) / NCH, _c = (it) % NCH; \
        uint32_t sb = su + ((it) % 3) * S_ST_B; \
        int ko = _c * KCH; \
        const __half* Bh = Bhi0 + (size_t)_jc * 128 * CDIM; \
        const __half* Bl = Blo0 + (size_t)_jc * 128 * CDIM; \
        cp16(sb + prow * ROWB + pseg * 16,         Ahi + (size_t)prow * CDIM + ko + pseg * 8); \
        cp16(sb + 10240 + prow * ROWB + pseg * 16, Alo + (size_t)prow * CDIM + ko + pseg * 8); \
        cp16(sb + 20480 + prow * ROWB + pseg * 16, Bh  + (size_t)prow * CDIM + ko + pseg * 8); \
        cp16(sb + 30720 + prow * ROWB + pseg * 16, Bl  + (size_t)prow * CDIM + ko + pseg * 8); \
    } while (0)

    S_PREF(0); CP_COMMIT();
    S_PREF(1); CP_COMMIT();

    float rm[2];
    rm[0] = rm[1] = -3.4e38f;
    float acc[8][4];

    for (int it = 0; it < NIT; it++) {
        int c = it % NCH;
        if (c == 0) {
#pragma unroll
            for (int j = 0; j < 8; j++)
#pragma unroll
                for (int t = 0; t < 4; t++) acc[j][t] = 0.f;
        }
        CP_WAIT(1);
        __syncthreads();
        if (it + 2 < NIT) S_PREF(it + 2);
        CP_COMMIT();
        uint32_t sb = su + (it % 3) * S_ST_B;
#pragma unroll
        for (int ks = 0; ks < 2; ks++) {
            int kk = ks * 16;
            uint32_t ah[4], al[4];
            ldmA(sb + (wm + a_row) * ROWB + (kk + a_kh) * 2, ah);
            ldmA(sb + 10240 + (wm + a_row) * ROWB + (kk + a_kh) * 2, al);
#pragma unroll
            for (int p = 0; p < 4; p++) {
                uint32_t bh4[4], bl4[4];
                ldmB4(sb + 20480 + (wn + p * 16 + bp_row) * ROWB + (kk + bp_kh) * 2, bh4);
                ldmB4(sb + 30720 + (wn + p * 16 + bp_row) * ROWB + (kk + bp_kh) * 2, bl4);
#pragma unroll
                for (int t = 0; t < 2; t++) {
                    int nt = 2 * p + t;
                    hmma(acc[nt], ah, bh4 + 2 * t);
                    hmma(acc[nt], ah, bl4 + 2 * t);
                    hmma(acc[nt], al, bh4 + 2 * t);
                }
            }
        }
        if (c == NCH - 1) {
#pragma unroll
            for (int hf = 0; hf < 2; hf++) {
                float m = rm[hf];
#pragma unroll
                for (int nt = 0; nt < 8; nt++)
                    m = fmaxf(m, fmaxf(acc[nt][hf * 2], acc[nt][hf * 2 + 1]));
                rm[hf] = m;
            }
        }
    }
#undef S_PREF

    __syncthreads();
    float* red = (float*)dsm;  // [128][2]
    int g = lane >> 2;
#pragma unroll
    for (int hf = 0; hf < 2; hf++) {
        float m = rm[hf];
        m = fmaxf(m, __shfl_xor_sync(0xffffffffu, m, 1));
        m = fmaxf(m, __shfl_xor_sync(0xffffffffu, m, 2));
        if ((lane & 3) == 0)
            red[(wm + g + hf * 8) * 2 + (warp & 1)] = m;
    }
    __syncthreads();
    if (tid < 128)
        scores[(size_t)b * NS + r0 + tid] =
            fmaxf(red[tid * 2], red[tid * 2 + 1]) * 0.03608439182435161f;
}

// ================= tensor-core attention =================
#define AT_SMEM 73728
#define AT_Q   0
#define AT_KV  18432
#define AT_P   36864
#define AT_ST  71680
#define QROWB  144
#define PROWB  272

__global__ __launch_bounds__(256)
void attn_kernel(const __half* __restrict__ qh, const __half* __restrict__ kh,
                 const __half* __restrict__ vh,
                 float* __restrict__ attn_out, __half* __restrict__ ctx_h)
{
    extern __shared__ char dsm[];
    uint32_t su = smem_u32(dsm);
    int tid = threadIdx.x, warp = tid >> 5, lane = tid & 31;
    int qt = blockIdx.x, h = blockIdx.y, b = blockIdx.z;
    int qr0 = qt * 128;

    const __half* Qg = qh + ((size_t)(b * NB + qr0)) * CDIM + h * DH;
    const __half* Kg = kh + ((size_t)b * TOPK) * CDIM + h * DH;
    const __half* Vg = vh + ((size_t)b * TOPK) * CDIM + h * DH;

#pragma unroll
    for (int i = 0; i < 4; i++) {
        int idx = tid + i * 256;
        int r = idx >> 3, c = idx & 7;
        *(uint4*)(dsm + AT_Q  + r * QROWB + c * 16) = *(const uint4*)(Qg + (size_t)r * CDIM + c * 8);
        *(uint4*)(dsm + AT_KV + r * QROWB + c * 16) = *(const uint4*)(Kg + (size_t)r * CDIM + c * 8);
    }
    __syncthreads();

    int wm = (warp >> 1) * 32, wn = (warp & 1) * 64;
    int a_row = lane & 15, a_kh = (lane >> 4) * 8;
    int bp_row = ((lane >> 4) & 1) * 8 + (lane & 7);
    int bp_kh  = ((lane >> 3) & 1) * 8;

    float acc[2][8][4];
#pragma unroll
    for (int i = 0; i < 2; i++)
#pragma unroll
        for (int j = 0; j < 8; j++)
#pragma unroll
            for (int t = 0; t < 4; t++) acc[i][j][t] = 0.f;

#pragma unroll
    for (int ks = 0; ks < 4; ks++) {
        int kk = ks * 16;
        uint32_t afr[2][4];
#pragma unroll
        for (int mt = 0; mt < 2; mt++)
            ldmA(su + AT_Q + (wm + mt * 16 + a_row) * QROWB + (kk + a_kh) * 2, afr[mt]);
#pragma unroll
        for (int p = 0; p < 4; p++) {
            uint32_t bfr[4];
            ldmB4(su + AT_KV + (wn + p * 16 + bp_row) * QROWB + (kk + bp_kh) * 2, bfr);
            hmma(acc[0][2 * p],     afr[0], bfr);
            hmma(acc[1][2 * p],     afr[1], bfr);
            hmma(acc[0][2 * p + 1], afr[0], bfr + 2);
            hmma(acc[1][2 * p + 1], afr[1], bfr + 2);
        }
    }
    __syncthreads();

#pragma unroll
    for (int i = 0; i < 4; i++) {
        int idx = tid + i * 256;
        int r = idx >> 3, c = idx & 7;
        *(uint4*)(dsm + AT_KV + r * QROWB + c * 16) = *(const uint4*)(Vg + (size_t)r * CDIM + c * 8);
    }

    float* rstat = (float*)(dsm + AT_ST);
    int g = lane >> 2, t4 = (lane & 3) * 2;

#pragma unroll
    for (int i = 0; i < 2; i++)
#pragma unroll
        for (int j = 0; j < 8; j++)
#pragma unroll
            for (int t = 0; t < 4; t++) acc[i][j][t] *= 0.125f;

    float gmax[2][2];
#pragma unroll
    for (int mt = 0; mt < 2; mt++)
#pragma unroll
        for (int hf = 0; hf < 2; hf++) {
            float m = -3.4e38f;
#pragma unroll
            for (int nt = 0; nt < 8; nt++)
                m = fmaxf(m, fmaxf(acc[mt][nt][hf * 2], acc[mt][nt][hf * 2 + 1]));
            m = fmaxf(m, __shfl_xor_sync(0xffffffffu, m, 1));
            m = fmaxf(m, __shfl_xor_sync(0xffffffffu, m, 2));
            if ((lane & 3) == 0)
                rstat[(wm + mt * 16 + g + hf * 8) * 2 + (warp & 1)] = m;
        }
    __syncthreads();
#pragma unroll
    for (int mt = 0; mt < 2; mt++)
#pragma unroll
        for (int hf = 0; hf < 2; hf++) {
            int row = wm + mt * 16 + g + hf * 8;
            gmax[mt][hf] = fmaxf(rstat[row * 2], rstat[row * 2 + 1]);
        }
    __syncthreads();

    float gsum[2][2];
#pragma unroll
    for (int mt = 0; mt < 2; mt++)
#pragma unroll
        for (int hf = 0; hf < 2; hf++) {
            float s = 0.f;
#pragma unroll
            for (int nt = 0; nt < 8; nt++) {
                float e0 = expf(acc[mt][nt][hf * 2]     - gmax[mt][hf]);
                float e1 = expf(acc[mt][nt][hf * 2 + 1] - gmax[mt][hf]);
                acc[mt][nt][hf * 2] = e0; acc[mt][nt][hf * 2 + 1] = e1;
                s += e0 + e1;
            }
            s += __shfl_xor_sync(0xffffffffu, s, 1);
            s += __shfl_xor_sync(0xffffffffu, s, 2);
            if ((lane & 3) == 0)
                rstat[(wm + mt * 16 + g + hf * 8) * 2 + (warp & 1)] = s;
        }
    __syncthreads();
#pragma unroll
    for (int mt = 0; mt < 2; mt++)
#pragma unroll
        for (int hf = 0; hf < 2; hf++) {
            int row = wm + mt * 16 + g + hf * 8;
            gsum[mt][hf] = 1.0f / (rstat[row * 2] + rstat[row * 2 + 1]);
        }

#pragma unroll
    for (int mt = 0; mt < 2; mt++)
#pragma unroll
        for (int hf = 0; hf < 2; hf++) {
            int row = wm + mt * 16 + g + hf * 8;
            size_t o = (((size_t)(b * HEADS + h)) * NB + qr0 + row) * TOPK;
            float inv = gsum[mt][hf];
#pragma unroll
            for (int nt = 0; nt < 8; nt++) {
                int col = wn + nt * 8 + t4;
                float p0 = acc[mt][nt][hf * 2]     * inv;
                float p1 = acc[mt][nt][hf * 2 + 1] * inv;
                *(float2*)(attn_out + o + col) = make_float2(p0, p1);
                *(__half2*)(dsm + AT_P + row * PROWB + col * 2) = __floats2half2_rn(p0, p1);
            }
        }
    __syncthreads();

    int wq = warp * 16;
    float acc2[8][4];
#pragma unroll
    for (int j = 0; j < 8; j++)
#pragma unroll
        for (int t = 0; t < 4; t++) acc2[j][t] = 0.f;

    int vt = lane >> 3, vr = lane & 7;
#pragma unroll
    for (int ks = 0; ks < 8; ks++) {
        int kk = ks * 16;
        uint32_t ap[4];
        ldmA(su + AT_P + (wq + a_row) * PROWB + (kk + a_kh) * 2, ap);
#pragma unroll
        for (int p = 0; p < 4; p++) {
            uint32_t bv[4];
            uint32_t addr = su + AT_KV + (kk + (vt & 1) * 8 + vr) * QROWB + (p * 16 + (vt >> 1) * 8) * 2;
            ldmB4T(addr, bv);
            hmma(acc2[2 * p],     ap, bv);
            hmma(acc2[2 * p + 1], ap, bv + 2);
        }
    }
#pragma unroll
    for (int nt = 0; nt < 8; nt++)
#pragma unroll
        for (int hf = 0; hf < 2; hf++) {
            int row = wq + g + hf * 8;
            int col = nt * 8 + t4;
            *(__half2*)(ctx_h + ((size_t)(b * NB + qr0 + row)) * CDIM + h * DH + col) =
                __floats2half2_rn(acc2[nt][hf * 2], acc2[nt][hf * 2 + 1]);
        }
}

// ================= converts / transposes =================
__global__ __launch_bounds__(256)
void cvt_split_kernel(const float* __restrict__ in, __half* __restrict__ hi,
                      __half* __restrict__ lo, int n4)
{
    int i = blockIdx.x * 256 + threadIdx.x;
    if (i < n4) {
        float4 v = ((const float4*)in)[i];
        float h0 = __half2float(__float2half_rn(v.x));
        float h1 = __half2float(__float2half_rn(v.y));
        float h2 = __half2float(__float2half_rn(v.z));
        float h3 = __half2float(__float2half_rn(v.w));
        ((__half2*)hi)[2 * i]     = __floats2half2_rn(v.x, v.y);
        ((__half2*)hi)[2 * i + 1] = __floats2half2_rn(v.z, v.w);
        ((__half2*)lo)[2 * i]     = __floats2half2_rn(v.x - h0, v.y - h1);
        ((__half2*)lo)[2 * i + 1] = __floats2half2_rn(v.z - h2, v.w - h3);
    }
}

__global__ __launch_bounds__(256)
void transpose_h_kernel(const float* __restrict__ in, __half* __restrict__ out, int K, int N)
{
    __shared__ float t[32][33];
    int k0 = blockIdx.y * 32, n0 = blockIdx.x * 32;
    int tx = threadIdx.x & 31, ty = threadIdx.x >> 5;
#pragma unroll
    for (int i = 0; i < 4; i++)
        t[ty + i * 8][tx] = in[(size_t)(k0 + ty + i * 8) * N + n0 + tx];
    __syncthreads();
#pragma unroll
    for (int i = 0; i < 4; i++)
        out[(size_t)(n0 + ty + i * 8) * K + k0 + tx] = __float2half(t[tx][ty + i * 8]);
}

// ================= top-k =================
__global__ __launch_bounds__(1024)
void topk_kernel(const float* __restrict__ scores, float* __restrict__ topk_out)
{
    __shared__ unsigned long long keys[NS];
    int b = blockIdx.x, tid = threadIdx.x;
    for (int t = tid; t < NS; t += 1024) {
        unsigned int x = __float_as_uint(scores[(size_t)b * NS + t]);
        unsigned int u = (x & 0x80000000u) ? ~x : (x | 0x80000000u);
        keys[t] = (((unsigned long long)(~u)) << 32) | (unsigned int)t;
    }
    __syncthreads();
    for (int k = 2; k <= NS; k <<= 1) {
        for (int j = k >> 1; j > 0; j >>= 1) {
            for (int t = tid; t < NS; t += 1024) {
                int ixj = t ^ j;
                if (ixj > t) {
                    bool up = ((t & k) == 0);
                    unsigned long long a = keys[t], c = keys[ixj];
                    if ((a > c) == up) { keys[t] = c; keys[ixj] = a; }
                }
            }
            __syncthreads();
        }
    }
    if (tid < TOPK) {
        int idx = (int)(unsigned int)(keys[tid] & 0xFFFFFFFFull);
        g_topk[b * TOPK + tid] = idx;
        topk_out[b * TOPK + tid] = (float)idx;
    }
}

// ================= gather =================
__global__ __launch_bounds__(192)
void gather_kernel(const float* __restrict__ sampled, float* __restrict__ sel_out,
                   __half* __restrict__ sel_h)
{
    int b = blockIdx.y, kk = blockIdx.x;
    int idx = g_topk[b * TOPK + kk];
    const float4* src = (const float4*)(sampled + ((size_t)b * NS + idx) * CDIM);
    float4 v = src[threadIdx.x];
    size_t rowoff = ((size_t)b * TOPK + kk) * CDIM;
    ((float4*)(sel_out + rowoff))[threadIdx.x] = v;
    __half2* dh = (__half2*)(sel_h + rowoff);
    dh[2 * threadIdx.x]     = __floats2half2_rn(v.x, v.y);
    dh[2 * threadIdx.x + 1] = __floats2half2_rn(v.z, v.w);
}

// ================= layernorm: warp per row =================
template <int OUTH>
__global__ __launch_bounds__(256)
void ln_kernel(const float* __restrict__ Xa, const float* __restrict__ Xb,
               const float* __restrict__ gam, const float* __restrict__ bet,
               float* __restrict__ outp, __half* __restrict__ outh)
{
    int warp = threadIdx.x >> 5, lane = threadIdx.x & 31;
    int row = blockIdx.x * 8 + warp;
    const float4* xa = (const float4*)(Xa + (size_t)row * CDIM);
    const float4* xb = (const float4*)(Xb + (size_t)row * CDIM);
    float x[24];
    float s = 0.f, ss = 0.f;
#pragma unroll
    for (int i = 0; i < 6; i++) {
        float4 a = xa[lane + i * 32];
        float4 b = xb[lane + i * 32];
        float v0 = a.x + b.x, v1 = a.y + b.y, v2 = a.z + b.z, v3 = a.w + b.w;
        x[i * 4] = v0; x[i * 4 + 1] = v1; x[i * 4 + 2] = v2; x[i * 4 + 3] = v3;
        s += v0 + v1 + v2 + v3;
        ss += v0 * v0 + v1 * v1 + v2 * v2 + v3 * v3;
    }
#pragma unroll
    for (int o = 16; o; o >>= 1) {
        s  += __shfl_xor_sync(0xffffffffu, s,  o);
        ss += __shfl_xor_sync(0xffffffffu, ss, o);
    }
    float mu = s * (1.0f / CDIM);
    float rstd = rsqrtf(ss * (1.0f / CDIM) - mu * mu + 1e-5f);
    const float4* gv = (const float4*)gam;
    const float4* bv = (const float4*)bet;
#pragma unroll
    for (int i = 0; i < 6; i++) {
        float4 gg = gv[lane + i * 32];
        float4 bb = bv[lane + i * 32];
        float y0 = (x[i * 4]     - mu) * rstd * gg.x + bb.x;
        float y1 = (x[i * 4 + 1] - mu) * rstd * gg.y + bb.y;
        float y2 = (x[i * 4 + 2] - mu) * rstd * gg.z + bb.z;
        float y3 = (x[i * 4 + 3] - mu) * rstd * gg.w + bb.w;
        ((float4*)(outp + (size_t)row * CDIM))[lane + i * 32] = make_float4(y0, y1, y2, y3);
        if (OUTH) {
            __half2* oh = (__half2*)(outh + (size_t)row * CDIM) + (lane + i * 32) * 2;
            oh[0] = __floats2half2_rn(y0, y1);
            oh[1] = __floats2half2_rn(y2, y3);
        }
    }
}

// ================= launch =================
extern "C" void kernel_launch(void* const* d_in, const int* in_sizes, int n_in,
                              void* d_out, int out_size)
{
    const float* base    = (const float*)d_in[0];
    const float* sampled = (const float*)d_in[1];
    const float* Wq = (const float*)d_in[2];  const float* bq = (const float*)d_in[3];
    const float* Wk = (const float*)d_in[4];  const float* bk = (const float*)d_in[5];
    const float* Wv = (const float*)d_in[6];  const float* bv = (const float*)d_in[7];
    const float* Wo = (const float*)d_in[8];  const float* bo = (const float*)d_in[9];
    const float* g1 = (const float*)d_in[10]; const float* b1 = (const float*)d_in[11];
    const float* g2 = (const float*)d_in[12]; const float* b2 = (const float*)d_in[13];
    const float* Wm1 = (const float*)d_in[14]; const float* bm1 = (const float*)d_in[15];
    const float* Wm2 = (const float*)d_in[16]; const float* bm2 = (const float*)d_in[17];

    float* out = (float*)d_out;
    float* out_x      = out;
    float* out_scores = out + (size_t)BATCH * NB * CDIM;
    float* out_attn   = out_scores + (size_t)BATCH * NS;
    float* out_topk   = out_attn + (size_t)BATCH * HEADS * NB * TOPK;
    float* out_sel    = out_topk + (size_t)BATCH * TOPK;

    float *p_tmp, *p_ctx, *p_x1;
    __half *p_qh, *p_kh, *p_vh, *p_act, *p_selh, *p_h;
    __half *p_WqT, *p_WkT, *p_WvT, *p_WoT, *p_Wm1T, *p_Wm2T;
    __half *p_shi, *p_slo, *p_bhi, *p_blo;
    cudaGetSymbolAddress((void**)&p_tmp,  g_tmp);
    cudaGetSymbolAddress((void**)&p_ctx,  g_ctx);
    cudaGetSymbolAddress((void**)&p_x1,   g_x1);
    cudaGetSymbolAddress((void**)&p_qh,   g_q_h);
    cudaGetSymbolAddress((void**)&p_kh,   g_k_h);
    cudaGetSymbolAddress((void**)&p_vh,   g_v_h);
    cudaGetSymbolAddress((void**)&p_act,  g_act_h);
    cudaGetSymbolAddress((void**)&p_selh, g_sel_h);
    cudaGetSymbolAddress((void**)&p_h,    g_h_h);
    cudaGetSymbolAddress((void**)&p_WqT,  g_WqT);
    cudaGetSymbolAddress((void**)&p_WkT,  g_WkT);
    cudaGetSymbolAddress((void**)&p_WvT,  g_WvT);
    cudaGetSymbolAddress((void**)&p_WoT,  g_WoT);
    cudaGetSymbolAddress((void**)&p_Wm1T, g_Wm1T);
    cudaGetSymbolAddress((void**)&p_Wm2T, g_Wm2T);
    cudaGetSymbolAddress((void**)&p_shi,  g_s_hi);
    cudaGetSymbolAddress((void**)&p_slo,  g_s_lo);
    cudaGetSymbolAddress((void**)&p_bhi,  g_b_hi);
    cudaGetSymbolAddress((void**)&p_blo,  g_b_lo);

    cudaFuncSetAttribute(gemm_mma<0,0>, cudaFuncAttributeMaxDynamicSharedMemorySize, G_SMEM);
    cudaFuncSetAttribute(gemm_mma<0,1>, cudaFuncAttributeMaxDynamicSharedMemorySize, G_SMEM);
    cudaFuncSetAttribute(gemm_mma<1,1>, cudaFuncAttributeMaxDynamicSharedMemorySize, G_SMEM);
    cudaFuncSetAttribute(saliency_mma,  cudaFuncAttributeMaxDynamicSharedMemorySize, S_SMEM);
    cudaFuncSetAttribute(attn_kernel,   cudaFuncAttributeMaxDynamicSharedMemorySize, AT_SMEM);

    const int M  = BATCH * NB;    // 16384
    const int Ms = BATCH * TOPK;  // 2048

    transpose_h_kernel<<<dim3(CDIM/32, CDIM/32), 256>>>(Wq,  p_WqT,  CDIM, CDIM);
    transpose_h_kernel<<<dim3(CDIM/32, CDIM/32), 256>>>(Wk,  p_WkT,  CDIM, CDIM);
    transpose_h_kernel<<<dim3(CDIM/32, CDIM/32), 256>>>(Wv,  p_WvT,  CDIM, CDIM);
    transpose_h_kernel<<<dim3(CDIM/32, CDIM/32), 256>>>(Wo,  p_WoT,  CDIM, CDIM);
    transpose_h_kernel<<<dim3(C4/32,   CDIM/32), 256>>>(Wm1, p_Wm1T, CDIM, C4);
    transpose_h_kernel<<<dim3(CDIM/32, C4/32),   256>>>(Wm2, p_Wm2T, C4, CDIM);

    cvt_split_kernel<<<(BATCH * NS * CDIM / 4 + 255) / 256, 256>>>(sampled, p_shi, p_slo, BATCH * NS * CDIM / 4);
    cvt_split_kernel<<<(BATCH * NB * CDIM / 4 + 255) / 256, 256>>>(base, p_bhi, p_blo, BATCH * NB * CDIM / 4);
    saliency_mma<<<dim3(NS/128, BATCH), 512, S_SMEM>>>(p_shi, p_slo, p_bhi, p_blo, out_scores);
    topk_kernel<<<BATCH, 1024>>>(out_scores, out_topk);
    gather_kernel<<<dim3(TOPK, BATCH), 192>>>(sampled, out_sel, p_selh);

    gemm_mma<0,1><<<dim3(CDIM/128, M/128),  256, G_SMEM>>>(p_bhi,  p_WqT, bq, nullptr, p_qh, M,  CDIM, CDIM);
    gemm_mma<0,1><<<dim3(CDIM/128, Ms/128), 256, G_SMEM>>>(p_selh, p_WkT, bk, nullptr, p_kh, Ms, CDIM, CDIM);
    gemm_mma<0,1><<<dim3(CDIM/128, Ms/128), 256, G_SMEM>>>(p_selh, p_WvT, bv, nullptr, p_vh, Ms, CDIM, CDIM);

    attn_kernel<<<dim3(NB/128, HEADS, BATCH), 256, AT_SMEM>>>(p_qh, p_kh, p_vh, out_attn, p_act);

    gemm_mma<0,0><<<dim3(CDIM/128, M/128), 256, G_SMEM>>>(p_act, p_WoT, bo, p_tmp, nullptr, M, CDIM, CDIM);

    ln_kernel<1><<<M/8, 256>>>(base, p_tmp, g1, b1, p_x1, p_act);
    gemm_mma<1,1><<<dim3(C4/128, M/128), 256, G_SMEM>>>(p_act, p_Wm1T, bm1, nullptr, p_h, M, C4, CDIM);
    gemm_mma<0,0><<<dim3(CDIM/128, M/128), 256, G_SMEM>>>(p_h, p_Wm2T, bm2, p_ctx, nullptr, M, CDIM, C4);
    ln_kernel<0><<<M/8, 256>>>(p_x1, p_ctx, g2, b2, out_x, nullptr);
}

// round 13
// speedup vs baseline: 5.1146x; 1.0079x over previous
#include <cuda_runtime.h>
#include <cuda_fp16.h>
#include <math.h>
#include <stdint.h>

#define BATCH 16
#define NB    1024
#define NS    4096
#define CDIM  768
#define HEADS 12
#define DH    64
#define TOPK  128
#define C4    3072

// ---------------- device scratch ----------------
__device__ float g_tmp[BATCH * (size_t)NB * CDIM];
__device__ float g_ctx[BATCH * (size_t)NB * CDIM];
__device__ float g_x1 [BATCH * (size_t)NB * CDIM];
__device__ __half g_q_h [BATCH * (size_t)NB * CDIM];
__device__ __half g_k_h [BATCH * (size_t)TOPK * CDIM];
__device__ __half g_v_h [BATCH * (size_t)TOPK * CDIM];
__device__ __half g_act_h [BATCH * (size_t)NB * CDIM];
__device__ __half g_sel_h [BATCH * (size_t)TOPK * CDIM];
__device__ __half g_h_h   [BATCH * (size_t)NB * C4];
__device__ __half g_WqT[CDIM * CDIM];
__device__ __half g_WkT[CDIM * CDIM];
__device__ __half g_WvT[CDIM * CDIM];
__device__ __half g_WoT[CDIM * CDIM];
__device__ __half g_Wm1T[(size_t)C4 * CDIM];
__device__ __half g_Wm2T[(size_t)CDIM * C4];
__device__ __half g_s_hi[BATCH * (size_t)NS * CDIM];
__device__ __half g_s_lo[BATCH * (size_t)NS * CDIM];
__device__ __half g_b_hi[BATCH * (size_t)NB * CDIM];
__device__ __half g_b_lo[BATCH * (size_t)NB * CDIM];

// ================= helpers =================
__device__ __forceinline__ uint32_t smem_u32(const void* p) {
    uint32_t a;
    asm("{ .reg .u64 t; cvta.to.shared.u64 t, %1; cvt.u32.u64 %0, t; }" : "=r"(a) : "l"(p));
    return a;
}
__device__ __forceinline__ void cp16(uint32_t dst, const void* src) {
    asm volatile("cp.async.cg.shared.global [%0], [%1], 16;" :: "r"(dst), "l"(src));
}
#define CP_COMMIT() asm volatile("cp.async.commit_group;" ::: "memory")
#define CP_WAIT(n)  asm volatile("cp.async.wait_group %0;" :: "n"(n) : "memory")

#define KCH 32
#define ROWB 80

__device__ __forceinline__ void ldmA(uint32_t addr, uint32_t* f) {
    asm volatile("ldmatrix.sync.aligned.m8n8.x4.shared.b16 {%0,%1,%2,%3}, [%4];"
        : "=r"(f[0]), "=r"(f[1]), "=r"(f[2]), "=r"(f[3]) : "r"(addr));
}
__device__ __forceinline__ void ldmB4(uint32_t addr, uint32_t* f) {
    asm volatile("ldmatrix.sync.aligned.m8n8.x4.shared.b16 {%0,%1,%2,%3}, [%4];"
        : "=r"(f[0]), "=r"(f[1]), "=r"(f[2]), "=r"(f[3]) : "r"(addr));
}
__device__ __forceinline__ void ldmB4T(uint32_t addr, uint32_t* f) {
    asm volatile("ldmatrix.sync.aligned.m8n8.x4.trans.shared.b16 {%0,%1,%2,%3}, [%4];"
        : "=r"(f[0]), "=r"(f[1]), "=r"(f[2]), "=r"(f[3]) : "r"(addr));
}
__device__ __forceinline__ void hmma(float* d, const uint32_t* a, const uint32_t* b) {
    asm volatile(
        "mma.sync.aligned.m16n8k16.row.col.f32.f16.f16.f32 "
        "{%0,%1,%2,%3}, {%4,%5,%6,%7}, {%8,%9}, {%0,%1,%2,%3};"
        : "+f"(d[0]), "+f"(d[1]), "+f"(d[2]), "+f"(d[3])
        : "r"(a[0]), "r"(a[1]), "r"(a[2]), "r"(a[3]), "r"(b[0]), "r"(b[1]));
}

// ================= GEMM core (shared by plain + fused-QKV kernels) =================
#define G_ST_B  20480
#define G_SMEM  (4 * G_ST_B)  // 81920

template <int ACT, int OUTH>
__device__ __forceinline__ void gemm_body(
    char* dsm, const __half* __restrict__ A, const __half* __restrict__ Bt,
    const float* __restrict__ bias, float* __restrict__ Cf,
    __half* __restrict__ Ch, int m0, int n0, int N, int K)
{
    uint32_t su = smem_u32(dsm);
    int tid = threadIdx.x, warp = tid >> 5, lane = tid & 31;
    int wm = (warp >> 1) * 32, wn = (warp & 1) * 64;

    const __half* Ab = A  + (size_t)m0 * K;
    const __half* Bb = Bt + (size_t)n0 * K;

    int row0 = tid >> 2, seg0 = (tid & 3);
    int row1 = (tid + 256) >> 2, seg1 = ((tid + 256) & 3);

    int nch = K / KCH;
#pragma unroll
    for (int s = 0; s < 3; s++) {
        uint32_t sb = su + s * G_ST_B;
        const __half* As = Ab + (size_t)s * KCH;
        const __half* Bs = Bb + (size_t)s * KCH;
        cp16(sb + row0 * ROWB + seg0 * 16, As + (size_t)row0 * K + seg0 * 8);
        cp16(sb + row1 * ROWB + seg1 * 16, As + (size_t)row1 * K + seg1 * 8);
        cp16(sb + 10240 + row0 * ROWB + seg0 * 16, Bs + (size_t)row0 * K + seg0 * 8);
        cp16(sb + 10240 + row1 * ROWB + seg1 * 16, Bs + (size_t)row1 * K + seg1 * 8);
        CP_COMMIT();
    }

    float acc[2][8][4];
#pragma unroll
    for (int i = 0; i < 2; i++)
#pragma unroll
        for (int j = 0; j < 8; j++)
#pragma unroll
            for (int t = 0; t < 4; t++) acc[i][j][t] = 0.f;

    int a_row = lane & 15, a_kh = (lane >> 4) * 8;
    int bp_row = ((lane >> 4) & 1) * 8 + (lane & 7);
    int bp_kh  = ((lane >> 3) & 1) * 8;

    for (int c = 0; c < nch; c++) {
        CP_WAIT(2);
        __syncthreads();
        if (c + 3 < nch) {
            uint32_t sb = su + ((c + 3) & 3) * G_ST_B;
            const __half* As = Ab + (size_t)(c + 3) * KCH;
            const __half* Bs = Bb + (size_t)(c + 3) * KCH;
            cp16(sb + row0 * ROWB + seg0 * 16, As + (size_t)row0 * K + seg0 * 8);
            cp16(sb + row1 * ROWB + seg1 * 16, As + (size_t)row1 * K + seg1 * 8);
            cp16(sb + 10240 + row0 * ROWB + seg0 * 16, Bs + (size_t)row0 * K + seg0 * 8);
            cp16(sb + 10240 + row1 * ROWB + seg1 * 16, Bs + (size_t)row1 * K + seg1 * 8);
        }
        CP_COMMIT();
        uint32_t sb = su + (c & 3) * G_ST_B;
#pragma unroll
        for (int ks = 0; ks < 2; ks++) {
            int kk = ks * 16;
            uint32_t afr[2][4];
#pragma unroll
            for (int mt = 0; mt < 2; mt++)
                ldmA(sb + (wm + mt * 16 + a_row) * ROWB + (kk + a_kh) * 2, afr[mt]);
#pragma unroll
            for (int p = 0; p < 4; p++) {
                uint32_t bfr[4];
                ldmB4(sb + 10240 + (wn + p * 16 + bp_row) * ROWB + (kk + bp_kh) * 2, bfr);
                hmma(acc[0][2 * p],     afr[0], bfr);
                hmma(acc[1][2 * p],     afr[1], bfr);
                hmma(acc[0][2 * p + 1], afr[0], bfr + 2);
                hmma(acc[1][2 * p + 1], afr[1], bfr + 2);
            }
        }
    }

    int g = lane >> 2, t4 = (lane & 3) * 2;
#pragma unroll
    for (int mt = 0; mt < 2; mt++) {
#pragma unroll
        for (int nt = 0; nt < 8; nt++) {
            int col = n0 + wn + nt * 8 + t4;
            float b0 = bias[col], b1 = bias[col + 1];
#pragma unroll
            for (int hf = 0; hf < 2; hf++) {
                int row = m0 + wm + mt * 16 + g + hf * 8;
                float x0 = acc[mt][nt][hf * 2 + 0] + b0;
                float x1 = acc[mt][nt][hf * 2 + 1] + b1;
                if (ACT == 1) {
                    x0 = 0.5f * x0 * (1.0f + erff(x0 * 0.70710678118654752f));
                    x1 = 0.5f * x1 * (1.0f + erff(x1 * 0.70710678118654752f));
                }
                if (OUTH) {
                    *(__half2*)(Ch + (size_t)row * N + col) = __floats2half2_rn(x0, x1);
                } else {
                    *(float2*)(Cf + (size_t)row * N + col) = make_float2(x0, x1);
                }
            }
        }
    }
}

template <int ACT, int OUTH>
__global__ __launch_bounds__(256, 2)
void gemm_mma(const __half* __restrict__ A, const __half* __restrict__ Bt,
              const float* __restrict__ bias, float* __restrict__ Cf,
              __half* __restrict__ Ch, int M, int N, int K)
{
    extern __shared__ char dsm[];
    gemm_body<ACT, OUTH>(dsm, A, Bt, bias, Cf, Ch,
                         blockIdx.y * 128, blockIdx.x * 128, N, K);
}

// fused Q/K/V projection: grid (CDIM/128, 160); by<128 Q, 128..143 K, 144..159 V
__global__ __launch_bounds__(256, 2)
void gemm_qkv(const __half* __restrict__ Aq, const __half* __restrict__ Akv,
              const __half* __restrict__ WqT, const __half* __restrict__ WkT,
              const __half* __restrict__ WvT,
              const float* __restrict__ bq, const float* __restrict__ bk,
              const float* __restrict__ bv,
              __half* __restrict__ Cq, __half* __restrict__ Ck, __half* __restrict__ Cv)
{
    extern __shared__ char dsm[];
    int by = blockIdx.y;
    const __half *A, *W;
    const float* bias;
    __half* C;
    int m0;
    if (by < 128)      { A = Aq;  W = WqT; bias = bq; C = Cq; m0 = by * 128; }
    else if (by < 144) { A = Akv; W = WkT; bias = bk; C = Ck; m0 = (by - 128) * 128; }
    else               { A = Akv; W = WvT; bias = bv; C = Cv; m0 = (by - 144) * 128; }
    gemm_body<0, 1>(dsm, A, W, bias, nullptr, C, m0, blockIdx.x * 128, CDIM, CDIM);
}

// ================= split-fp16 saliency: 512 threads, 16 warps =================
#define S_ST_B  40960
#define S_SMEM  (3 * S_ST_B)  // 122880

__global__ __launch_bounds__(512)
void saliency_mma(const __half* __restrict__ shi, const __half* __restrict__ slo,
                  const __half* __restrict__ bhi, const __half* __restrict__ blo,
                  float* __restrict__ scores)
{
    extern __shared__ char dsm[];
    uint32_t su = smem_u32(dsm);
    int tid = threadIdx.x, warp = tid >> 5, lane = tid & 31;
    int b = blockIdx.y;
    int r0 = blockIdx.x * 128;
    int wm = (warp >> 1) * 16, wn = (warp & 1) * 64;

    const __half* Ahi = shi + ((size_t)b * NS + r0) * CDIM;
    const __half* Alo = slo + ((size_t)b * NS + r0) * CDIM;
    const __half* Bhi0 = bhi + (size_t)b * NB * CDIM;
    const __half* Blo0 = blo + (size_t)b * NB * CDIM;

    int prow = tid >> 2, pseg = tid & 3;

    int a_row = lane & 15, a_kh = (lane >> 4) * 8;
    int bp_row = ((lane >> 4) & 1) * 8 + (lane & 7);
    int bp_kh  = ((lane >> 3) & 1) * 8;

    const int NCH = CDIM / KCH;   // 24
    const int NIT = 8 * NCH;      // 192

#define S_PREF(it) do { \
        int _jc = (it) / NCH, _c = (it) % NCH; \
        uint32_t sb = su + ((it) % 3) * S_ST_B; \
        int ko = _c * KCH; \
        const __half* Bh = Bhi0 + (size_t)_jc * 128 * CDIM; \
        const __half* Bl = Blo0 + (size_t)_jc * 128 * CDIM; \
        cp16(sb + prow * ROWB + pseg * 16,         Ahi + (size_t)prow * CDIM + ko + pseg * 8); \
        cp16(sb + 10240 + prow * ROWB + pseg * 16, Alo + (size_t)prow * CDIM + ko + pseg * 8); \
        cp16(sb + 20480 + prow * ROWB + pseg * 16, Bh  + (size_t)prow * CDIM + ko + pseg * 8); \
        cp16(sb + 30720 + prow * ROWB + pseg * 16, Bl  + (size_t)prow * CDIM + ko + pseg * 8); \
    } while (0)

    S_PREF(0); CP_COMMIT();
    S_PREF(1); CP_COMMIT();

    float rm[2];
    rm[0] = rm[1] = -3.4e38f;
    float acc[8][4];

    for (int it = 0; it < NIT; it++) {
        int c = it % NCH;
        if (c == 0) {
#pragma unroll
            for (int j = 0; j < 8; j++)
#pragma unroll
                for (int t = 0; t < 4; t++) acc[j][t] = 0.f;
        }
        CP_WAIT(1);
        __syncthreads();
        if (it + 2 < NIT) S_PREF(it + 2);
        CP_COMMIT();
        uint32_t sb = su + (it % 3) * S_ST_B;
#pragma unroll
        for (int ks = 0; ks < 2; ks++) {
            int kk = ks * 16;
            uint32_t ah[4], al[4];
            ldmA(sb + (wm + a_row) * ROWB + (kk + a_kh) * 2, ah);
            ldmA(sb + 10240 + (wm + a_row) * ROWB + (kk + a_kh) * 2, al);
#pragma unroll
            for (int p = 0; p < 4; p++) {
                uint32_t bh4[4], bl4[4];
                ldmB4(sb + 20480 + (wn + p * 16 + bp_row) * ROWB + (kk + bp_kh) * 2, bh4);
                ldmB4(sb + 30720 + (wn + p * 16 + bp_row) * ROWB + (kk + bp_kh) * 2, bl4);
#pragma unroll
                for (int t = 0; t < 2; t++) {
                    int nt = 2 * p + t;
                    hmma(acc[nt], ah, bh4 + 2 * t);
                    hmma(acc[nt], ah, bl4 + 2 * t);
                    hmma(acc[nt], al, bh4 + 2 * t);
                }
            }
        }
        if (c == NCH - 1) {
#pragma unroll
            for (int hf = 0; hf < 2; hf++) {
                float m = rm[hf];
#pragma unroll
                for (int nt = 0; nt < 8; nt++)
                    m = fmaxf(m, fmaxf(acc[nt][hf * 2], acc[nt][hf * 2 + 1]));
                rm[hf] = m;
            }
        }
    }
#undef S_PREF

    __syncthreads();
    float* red = (float*)dsm;
    int g = lane >> 2;
#pragma unroll
    for (int hf = 0; hf < 2; hf++) {
        float m = rm[hf];
        m = fmaxf(m, __shfl_xor_sync(0xffffffffu, m, 1));
        m = fmaxf(m, __shfl_xor_sync(0xffffffffu, m, 2));
        if ((lane & 3) == 0)
            red[(wm + g + hf * 8) * 2 + (warp & 1)] = m;
    }
    __syncthreads();
    if (tid < 128)
        scores[(size_t)b * NS + r0 + tid] =
            fmaxf(red[tid * 2], red[tid * 2 + 1]) * 0.03608439182435161f;
}

// ================= tensor-core attention =================
#define AT_SMEM 73728
#define AT_Q   0
#define AT_KV  18432
#define AT_P   36864
#define AT_ST  71680
#define QROWB  144
#define PROWB  272

__global__ __launch_bounds__(256)
void attn_kernel(const __half* __restrict__ qh, const __half* __restrict__ kh,
                 const __half* __restrict__ vh,
                 float* __restrict__ attn_out, __half* __restrict__ ctx_h)
{
    extern __shared__ char dsm[];
    uint32_t su = smem_u32(dsm);
    int tid = threadIdx.x, warp = tid >> 5, lane = tid & 31;
    int qt = blockIdx.x, h = blockIdx.y, b = blockIdx.z;
    int qr0 = qt * 128;

    const __half* Qg = qh + ((size_t)(b * NB + qr0)) * CDIM + h * DH;
    const __half* Kg = kh + ((size_t)b * TOPK) * CDIM + h * DH;
    const __half* Vg = vh + ((size_t)b * TOPK) * CDIM + h * DH;

#pragma unroll
    for (int i = 0; i < 4; i++) {
        int idx = tid + i * 256;
        int r = idx >> 3, c = idx & 7;
        *(uint4*)(dsm + AT_Q  + r * QROWB + c * 16) = *(const uint4*)(Qg + (size_t)r * CDIM + c * 8);
        *(uint4*)(dsm + AT_KV + r * QROWB + c * 16) = *(const uint4*)(Kg + (size_t)r * CDIM + c * 8);
    }
    __syncthreads();

    int wm = (warp >> 1) * 32, wn = (warp & 1) * 64;
    int a_row = lane & 15, a_kh = (lane >> 4) * 8;
    int bp_row = ((lane >> 4) & 1) * 8 + (lane & 7);
    int bp_kh  = ((lane >> 3) & 1) * 8;

    float acc[2][8][4];
#pragma unroll
    for (int i = 0; i < 2; i++)
#pragma unroll
        for (int j = 0; j < 8; j++)
#pragma unroll
            for (int t = 0; t < 4; t++) acc[i][j][t] = 0.f;

#pragma unroll
    for (int ks = 0; ks < 4; ks++) {
        int kk = ks * 16;
        uint32_t afr[2][4];
#pragma unroll
        for (int mt = 0; mt < 2; mt++)
            ldmA(su + AT_Q + (wm + mt * 16 + a_row) * QROWB + (kk + a_kh) * 2, afr[mt]);
#pragma unroll
        for (int p = 0; p < 4; p++) {
            uint32_t bfr[4];
            ldmB4(su + AT_KV + (wn + p * 16 + bp_row) * QROWB + (kk + bp_kh) * 2, bfr);
            hmma(acc[0][2 * p],     afr[0], bfr);
            hmma(acc[1][2 * p],     afr[1], bfr);
            hmma(acc[0][2 * p + 1], afr[0], bfr + 2);
            hmma(acc[1][2 * p + 1], afr[1], bfr + 2);
        }
    }
    __syncthreads();

#pragma unroll
    for (int i = 0; i < 4; i++) {
        int idx = tid + i * 256;
        int r = idx >> 3, c = idx & 7;
        *(uint4*)(dsm + AT_KV + r * QROWB + c * 16) = *(const uint4*)(Vg + (size_t)r * CDIM + c * 8);
    }

    float* rstat = (float*)(dsm + AT_ST);
    int g = lane >> 2, t4 = (lane & 3) * 2;

#pragma unroll
    for (int i = 0; i < 2; i++)
#pragma unroll
        for (int j = 0; j < 8; j++)
#pragma unroll
            for (int t = 0; t < 4; t++) acc[i][j][t] *= 0.125f;

    float gmax[2][2];
#pragma unroll
    for (int mt = 0; mt < 2; mt++)
#pragma unroll
        for (int hf = 0; hf < 2; hf++) {
            float m = -3.4e38f;
#pragma unroll
            for (int nt = 0; nt < 8; nt++)
                m = fmaxf(m, fmaxf(acc[mt][nt][hf * 2], acc[mt][nt][hf * 2 + 1]));
            m = fmaxf(m, __shfl_xor_sync(0xffffffffu, m, 1));
            m = fmaxf(m, __shfl_xor_sync(0xffffffffu, m, 2));
            if ((lane & 3) == 0)
                rstat[(wm + mt * 16 + g + hf * 8) * 2 + (warp & 1)] = m;
        }
    __syncthreads();
#pragma unroll
    for (int mt = 0; mt < 2; mt++)
#pragma unroll
        for (int hf = 0; hf < 2; hf++) {
            int row = wm + mt * 16 + g + hf * 8;
            gmax[mt][hf] = fmaxf(rstat[row * 2], rstat[row * 2 + 1]);
        }
    __syncthreads();

    float gsum[2][2];
#pragma unroll
    for (int mt = 0; mt < 2; mt++)
#pragma unroll
        for (int hf = 0; hf < 2; hf++) {
            float s = 0.f;
#pragma unroll
            for (int nt = 0; nt < 8; nt++) {
                float e0 = expf(acc[mt][nt][hf * 2]     - gmax[mt][hf]);
                float e1 = expf(acc[mt][nt][hf * 2 + 1] - gmax[mt][hf]);
                acc[mt][nt][hf * 2] = e0; acc[mt][nt][hf * 2 + 1] = e1;
                s += e0 + e1;
            }
            s += __shfl_xor_sync(0xffffffffu, s, 1);
            s += __shfl_xor_sync(0xffffffffu, s, 2);
            if ((lane & 3) == 0)
                rstat[(wm + mt * 16 + g + hf * 8) * 2 + (warp & 1)] = s;
        }
    __syncthreads();
#pragma unroll
    for (int mt = 0; mt < 2; mt++)
#pragma unroll
        for (int hf = 0; hf < 2; hf++) {
            int row = wm + mt * 16 + g + hf * 8;
            gsum[mt][hf] = 1.0f / (rstat[row * 2] + rstat[row * 2 + 1]);
        }

#pragma unroll
    for (int mt = 0; mt < 2; mt++)
#pragma unroll
        for (int hf = 0; hf < 2; hf++) {
            int row = wm + mt * 16 + g + hf * 8;
            size_t o = (((size_t)(b * HEADS + h)) * NB + qr0 + row) * TOPK;
            float inv = gsum[mt][hf];
#pragma unroll
            for (int nt = 0; nt < 8; nt++) {
                int col = wn + nt * 8 + t4;
                float p0 = acc[mt][nt][hf * 2]     * inv;
                float p1 = acc[mt][nt][hf * 2 + 1] * inv;
                *(float2*)(attn_out + o + col) = make_float2(p0, p1);
                *(__half2*)(dsm + AT_P + row * PROWB + col * 2) = __floats2half2_rn(p0, p1);
            }
        }
    __syncthreads();

    int wq = warp * 16;
    float acc2[8][4];
#pragma unroll
    for (int j = 0; j < 8; j++)
#pragma unroll
        for (int t = 0; t < 4; t++) acc2[j][t] = 0.f;

    int vt = lane >> 3, vr = lane & 7;
#pragma unroll
    for (int ks = 0; ks < 8; ks++) {
        int kk = ks * 16;
        uint32_t ap[4];
        ldmA(su + AT_P + (wq + a_row) * PROWB + (kk + a_kh) * 2, ap);
#pragma unroll
        for (int p = 0; p < 4; p++) {
            uint32_t bv[4];
            uint32_t addr = su + AT_KV + (kk + (vt & 1) * 8 + vr) * QROWB + (p * 16 + (vt >> 1) * 8) * 2;
            ldmB4T(addr, bv);
            hmma(acc2[2 * p],     ap, bv);
            hmma(acc2[2 * p + 1], ap, bv + 2);
        }
    }
#pragma unroll
    for (int nt = 0; nt < 8; nt++)
#pragma unroll
        for (int hf = 0; hf < 2; hf++) {
            int row = wq + g + hf * 8;
            int col = nt * 8 + t4;
            *(__half2*)(ctx_h + ((size_t)(b * NB + qr0 + row)) * CDIM + h * DH + col) =
                __floats2half2_rn(acc2[nt][hf * 2], acc2[nt][hf * 2 + 1]);
        }
}

// ================= fused converts (sampled + base) =================
#define N4S (BATCH * NS * CDIM / 4)
#define N4B (BATCH * NB * CDIM / 4)

__global__ __launch_bounds__(256)
void cvt_split_all(const float* __restrict__ sampled, const float* __restrict__ base,
                   __half* __restrict__ shi, __half* __restrict__ slo,
                   __half* __restrict__ bhi, __half* __restrict__ blo)
{
    int i = blockIdx.x * 256 + threadIdx.x;
    const float* in;
    __half *hi, *lo;
    int j;
    if (i < N4S) { in = sampled; hi = shi; lo = slo; j = i; }
    else if (i < N4S + N4B) { in = base; hi = bhi; lo = blo; j = i - N4S; }
    else return;
    float4 v = ((const float4*)in)[j];
    float h0 = __half2float(__float2half_rn(v.x));
    float h1 = __half2float(__float2half_rn(v.y));
    float h2 = __half2float(__float2half_rn(v.z));
    float h3 = __half2float(__float2half_rn(v.w));
    ((__half2*)hi)[2 * j]     = __floats2half2_rn(v.x, v.y);
    ((__half2*)hi)[2 * j + 1] = __floats2half2_rn(v.z, v.w);
    ((__half2*)lo)[2 * j]     = __floats2half2_rn(v.x - h0, v.y - h1);
    ((__half2*)lo)[2 * j + 1] = __floats2half2_rn(v.z - h2, v.w - h3);
}

// ================= fused weight transposes (6 -> 1 launch) =================
__global__ __launch_bounds__(256)
void transpose_all(const float* __restrict__ Wq, const float* __restrict__ Wk,
                   const float* __restrict__ Wv, const float* __restrict__ Wo,
                   const float* __restrict__ Wm1, const float* __restrict__ Wm2,
                   __half* __restrict__ WqT, __half* __restrict__ WkT,
                   __half* __restrict__ WvT, __half* __restrict__ WoT,
                   __half* __restrict__ Wm1T, __half* __restrict__ Wm2T)
{
    __shared__ float t[32][33];
    int tb = blockIdx.x;
    const float* in;
    __half* out;
    int K, N, nx, local;
    if (tb < 2304) {                 // 4 x 576 square transposes
        int w = tb / 576; local = tb % 576; K = CDIM; N = CDIM; nx = 24;
        if (w == 0)      { in = Wq; out = WqT; }
        else if (w == 1) { in = Wk; out = WkT; }
        else if (w == 2) { in = Wv; out = WvT; }
        else             { in = Wo; out = WoT; }
    } else if (tb < 4608) {          // Wm1 [768,3072] -> [3072,768]
        local = tb - 2304; in = Wm1; out = Wm1T; K = CDIM; N = C4; nx = 96;
    } else {                         // Wm2 [3072,768] -> [768,3072]
        local = tb - 4608; in = Wm2; out = Wm2T; K = C4; N = CDIM; nx = 24;
    }
    int bx = local % nx, by = local / nx;
    int k0 = by * 32, n0 = bx * 32;
    int tx = threadIdx.x & 31, ty = threadIdx.x >> 5;
#pragma unroll
    for (int i = 0; i < 4; i++)
        t[ty + i * 8][tx] = in[(size_t)(k0 + ty + i * 8) * N + n0 + tx];
    __syncthreads();
#pragma unroll
    for (int i = 0; i < 4; i++)
        out[(size_t)(n0 + ty + i * 8) * K + k0 + tx] = __float2half(t[tx][ty + i * 8]);
}

// ================= top-k + fused gather =================
__global__ __launch_bounds__(1024)
void topk_gather_kernel(const float* __restrict__ scores,
                        const float* __restrict__ sampled,
                        float* __restrict__ topk_out,
                        float* __restrict__ sel_out, __half* __restrict__ sel_h)
{
    __shared__ unsigned long long keys[NS];
    int b = blockIdx.x, tid = threadIdx.x;
    for (int t = tid; t < NS; t += 1024) {
        unsigned int x = __float_as_uint(scores[(size_t)b * NS + t]);
        unsigned int u = (x & 0x80000000u) ? ~x : (x | 0x80000000u);
        keys[t] = (((unsigned long long)(~u)) << 32) | (unsigned int)t;
    }
    __syncthreads();
    for (int k = 2; k <= NS; k <<= 1) {
        for (int j = k >> 1; j > 0; j >>= 1) {
            for (int t = tid; t < NS; t += 1024) {
                int ixj = t ^ j;
                if (ixj > t) {
                    bool up = ((t & k) == 0);
                    unsigned long long a = keys[t], c = keys[ixj];
                    if ((a > c) == up) { keys[t] = c; keys[ixj] = a; }
                }
            }
            __syncthreads();
        }
    }
    if (tid < TOPK)
        topk_out[b * TOPK + tid] = (float)(unsigned int)(keys[tid] & 0xFFFFFFFFull);
    // fused gather: 128 rows x 192 float4
    for (int e = tid; e < TOPK * (CDIM / 4); e += 1024) {
        int kk = e / (CDIM / 4), c = e % (CDIM / 4);
        int idx = (int)(unsigned int)(keys[kk] & 0xFFFFFFFFull);
        float4 v = ((const float4*)(sampled + ((size_t)b * NS + idx) * CDIM))[c];
        size_t rowoff = ((size_t)b * TOPK + kk) * CDIM;
        ((float4*)(sel_out + rowoff))[c] = v;
        __half2* dh = (__half2*)(sel_h + rowoff) + c * 2;
        dh[0] = __floats2half2_rn(v.x, v.y);
        dh[1] = __floats2half2_rn(v.z, v.w);
    }
}

// ================= layernorm: warp per row =================
template <int OUTH>
__global__ __launch_bounds__(256)
void ln_kernel(const float* __restrict__ Xa, const float* __restrict__ Xb,
               const float* __restrict__ gam, const float* __restrict__ bet,
               float* __restrict__ outp, __half* __restrict__ outh)
{
    int warp = threadIdx.x >> 5, lane = threadIdx.x & 31;
    int row = blockIdx.x * 8 + warp;
    const float4* xa = (const float4*)(Xa + (size_t)row * CDIM);
    const float4* xb = (const float4*)(Xb + (size_t)row * CDIM);
    float x[24];
    float s = 0.f, ss = 0.f;
#pragma unroll
    for (int i = 0; i < 6; i++) {
        float4 a = xa[lane + i * 32];
        float4 b = xb[lane + i * 32];
        float v0 = a.x + b.x, v1 = a.y + b.y, v2 = a.z + b.z, v3 = a.w + b.w;
        x[i * 4] = v0; x[i * 4 + 1] = v1; x[i * 4 + 2] = v2; x[i * 4 + 3] = v3;
        s += v0 + v1 + v2 + v3;
        ss += v0 * v0 + v1 * v1 + v2 * v2 + v3 * v3;
    }
#pragma unroll
    for (int o = 16; o; o >>= 1) {
        s  += __shfl_xor_sync(0xffffffffu, s,  o);
        ss += __shfl_xor_sync(0xffffffffu, ss, o);
    }
    float mu = s * (1.0f / CDIM);
    float rstd = rsqrtf(ss * (1.0f / CDIM) - mu * mu + 1e-5f);
    const float4* gv = (const float4*)gam;
    const float4* bv = (const float4*)bet;
#pragma unroll
    for (int i = 0; i < 6; i++) {
        float4 gg = gv[lane + i * 32];
        float4 bb = bv[lane + i * 32];
        float y0 = (x[i * 4]     - mu) * rstd * gg.x + bb.x;
        float y1 = (x[i * 4 + 1] - mu) * rstd * gg.y + bb.y;
        float y2 = (x[i * 4 + 2] - mu) * rstd * gg.z + bb.z;
        float y3 = (x[i * 4 + 3] - mu) * rstd * gg.w + bb.w;
        ((float4*)(outp + (size_t)row * CDIM))[lane + i * 32] = make_float4(y0, y1, y2, y3);
        if (OUTH) {
            __half2* oh = (__half2*)(outh + (size_t)row * CDIM) + (lane + i * 32) * 2;
            oh[0] = __floats2half2_rn(y0, y1);
            oh[1] = __floats2half2_rn(y2, y3);
        }
    }
}

// ================= launch =================
extern "C" void kernel_launch(void* const* d_in, const int* in_sizes, int n_in,
                              void* d_out, int out_size)
{
    const float* base    = (const float*)d_in[0];
    const float* sampled = (const float*)d_in[1];
    const float* Wq = (const float*)d_in[2];  const float* bq = (const float*)d_in[3];
    const float* Wk = (const float*)d_in[4];  const float* bk = (const float*)d_in[5];
    const float* Wv = (const float*)d_in[6];  const float* bv = (const float*)d_in[7];
    const float* Wo = (const float*)d_in[8];  const float* bo = (const float*)d_in[9];
    const float* g1 = (const float*)d_in[10]; const float* b1 = (const float*)d_in[11];
    const float* g2 = (const float*)d_in[12]; const float* b2 = (const float*)d_in[13];
    const float* Wm1 = (const float*)d_in[14]; const float* bm1 = (const float*)d_in[15];
    const float* Wm2 = (const float*)d_in[16]; const float* bm2 = (const float*)d_in[17];

    float* out = (float*)d_out;
    float* out_x      = out;
    float* out_scores = out + (size_t)BATCH * NB * CDIM;
    float* out_attn   = out_scores + (size_t)BATCH * NS;
    float* out_topk   = out_attn + (size_t)BATCH * HEADS * NB * TOPK;
    float* out_sel    = out_topk + (size_t)BATCH * TOPK;

    float *p_tmp, *p_ctx, *p_x1;
    __half *p_qh, *p_kh, *p_vh, *p_act, *p_selh, *p_h;
    __half *p_WqT, *p_WkT, *p_WvT, *p_WoT, *p_Wm1T, *p_Wm2T;
    __half *p_shi, *p_slo, *p_bhi, *p_blo;
    cudaGetSymbolAddress((void**)&p_tmp,  g_tmp);
    cudaGetSymbolAddress((void**)&p_ctx,  g_ctx);
    cudaGetSymbolAddress((void**)&p_x1,   g_x1);
    cudaGetSymbolAddress((void**)&p_qh,   g_q_h);
    cudaGetSymbolAddress((void**)&p_kh,   g_k_h);
    cudaGetSymbolAddress((void**)&p_vh,   g_v_h);
    cudaGetSymbolAddress((void**)&p_act,  g_act_h);
    cudaGetSymbolAddress((void**)&p_selh, g_sel_h);
    cudaGetSymbolAddress((void**)&p_h,    g_h_h);
    cudaGetSymbolAddress((void**)&p_WqT,  g_WqT);
    cudaGetSymbolAddress((void**)&p_WkT,  g_WkT);
    cudaGetSymbolAddress((void**)&p_WvT,  g_WvT);
    cudaGetSymbolAddress((void**)&p_WoT,  g_WoT);
    cudaGetSymbolAddress((void**)&p_Wm1T, g_Wm1T);
    cudaGetSymbolAddress((void**)&p_Wm2T, g_Wm2T);
    cudaGetSymbolAddress((void**)&p_shi,  g_s_hi);
    cudaGetSymbolAddress((void**)&p_slo,  g_s_lo);
    cudaGetSymbolAddress((void**)&p_bhi,  g_b_hi);
    cudaGetSymbolAddress((void**)&p_blo,  g_b_lo);

    cudaFuncSetAttribute(gemm_mma<0,0>, cudaFuncAttributeMaxDynamicSharedMemorySize, G_SMEM);
    cudaFuncSetAttribute(gemm_mma<1,1>, cudaFuncAttributeMaxDynamicSharedMemorySize, G_SMEM);
    cudaFuncSetAttribute(gemm_qkv,      cudaFuncAttributeMaxDynamicSharedMemorySize, G_SMEM);
    cudaFuncSetAttribute(saliency_mma,  cudaFuncAttributeMaxDynamicSharedMemorySize, S_SMEM);
    cudaFuncSetAttribute(attn_kernel,   cudaFuncAttributeMaxDynamicSharedMemorySize, AT_SMEM);

    const int M = BATCH * NB;    // 16384

    // 1) fused weight transposes + fused split converts
    transpose_all<<<6912, 256>>>(Wq, Wk, Wv, Wo, Wm1, Wm2,
                                 p_WqT, p_WkT, p_WvT, p_WoT, p_Wm1T, p_Wm2T);
    cvt_split_all<<<(N4S + N4B + 255) / 256, 256>>>(sampled, base, p_shi, p_slo, p_bhi, p_blo);

    // 2) saliency + fused topk/gather
    saliency_mma<<<dim3(NS/128, BATCH), 512, S_SMEM>>>(p_shi, p_slo, p_bhi, p_blo, out_scores);
    topk_gather_kernel<<<BATCH, 1024>>>(out_scores, sampled, out_topk, out_sel, p_selh);

    // 3) fused Q/K/V projection
    gemm_qkv<<<dim3(CDIM/128, 160), 256, G_SMEM>>>(p_bhi, p_selh, p_WqT, p_WkT, p_WvT,
                                                   bq, bk, bv, p_qh, p_kh, p_vh);

    // 4) attention
    attn_kernel<<<dim3(NB/128, HEADS, BATCH), 256, AT_SMEM>>>(p_qh, p_kh, p_vh, out_attn, p_act);

    // 5) O-projection
    gemm_mma<0,0><<<dim3(CDIM/128, M/128), 256, G_SMEM>>>(p_act, p_WoT, bo, p_tmp, nullptr, M, CDIM, CDIM);

    // 6) LN1 + MLP + LN2
    ln_kernel<1><<<M/8, 256>>>(base, p_tmp, g1, b1, p_x1, p_act);
    gemm_mma<1,1><<<dim3(C4/128, M/128), 256, G_SMEM>>>(p_act, p_Wm1T, bm1, nullptr, p_h, M, C4, CDIM);
    gemm_mma<0,0><<<dim3(CDIM/128, M/128), 256, G_SMEM>>>(p_h, p_Wm2T, bm2, p_ctx, nullptr, M, CDIM, C4);
    ln_kernel<0><<<M/8, 256>>>(p_x1, p_ctx, g2, b2, out_x, nullptr);
}

// round 14
// speedup vs baseline: 5.9242x; 1.1583x over previous
#include <cuda_runtime.h>
#include <cuda_fp16.h>
#include <math.h>
#include <stdint.h>

#define BATCH 16
#define NB    1024
#define NS    4096
#define CDIM  768
#define HEADS 12
#define DH    64
#define TOPK  128
#define C4    3072

// ---------------- device scratch ----------------
__device__ float g_tmp[BATCH * (size_t)NB * CDIM];
__device__ float g_ctx[BATCH * (size_t)NB * CDIM];
__device__ float g_x1 [BATCH * (size_t)NB * CDIM];
__device__ unsigned long long g_part[BATCH * 1024];   // stage-1 topk winners
__device__ __half g_q_h [BATCH * (size_t)NB * CDIM];
__device__ __half g_k_h [BATCH * (size_t)TOPK * CDIM];
__device__ __half g_v_h [BATCH * (size_t)TOPK * CDIM];
__device__ __half g_act_h [BATCH * (size_t)NB * CDIM];
__device__ __half g_sel_h [BATCH * (size_t)TOPK * CDIM];
__device__ __half g_h_h   [BATCH * (size_t)NB * C4];
__device__ __half g_WqT[CDIM * CDIM];
__device__ __half g_WkT[CDIM * CDIM];
__device__ __half g_WvT[CDIM * CDIM];
__device__ __half g_WoT[CDIM * CDIM];
__device__ __half g_Wm1T[(size_t)C4 * CDIM];
__device__ __half g_Wm2T[(size_t)CDIM * C4];
__device__ __half g_s_hi[BATCH * (size_t)NS * CDIM];
__device__ __half g_s_lo[BATCH * (size_t)NS * CDIM];
__device__ __half g_b_hi[BATCH * (size_t)NB * CDIM];
__device__ __half g_b_lo[BATCH * (size_t)NB * CDIM];

// ================= helpers =================
__device__ __forceinline__ uint32_t smem_u32(const void* p) {
    uint32_t a;
    asm("{ .reg .u64 t; cvta.to.shared.u64 t, %1; cvt.u32.u64 %0, t; }" : "=r"(a) : "l"(p));
    return a;
}
__device__ __forceinline__ void cp16(uint32_t dst, const void* src) {
    asm volatile("cp.async.cg.shared.global [%0], [%1], 16;" :: "r"(dst), "l"(src));
}
#define CP_COMMIT() asm volatile("cp.async.commit_group;" ::: "memory")
#define CP_WAIT(n)  asm volatile("cp.async.wait_group %0;" :: "n"(n) : "memory")

#define KCH 32
#define ROWB 80

__device__ __forceinline__ void ldmA(uint32_t addr, uint32_t* f) {
    asm volatile("ldmatrix.sync.aligned.m8n8.x4.shared.b16 {%0,%1,%2,%3}, [%4];"
        : "=r"(f[0]), "=r"(f[1]), "=r"(f[2]), "=r"(f[3]) : "r"(addr));
}
__device__ __forceinline__ void ldmB4(uint32_t addr, uint32_t* f) {
    asm volatile("ldmatrix.sync.aligned.m8n8.x4.shared.b16 {%0,%1,%2,%3}, [%4];"
        : "=r"(f[0]), "=r"(f[1]), "=r"(f[2]), "=r"(f[3]) : "r"(addr));
}
__device__ __forceinline__ void ldmB4T(uint32_t addr, uint32_t* f) {
    asm volatile("ldmatrix.sync.aligned.m8n8.x4.trans.shared.b16 {%0,%1,%2,%3}, [%4];"
        : "=r"(f[0]), "=r"(f[1]), "=r"(f[2]), "=r"(f[3]) : "r"(addr));
}
__device__ __forceinline__ void hmma(float* d, const uint32_t* a, const uint32_t* b) {
    asm volatile(
        "mma.sync.aligned.m16n8k16.row.col.f32.f16.f16.f32 "
        "{%0,%1,%2,%3}, {%4,%5,%6,%7}, {%8,%9}, {%0,%1,%2,%3};"
        : "+f"(d[0]), "+f"(d[1]), "+f"(d[2]), "+f"(d[3])
        : "r"(a[0]), "r"(a[1]), "r"(a[2]), "r"(a[3]), "r"(b[0]), "r"(b[1]));
}
// orderable-uint float encoding (monotone): larger float -> larger uint
__device__ __forceinline__ uint32_t fenc(float f) {
    uint32_t u = __float_as_uint(f);
    return (u & 0x80000000u) ? ~u : (u | 0x80000000u);
}
__device__ __forceinline__ float fdec(uint32_t u) {
    uint32_t b = (u & 0x80000000u) ? (u & 0x7FFFFFFFu) : ~u;
    return __uint_as_float(b);
}

// ================= GEMM core =================
#define G_ST_B  20480
#define G_SMEM  (4 * G_ST_B)

template <int ACT, int OUTH>
__device__ __forceinline__ void gemm_body(
    char* dsm, const __half* __restrict__ A, const __half* __restrict__ Bt,
    const float* __restrict__ bias, float* __restrict__ Cf,
    __half* __restrict__ Ch, int m0, int n0, int N, int K)
{
    uint32_t su = smem_u32(dsm);
    int tid = threadIdx.x, warp = tid >> 5, lane = tid & 31;
    int wm = (warp >> 1) * 32, wn = (warp & 1) * 64;

    const __half* Ab = A  + (size_t)m0 * K;
    const __half* Bb = Bt + (size_t)n0 * K;

    int row0 = tid >> 2, seg0 = (tid & 3);
    int row1 = (tid + 256) >> 2, seg1 = ((tid + 256) & 3);

    int nch = K / KCH;
#pragma unroll
    for (int s = 0; s < 3; s++) {
        uint32_t sb = su + s * G_ST_B;
        const __half* As = Ab + (size_t)s * KCH;
        const __half* Bs = Bb + (size_t)s * KCH;
        cp16(sb + row0 * ROWB + seg0 * 16, As + (size_t)row0 * K + seg0 * 8);
        cp16(sb + row1 * ROWB + seg1 * 16, As + (size_t)row1 * K + seg1 * 8);
        cp16(sb + 10240 + row0 * ROWB + seg0 * 16, Bs + (size_t)row0 * K + seg0 * 8);
        cp16(sb + 10240 + row1 * ROWB + seg1 * 16, Bs + (size_t)row1 * K + seg1 * 8);
        CP_COMMIT();
    }

    float acc[2][8][4];
#pragma unroll
    for (int i = 0; i < 2; i++)
#pragma unroll
        for (int j = 0; j < 8; j++)
#pragma unroll
            for (int t = 0; t < 4; t++) acc[i][j][t] = 0.f;

    int a_row = lane & 15, a_kh = (lane >> 4) * 8;
    int bp_row = ((lane >> 4) & 1) * 8 + (lane & 7);
    int bp_kh  = ((lane >> 3) & 1) * 8;

    for (int c = 0; c < nch; c++) {
        CP_WAIT(2);
        __syncthreads();
        if (c + 3 < nch) {
            uint32_t sb = su + ((c + 3) & 3) * G_ST_B;
            const __half* As = Ab + (size_t)(c + 3) * KCH;
            const __half* Bs = Bb + (size_t)(c + 3) * KCH;
            cp16(sb + row0 * ROWB + seg0 * 16, As + (size_t)row0 * K + seg0 * 8);
            cp16(sb + row1 * ROWB + seg1 * 16, As + (size_t)row1 * K + seg1 * 8);
            cp16(sb + 10240 + row0 * ROWB + seg0 * 16, Bs + (size_t)row0 * K + seg0 * 8);
            cp16(sb + 10240 + row1 * ROWB + seg1 * 16, Bs + (size_t)row1 * K + seg1 * 8);
        }
        CP_COMMIT();
        uint32_t sb = su + (c & 3) * G_ST_B;
#pragma unroll
        for (int ks = 0; ks < 2; ks++) {
            int kk = ks * 16;
            uint32_t afr[2][4];
#pragma unroll
            for (int mt = 0; mt < 2; mt++)
                ldmA(sb + (wm + mt * 16 + a_row) * ROWB + (kk + a_kh) * 2, afr[mt]);
#pragma unroll
            for (int p = 0; p < 4; p++) {
                uint32_t bfr[4];
                ldmB4(sb + 10240 + (wn + p * 16 + bp_row) * ROWB + (kk + bp_kh) * 2, bfr);
                hmma(acc[0][2 * p],     afr[0], bfr);
                hmma(acc[1][2 * p],     afr[1], bfr);
                hmma(acc[0][2 * p + 1], afr[0], bfr + 2);
                hmma(acc[1][2 * p + 1], afr[1], bfr + 2);
            }
        }
    }

    int g = lane >> 2, t4 = (lane & 3) * 2;
#pragma unroll
    for (int mt = 0; mt < 2; mt++) {
#pragma unroll
        for (int nt = 0; nt < 8; nt++) {
            int col = n0 + wn + nt * 8 + t4;
            float b0 = bias[col], b1 = bias[col + 1];
#pragma unroll
            for (int hf = 0; hf < 2; hf++) {
                int row = m0 + wm + mt * 16 + g + hf * 8;
                float x0 = acc[mt][nt][hf * 2 + 0] + b0;
                float x1 = acc[mt][nt][hf * 2 + 1] + b1;
                if (ACT == 1) {
                    x0 = 0.5f * x0 * (1.0f + erff(x0 * 0.70710678118654752f));
                    x1 = 0.5f * x1 * (1.0f + erff(x1 * 0.70710678118654752f));
                }
                if (OUTH) {
                    *(__half2*)(Ch + (size_t)row * N + col) = __floats2half2_rn(x0, x1);
                } else {
                    *(float2*)(Cf + (size_t)row * N + col) = make_float2(x0, x1);
                }
            }
        }
    }
}

template <int ACT, int OUTH>
__global__ __launch_bounds__(256, 2)
void gemm_mma(const __half* __restrict__ A, const __half* __restrict__ Bt,
              const float* __restrict__ bias, float* __restrict__ Cf,
              __half* __restrict__ Ch, int M, int N, int K)
{
    extern __shared__ char dsm[];
    gemm_body<ACT, OUTH>(dsm, A, Bt, bias, Cf, Ch,
                         blockIdx.y * 128, blockIdx.x * 128, N, K);
}

__global__ __launch_bounds__(256, 2)
void gemm_qkv(const __half* __restrict__ Aq, const __half* __restrict__ Akv,
              const __half* __restrict__ WqT, const __half* __restrict__ WkT,
              const __half* __restrict__ WvT,
              const float* __restrict__ bq, const float* __restrict__ bk,
              const float* __restrict__ bv,
              __half* __restrict__ Cq, __half* __restrict__ Ck, __half* __restrict__ Cv)
{
    extern __shared__ char dsm[];
    int by = blockIdx.y;
    const __half *A, *W;
    const float* bias;
    __half* C;
    int m0;
    if (by < 128)      { A = Aq;  W = WqT; bias = bq; C = Cq; m0 = by * 128; }
    else if (by < 144) { A = Akv; W = WkT; bias = bk; C = Ck; m0 = (by - 128) * 128; }
    else               { A = Akv; W = WvT; bias = bv; C = Cv; m0 = (by - 144) * 128; }
    gemm_body<0, 1>(dsm, A, W, bias, nullptr, C, m0, blockIdx.x * 128, CDIM, CDIM);
}

// ================= saliency: hi-only HMMA + exact rescue =================
// smem: 3 stages x (A-hi 10240 + B-hi 10240) | rowmax[128] | exact[128] | cnt | list[4096]
#define S2_ST_B   20480
#define S2_BUF    (3 * S2_ST_B)        // 61440
#define S2_ROWMAX S2_BUF               // 512 B
#define S2_EXACT  (S2_BUF + 512)       // 512 B
#define S2_CNT    (S2_BUF + 1024)      // 16 B (padded)
#define S2_LIST   (S2_BUF + 1040)
#define S2_CAP    4096
#define S2_SMEM   (S2_LIST + S2_CAP * 8)   // 94,608
#define S_MARGIN  1.0f

__global__ __launch_bounds__(512)
void saliency_mma(const __half* __restrict__ shi, const __half* __restrict__ slo,
                  const __half* __restrict__ bhi, const __half* __restrict__ blo,
                  float* __restrict__ scores)
{
    extern __shared__ char dsm[];
    uint32_t su = smem_u32(dsm);
    uint32_t* rowmax = (uint32_t*)(dsm + S2_ROWMAX);
    uint32_t* exacts = (uint32_t*)(dsm + S2_EXACT);
    uint32_t* cnt    = (uint32_t*)(dsm + S2_CNT);
    uint2*    list   = (uint2*)(dsm + S2_LIST);

    int tid = threadIdx.x, warp = tid >> 5, lane = tid & 31;
    int b = blockIdx.y;
    int r0 = blockIdx.x * 128;
    int wm = (warp >> 1) * 16, wn = (warp & 1) * 64;

    if (tid < 128) { rowmax[tid] = 0x007FFFFFu; exacts[tid] = 0x007FFFFFu; } // enc(-inf)
    if (tid == 0) *cnt = 0;

    const __half* Ahi  = shi + ((size_t)b * NS + r0) * CDIM;
    const __half* Bhi0 = bhi + (size_t)b * NB * CDIM;

    int prow = tid >> 2, pseg = tid & 3;

    int a_row = lane & 15, a_kh = (lane >> 4) * 8;
    int bp_row = ((lane >> 4) & 1) * 8 + (lane & 7);
    int bp_kh  = ((lane >> 3) & 1) * 8;
    int g = lane >> 2, t4 = (lane & 3) * 2;

    const int NCH = CDIM / KCH;   // 24
    const int NIT = 8 * NCH;      // 192

#define S_PREF(it) do { \
        int _jc = (it) / NCH, _c = (it) % NCH; \
        uint32_t sb = su + ((it) % 3) * S2_ST_B; \
        int ko = _c * KCH; \
        const __half* Bh = Bhi0 + (size_t)_jc * 128 * CDIM; \
        cp16(sb + prow * ROWB + pseg * 16,         Ahi + (size_t)prow * CDIM + ko + pseg * 8); \
        cp16(sb + 10240 + prow * ROWB + pseg * 16, Bh  + (size_t)prow * CDIM + ko + pseg * 8); \
    } while (0)

    S_PREF(0); CP_COMMIT();
    S_PREF(1); CP_COMMIT();

    float acc[8][4];

    for (int it = 0; it < NIT; it++) {
        int c = it % NCH, jc = it / NCH;
        if (c == 0) {
#pragma unroll
            for (int j = 0; j < 8; j++)
#pragma unroll
                for (int t = 0; t < 4; t++) acc[j][t] = 0.f;
        }
        CP_WAIT(1);
        __syncthreads();
        if (it + 2 < NIT) S_PREF(it + 2);
        CP_COMMIT();
        uint32_t sb = su + (it % 3) * S2_ST_B;
#pragma unroll
        for (int ks = 0; ks < 2; ks++) {
            int kk = ks * 16;
            uint32_t ah[4];
            ldmA(sb + (wm + a_row) * ROWB + (kk + a_kh) * 2, ah);
#pragma unroll
            for (int p = 0; p < 4; p++) {
                uint32_t bh4[4];
                ldmB4(sb + 10240 + (wn + p * 16 + bp_row) * ROWB + (kk + bp_kh) * 2, bh4);
                hmma(acc[2 * p],     ah, bh4);
                hmma(acc[2 * p + 1], ah, bh4 + 2);
            }
        }
        if (c == NCH - 1) {
            // fold this jc's 128 j-columns: rowmax update, then flag candidates
#pragma unroll
            for (int hf = 0; hf < 2; hf++) {
                int row = wm + g + hf * 8;
                float m = -3.4e38f;
#pragma unroll
                for (int nt = 0; nt < 8; nt++)
                    m = fmaxf(m, fmaxf(acc[nt][hf * 2], acc[nt][hf * 2 + 1]));
                atomicMax(&rowmax[row], fenc(m));
            }
            __syncthreads();
#pragma unroll
            for (int hf = 0; hf < 2; hf++) {
                int row = wm + g + hf * 8;
                float thr = fdec(rowmax[row]) - S_MARGIN;
#pragma unroll
                for (int nt = 0; nt < 8; nt++)
#pragma unroll
                    for (int e = 0; e < 2; e++) {
                        float s = acc[nt][hf * 2 + e];
                        if (s >= thr) {
                            uint32_t idx = atomicAdd(cnt, 1u);
                            if (idx < S2_CAP) {
                                int jg = jc * 128 + wn + nt * 8 + t4 + e;
                                list[idx] = make_uint2(((uint32_t)row << 16) | (uint32_t)jg,
                                                       __float_as_uint(s));
                            }
                        }
                    }
            }
        }
    }
#undef S_PREF

    __syncthreads();
    // exact fp32 rescue for surviving candidates
    int n = *cnt; if (n > S2_CAP) n = S2_CAP;
    for (int i = tid; i < n; i += 512) {
        int row = list[i].x >> 16, jg = list[i].x & 0xFFFFu;
        float s = __uint_as_float(list[i].y);
        if (s >= fdec(rowmax[row]) - S_MARGIN) {
            const __half2* ah2 = (const __half2*)(shi + ((size_t)b * NS + r0 + row) * CDIM);
            const __half2* al2 = (const __half2*)(slo + ((size_t)b * NS + r0 + row) * CDIM);
            const __half2* bh2 = (const __half2*)(bhi + ((size_t)b * NB + jg) * CDIM);
            const __half2* bl2 = (const __half2*)(blo + ((size_t)b * NB + jg) * CDIM);
            float dot = 0.f;
#pragma unroll 4
            for (int k2 = 0; k2 < CDIM / 2; k2++) {
                float2 ah = __half22float2(ah2[k2]);
                float2 al = __half22float2(al2[k2]);
                float2 bh = __half22float2(bh2[k2]);
                float2 bl = __half22float2(bl2[k2]);
                float ax = ah.x + al.x, ay = ah.y + al.y;
                float bx = bh.x + bl.x, by = bh.y + bl.y;
                dot += ax * bx + ay * by;
            }
            atomicMax(&exacts[row], fenc(dot));
        }
    }
    __syncthreads();
    if (tid < 128)
        scores[(size_t)b * NS + r0 + tid] = fdec(exacts[tid]) * 0.03608439182435161f;
}

// ================= tensor-core attention =================
#define AT_SMEM 73728
#define AT_Q   0
#define AT_KV  18432
#define AT_P   36864
#define AT_ST  71680
#define QROWB  144
#define PROWB  272

__global__ __launch_bounds__(256)
void attn_kernel(const __half* __restrict__ qh, const __half* __restrict__ kh,
                 const __half* __restrict__ vh,
                 float* __restrict__ attn_out, __half* __restrict__ ctx_h)
{
    extern __shared__ char dsm[];
    uint32_t su = smem_u32(dsm);
    int tid = threadIdx.x, warp = tid >> 5, lane = tid & 31;
    int qt = blockIdx.x, h = blockIdx.y, b = blockIdx.z;
    int qr0 = qt * 128;

    const __half* Qg = qh + ((size_t)(b * NB + qr0)) * CDIM + h * DH;
    const __half* Kg = kh + ((size_t)b * TOPK) * CDIM + h * DH;
    const __half* Vg = vh + ((size_t)b * TOPK) * CDIM + h * DH;

#pragma unroll
    for (int i = 0; i < 4; i++) {
        int idx = tid + i * 256;
        int r = idx >> 3, c = idx & 7;
        *(uint4*)(dsm + AT_Q  + r * QROWB + c * 16) = *(const uint4*)(Qg + (size_t)r * CDIM + c * 8);
        *(uint4*)(dsm + AT_KV + r * QROWB + c * 16) = *(const uint4*)(Kg + (size_t)r * CDIM + c * 8);
    }
    __syncthreads();

    int wm = (warp >> 1) * 32, wn = (warp & 1) * 64;
    int a_row = lane & 15, a_kh = (lane >> 4) * 8;
    int bp_row = ((lane >> 4) & 1) * 8 + (lane & 7);
    int bp_kh  = ((lane >> 3) & 1) * 8;

    float acc[2][8][4];
#pragma unroll
    for (int i = 0; i < 2; i++)
#pragma unroll
        for (int j = 0; j < 8; j++)
#pragma unroll
            for (int t = 0; t < 4; t++) acc[i][j][t] = 0.f;

#pragma unroll
    for (int ks = 0; ks < 4; ks++) {
        int kk = ks * 16;
        uint32_t afr[2][4];
#pragma unroll
        for (int mt = 0; mt < 2; mt++)
            ldmA(su + AT_Q + (wm + mt * 16 + a_row) * QROWB + (kk + a_kh) * 2, afr[mt]);
#pragma unroll
        for (int p = 0; p < 4; p++) {
            uint32_t bfr[4];
            ldmB4(su + AT_KV + (wn + p * 16 + bp_row) * QROWB + (kk + bp_kh) * 2, bfr);
            hmma(acc[0][2 * p],     afr[0], bfr);
            hmma(acc[1][2 * p],     afr[1], bfr);
            hmma(acc[0][2 * p + 1], afr[0], bfr + 2);
            hmma(acc[1][2 * p + 1], afr[1], bfr + 2);
        }
    }
    __syncthreads();

#pragma unroll
    for (int i = 0; i < 4; i++) {
        int idx = tid + i * 256;
        int r = idx >> 3, c = idx & 7;
        *(uint4*)(dsm + AT_KV + r * QROWB + c * 16) = *(const uint4*)(Vg + (size_t)r * CDIM + c * 8);
    }

    float* rstat = (float*)(dsm + AT_ST);
    int g = lane >> 2, t4 = (lane & 3) * 2;

#pragma unroll
    for (int i = 0; i < 2; i++)
#pragma unroll
        for (int j = 0; j < 8; j++)
#pragma unroll
            for (int t = 0; t < 4; t++) acc[i][j][t] *= 0.125f;

    float gmax[2][2];
#pragma unroll
    for (int mt = 0; mt < 2; mt++)
#pragma unroll
        for (int hf = 0; hf < 2; hf++) {
            float m = -3.4e38f;
#pragma unroll
            for (int nt = 0; nt < 8; nt++)
                m = fmaxf(m, fmaxf(acc[mt][nt][hf * 2], acc[mt][nt][hf * 2 + 1]));
            m = fmaxf(m, __shfl_xor_sync(0xffffffffu, m, 1));
            m = fmaxf(m, __shfl_xor_sync(0xffffffffu, m, 2));
            if ((lane & 3) == 0)
                rstat[(wm + mt * 16 + g + hf * 8) * 2 + (warp & 1)] = m;
        }
    __syncthreads();
#pragma unroll
    for (int mt = 0; mt < 2; mt++)
#pragma unroll
        for (int hf = 0; hf < 2; hf++) {
            int row = wm + mt * 16 + g + hf * 8;
            gmax[mt][hf] = fmaxf(rstat[row * 2], rstat[row * 2 + 1]);
        }
    __syncthreads();

    float gsum[2][2];
#pragma unroll
    for (int mt = 0; mt < 2; mt++)
#pragma unroll
        for (int hf = 0; hf < 2; hf++) {
            float s = 0.f;
#pragma unroll
            for (int nt = 0; nt < 8; nt++) {
                float e0 = expf(acc[mt][nt][hf * 2]     - gmax[mt][hf]);
                float e1 = expf(acc[mt][nt][hf * 2 + 1] - gmax[mt][hf]);
                acc[mt][nt][hf * 2] = e0; acc[mt][nt][hf * 2 + 1] = e1;
                s += e0 + e1;
            }
            s += __shfl_xor_sync(0xffffffffu, s, 1);
            s += __shfl_xor_sync(0xffffffffu, s, 2);
            if ((lane & 3) == 0)
                rstat[(wm + mt * 16 + g + hf * 8) * 2 + (warp & 1)] = s;
        }
    __syncthreads();
#pragma unroll
    for (int mt = 0; mt < 2; mt++)
#pragma unroll
        for (int hf = 0; hf < 2; hf++) {
            int row = wm + mt * 16 + g + hf * 8;
            gsum[mt][hf] = 1.0f / (rstat[row * 2] + rstat[row * 2 + 1]);
        }

#pragma unroll
    for (int mt = 0; mt < 2; mt++)
#pragma unroll
        for (int hf = 0; hf < 2; hf++) {
            int row = wm + mt * 16 + g + hf * 8;
            size_t o = (((size_t)(b * HEADS + h)) * NB + qr0 + row) * TOPK;
            float inv = gsum[mt][hf];
#pragma unroll
            for (int nt = 0; nt < 8; nt++) {
                int col = wn + nt * 8 + t4;
                float p0 = acc[mt][nt][hf * 2]     * inv;
                float p1 = acc[mt][nt][hf * 2 + 1] * inv;
                *(float2*)(attn_out + o + col) = make_float2(p0, p1);
                *(__half2*)(dsm + AT_P + row * PROWB + col * 2) = __floats2half2_rn(p0, p1);
            }
        }
    __syncthreads();

    int wq = warp * 16;
    float acc2[8][4];
#pragma unroll
    for (int j = 0; j < 8; j++)
#pragma unroll
        for (int t = 0; t < 4; t++) acc2[j][t] = 0.f;

    int vt = lane >> 3, vr = lane & 7;
#pragma unroll
    for (int ks = 0; ks < 8; ks++) {
        int kk = ks * 16;
        uint32_t ap[4];
        ldmA(su + AT_P + (wq + a_row) * PROWB + (kk + a_kh) * 2, ap);
#pragma unroll
        for (int p = 0; p < 4; p++) {
            uint32_t bv[4];
            uint32_t addr = su + AT_KV + (kk + (vt & 1) * 8 + vr) * QROWB + (p * 16 + (vt >> 1) * 8) * 2;
            ldmB4T(addr, bv);
            hmma(acc2[2 * p],     ap, bv);
            hmma(acc2[2 * p + 1], ap, bv + 2);
        }
    }
#pragma unroll
    for (int nt = 0; nt < 8; nt++)
#pragma unroll
        for (int hf = 0; hf < 2; hf++) {
            int row = wq + g + hf * 8;
            int col = nt * 8 + t4;
            *(__half2*)(ctx_h + ((size_t)(b * NB + qr0 + row)) * CDIM + h * DH + col) =
                __floats2half2_rn(acc2[nt][hf * 2], acc2[nt][hf * 2 + 1]);
        }
}

// ================= fused converts (sampled + base) =================
#define N4S (BATCH * NS * CDIM / 4)
#define N4B (BATCH * NB * CDIM / 4)

__global__ __launch_bounds__(256)
void cvt_split_all(const float* __restrict__ sampled, const float* __restrict__ base,
                   __half* __restrict__ shi, __half* __restrict__ slo,
                   __half* __restrict__ bhi, __half* __restrict__ blo)
{
    int i = blockIdx.x * 256 + threadIdx.x;
    const float* in;
    __half *hi, *lo;
    int j;
    if (i < N4S) { in = sampled; hi = shi; lo = slo; j = i; }
    else if (i < N4S + N4B) { in = base; hi = bhi; lo = blo; j = i - N4S; }
    else return;
    float4 v = ((const float4*)in)[j];
    float h0 = __half2float(__float2half_rn(v.x));
    float h1 = __half2float(__float2half_rn(v.y));
    float h2 = __half2float(__float2half_rn(v.z));
    float h3 = __half2float(__float2half_rn(v.w));
    ((__half2*)hi)[2 * j]     = __floats2half2_rn(v.x, v.y);
    ((__half2*)hi)[2 * j + 1] = __floats2half2_rn(v.z, v.w);
    ((__half2*)lo)[2 * j]     = __floats2half2_rn(v.x - h0, v.y - h1);
    ((__half2*)lo)[2 * j + 1] = __floats2half2_rn(v.z - h2, v.w - h3);
}

// ================= fused weight transposes =================
__global__ __launch_bounds__(256)
void transpose_all(const float* __restrict__ Wq, const float* __restrict__ Wk,
                   const float* __restrict__ Wv, const float* __restrict__ Wo,
                   const float* __restrict__ Wm1, const float* __restrict__ Wm2,
                   __half* __restrict__ WqT, __half* __restrict__ WkT,
                   __half* __restrict__ WvT, __half* __restrict__ WoT,
                   __half* __restrict__ Wm1T, __half* __restrict__ Wm2T)
{
    __shared__ float t[32][33];
    int tb = blockIdx.x;
    const float* in;
    __half* out;
    int K, N, nx, local;
    if (tb < 2304) {
        int w = tb / 576; local = tb % 576; K = CDIM; N = CDIM; nx = 24;
        if (w == 0)      { in = Wq; out = WqT; }
        else if (w == 1) { in = Wk; out = WkT; }
        else if (w == 2) { in = Wv; out = WvT; }
        else             { in = Wo; out = WoT; }
    } else if (tb < 4608) {
        local = tb - 2304; in = Wm1; out = Wm1T; K = CDIM; N = C4; nx = 96;
    } else {
        local = tb - 4608; in = Wm2; out = Wm2T; K = C4; N = CDIM; nx = 24;
    }
    int bx = local % nx, by = local / nx;
    int k0 = by * 32, n0 = bx * 32;
    int tx = threadIdx.x & 31, ty = threadIdx.x >> 5;
#pragma unroll
    for (int i = 0; i < 4; i++)
        t[ty + i * 8][tx] = in[(size_t)(k0 + ty + i * 8) * N + n0 + tx];
    __syncthreads();
#pragma unroll
    for (int i = 0; i < 4; i++)
        out[(size_t)(n0 + ty + i * 8) * K + k0 + tx] = __float2half(t[tx][ty + i * 8]);
}

// ================= two-stage exact top-k =================
// stage 1: per (batch, 512-chunk): sort chunk desc, emit top-128 keys
__global__ __launch_bounds__(512)
void topk_stage1(const float* __restrict__ scores, unsigned long long* __restrict__ part)
{
    __shared__ unsigned long long keys[512];
    int b = blockIdx.y, ch = blockIdx.x, tid = threadIdx.x;
    int t = ch * 512 + tid;
    unsigned int x = __float_as_uint(scores[(size_t)b * NS + t]);
    unsigned int u = (x & 0x80000000u) ? ~x : (x | 0x80000000u);
    keys[tid] = (((unsigned long long)(~u)) << 32) | (unsigned int)t;
    __syncthreads();
    for (int k = 2; k <= 512; k <<= 1) {
        for (int j = k >> 1; j > 0; j >>= 1) {
            int ixj = tid ^ j;
            if (ixj > tid) {
                bool up = ((tid & k) == 0);
                unsigned long long a = keys[tid], c = keys[ixj];
                if ((a > c) == up) { keys[tid] = c; keys[ixj] = a; }
            }
            __syncthreads();
        }
    }
    if (tid < TOPK)
        part[((size_t)b * 8 + ch) * TOPK + tid] = keys[tid];
}

// stage 2: merge 8x128 winners, sort 1024, write topk + gather
__global__ __launch_bounds__(1024)
void topk_stage2(const unsigned long long* __restrict__ part,
                 const float* __restrict__ sampled,
                 float* __restrict__ topk_out,
                 float* __restrict__ sel_out, __half* __restrict__ sel_h)
{
    __shared__ unsigned long long keys[1024];
    int b = blockIdx.x, tid = threadIdx.x;
    keys[tid] = part[(size_t)b * 1024 + tid];
    __syncthreads();
    for (int k = 2; k <= 1024; k <<= 1) {
        for (int j = k >> 1; j > 0; j >>= 1) {
            int ixj = tid ^ j;
            if (ixj > tid) {
                bool up = ((tid & k) == 0);
                unsigned long long a = keys[tid], c = keys[ixj];
                if ((a > c) == up) { keys[tid] = c; keys[ixj] = a; }
            }
            __syncthreads();
        }
    }
    if (tid < TOPK)
        topk_out[b * TOPK + tid] = (float)(unsigned int)(keys[tid] & 0xFFFFFFFFull);
    for (int e = tid; e < TOPK * (CDIM / 4); e += 1024) {
        int kk = e / (CDIM / 4), c = e % (CDIM / 4);
        int idx = (int)(unsigned int)(keys[kk] & 0xFFFFFFFFull);
        float4 v = ((const float4*)(sampled + ((size_t)b * NS + idx) * CDIM))[c];
        size_t rowoff = ((size_t)b * TOPK + kk) * CDIM;
        ((float4*)(sel_out + rowoff))[c] = v;
        __half2* dh = (__half2*)(sel_h + rowoff) + c * 2;
        dh[0] = __floats2half2_rn(v.x, v.y);
        dh[1] = __floats2half2_rn(v.z, v.w);
    }
}

// ================= layernorm: warp per row =================
template <int OUTH>
__global__ __launch_bounds__(256)
void ln_kernel(const float* __restrict__ Xa, const float* __restrict__ Xb,
               const float* __restrict__ gam, const float* __restrict__ bet,
               float* __restrict__ outp, __half* __restrict__ outh)
{
    int warp = threadIdx.x >> 5, lane = threadIdx.x & 31;
    int row = blockIdx.x * 8 + warp;
    const float4* xa = (const float4*)(Xa + (size_t)row * CDIM);
    const float4* xb = (const float4*)(Xb + (size_t)row * CDIM);
    float x[24];
    float s = 0.f, ss = 0.f;
#pragma unroll
    for (int i = 0; i < 6; i++) {
        float4 a = xa[lane + i * 32];
        float4 b = xb[lane + i * 32];
        float v0 = a.x + b.x, v1 = a.y + b.y, v2 = a.z + b.z, v3 = a.w + b.w;
        x[i * 4] = v0; x[i * 4 + 1] = v1; x[i * 4 + 2] = v2; x[i * 4 + 3] = v3;
        s += v0 + v1 + v2 + v3;
        ss += v0 * v0 + v1 * v1 + v2 * v2 + v3 * v3;
    }
#pragma unroll
    for (int o = 16; o; o >>= 1) {
        s  += __shfl_xor_sync(0xffffffffu, s,  o);
        ss += __shfl_xor_sync(0xffffffffu, ss, o);
    }
    float mu = s * (1.0f / CDIM);
    float rstd = rsqrtf(ss * (1.0f / CDIM) - mu * mu + 1e-5f);
    const float4* gv = (const float4*)gam;
    const float4* bv = (const float4*)bet;
#pragma unroll
    for (int i = 0; i < 6; i++) {
        float4 gg = gv[lane + i * 32];
        float4 bb = bv[lane + i * 32];
        float y0 = (x[i * 4]     - mu) * rstd * gg.x + bb.x;
        float y1 = (x[i * 4 + 1] - mu) * rstd * gg.y + bb.y;
        float y2 = (x[i * 4 + 2] - mu) * rstd * gg.z + bb.z;
        float y3 = (x[i * 4 + 3] - mu) * rstd * gg.w + bb.w;
        ((float4*)(outp + (size_t)row * CDIM))[lane + i * 32] = make_float4(y0, y1, y2, y3);
        if (OUTH) {
            __half2* oh = (__half2*)(outh + (size_t)row * CDIM) + (lane + i * 32) * 2;
            oh[0] = __floats2half2_rn(y0, y1);
            oh[1] = __floats2half2_rn(y2, y3);
        }
    }
}

// ================= launch =================
extern "C" void kernel_launch(void* const* d_in, const int* in_sizes, int n_in,
                              void* d_out, int out_size)
{
    const float* base    = (const float*)d_in[0];
    const float* sampled = (const float*)d_in[1];
    const float* Wq = (const float*)d_in[2];  const float* bq = (const float*)d_in[3];
    const float* Wk = (const float*)d_in[4];  const float* bk = (const float*)d_in[5];
    const float* Wv = (const float*)d_in[6];  const float* bv = (const float*)d_in[7];
    const float* Wo = (const float*)d_in[8];  const float* bo = (const float*)d_in[9];
    const float* g1 = (const float*)d_in[10]; const float* b1 = (const float*)d_in[11];
    const float* g2 = (const float*)d_in[12]; const float* b2 = (const float*)d_in[13];
    const float* Wm1 = (const float*)d_in[14]; const float* bm1 = (const float*)d_in[15];
    const float* Wm2 = (const float*)d_in[16]; const float* bm2 = (const float*)d_in[17];

    float* out = (float*)d_out;
    float* out_x      = out;
    float* out_scores = out + (size_t)BATCH * NB * CDIM;
    float* out_attn   = out_scores + (size_t)BATCH * NS;
    float* out_topk   = out_attn + (size_t)BATCH * HEADS * NB * TOPK;
    float* out_sel    = out_topk + (size_t)BATCH * TOPK;

    float *p_tmp, *p_ctx, *p_x1;
    unsigned long long* p_part;
    __half *p_qh, *p_kh, *p_vh, *p_act, *p_selh, *p_h;
    __half *p_WqT, *p_WkT, *p_WvT, *p_WoT, *p_Wm1T, *p_Wm2T;
    __half *p_shi, *p_slo, *p_bhi, *p_blo;
    cudaGetSymbolAddress((void**)&p_tmp,  g_tmp);
    cudaGetSymbolAddress((void**)&p_ctx,  g_ctx);
    cudaGetSymbolAddress((void**)&p_x1,   g_x1);
    cudaGetSymbolAddress((void**)&p_part, g_part);
    cudaGetSymbolAddress((void**)&p_qh,   g_q_h);
    cudaGetSymbolAddress((void**)&p_kh,   g_k_h);
    cudaGetSymbolAddress((void**)&p_vh,   g_v_h);
    cudaGetSymbolAddress((void**)&p_act,  g_act_h);
    cudaGetSymbolAddress((void**)&p_selh, g_sel_h);
    cudaGetSymbolAddress((void**)&p_h,    g_h_h);
    cudaGetSymbolAddress((void**)&p_WqT,  g_WqT);
    cudaGetSymbolAddress((void**)&p_WkT,  g_WkT);
    cudaGetSymbolAddress((void**)&p_WvT,  g_WvT);
    cudaGetSymbolAddress((void**)&p_WoT,  g_WoT);
    cudaGetSymbolAddress((void**)&p_Wm1T, g_Wm1T);
    cudaGetSymbolAddress((void**)&p_Wm2T, g_Wm2T);
    cudaGetSymbolAddress((void**)&p_shi,  g_s_hi);
    cudaGetSymbolAddress((void**)&p_slo,  g_s_lo);
    cudaGetSymbolAddress((void**)&p_bhi,  g_b_hi);
    cudaGetSymbolAddress((void**)&p_blo,  g_b_lo);

    cudaFuncSetAttribute(gemm_mma<0,0>, cudaFuncAttributeMaxDynamicSharedMemorySize, G_SMEM);
    cudaFuncSetAttribute(gemm_mma<1,1>, cudaFuncAttributeMaxDynamicSharedMemorySize, G_SMEM);
    cudaFuncSetAttribute(gemm_qkv,      cudaFuncAttributeMaxDynamicSharedMemorySize, G_SMEM);
    cudaFuncSetAttribute(saliency_mma,  cudaFuncAttributeMaxDynamicSharedMemorySize, S2_SMEM);
    cudaFuncSetAttribute(attn_kernel,   cudaFuncAttributeMaxDynamicSharedMemorySize, AT_SMEM);

    const int M = BATCH * NB;

    transpose_all<<<6912, 256>>>(Wq, Wk, Wv, Wo, Wm1, Wm2,
                                 p_WqT, p_WkT, p_WvT, p_WoT, p_Wm1T, p_Wm2T);
    cvt_split_all<<<(N4S + N4B + 255) / 256, 256>>>(sampled, base, p_shi, p_slo, p_bhi, p_blo);

    saliency_mma<<<dim3(NS/128, BATCH), 512, S2_SMEM>>>(p_shi, p_slo, p_bhi, p_blo, out_scores);
    topk_stage1<<<dim3(8, BATCH), 512>>>(out_scores, p_part);
    topk_stage2<<<BATCH, 1024>>>(p_part, sampled, out_topk, out_sel, p_selh);

    gemm_qkv<<<dim3(CDIM/128, 160), 256, G_SMEM>>>(p_bhi, p_selh, p_WqT, p_WkT, p_WvT,
                                                   bq, bk, bv, p_qh, p_kh, p_vh);

    attn_kernel<<<dim3(NB/128, HEADS, BATCH), 256, AT_SMEM>>>(p_qh, p_kh, p_vh, out_attn, p_act);

    gemm_mma<0,0><<<dim3(CDIM/128, M/128), 256, G_SMEM>>>(p_act, p_WoT, bo, p_tmp, nullptr, M, CDIM, CDIM);

    ln_kernel<1><<<M/8, 256>>>(base, p_tmp, g1, b1, p_x1, p_act);
    gemm_mma<1,1><<<dim3(C4/128, M/128), 256, G_SMEM>>>(p_act, p_Wm1T, bm1, nullptr, p_h, M, C4, CDIM);
    gemm_mma<0,0><<<dim3(CDIM/128, M/128), 256, G_SMEM>>>(p_h, p_Wm2T, bm2, p_ctx, nullptr, M, CDIM, C4);
    ln_kernel<0><<<M/8, 256>>>(p_x1, p_ctx, g2, b2, out_x, nullptr);
}